// round 1
// baseline (speedup 1.0000x reference)
#include <cuda_runtime.h>
#include <math.h>
#include <stdint.h>

// Problem constants
#define NT 256
constexpr int Bb  = 4;
constexpr int Ss  = 1024;
constexpr int Hh  = 1024;
constexpr int Nn  = 16;
constexpr int Dd  = 64;
constexpr int FFd = 4096;
constexpr float SCALE = 0.125f;   // 1/sqrt(64)
constexpr float EPSLN = 1e-5f;

// ---------------- scratch (static device globals; no allocation) -------------
__device__ float g_wpack[1024 * 5120];          // repacked [K=H][5*N*D] weights
__device__ float g_qr[Bb * Nn * Ss * Dd];
__device__ float g_qi[Bb * Nn * Ss * Dd];
__device__ float g_kr[Bb * Nn * Ss * Dd];
__device__ float g_ki[Bb * Nn * Ss * Dd];
__device__ float g_v [Bb * Nn * Ss * Dd];
__device__ float g_scores[(size_t)Bb * Nn * Ss * Ss];   // 256 MB, reused as probs
__device__ float g_concat[Bb * Ss * Hh];
__device__ float g_h1[Bb * Ss * Hh];
__device__ float g_tmp[Bb * Ss * Hh];
__device__ float g_ff[(size_t)Bb * Ss * FFd];

// ---------------- generic tiled SGEMM accumulation core ----------------------
// C tile [BM x BN] accumulated by (BM/TM)*(BN/TN)=NT threads.
// A row-major [M,K] (lda), B row-major [K,N] (ldb) or, if TRANSB, B is [N,K]
// and we compute A @ B^T. SIGN=+1/-1 folds into FFMA negation (free).
template<int BM, int BN, int BK, int TM, int TN, bool TRANSB, int SIGN>
__device__ __forceinline__ void gemm_acc(
    const float* __restrict__ A, int lda,
    const float* __restrict__ Bp, int ldb,
    int K, int m0, int n0,
    float (&acc)[TM][TN], float* As, float* Bs)
{
    const int tid = threadIdx.x;
    const int tx  = tid % (BN / TN);
    const int ty  = tid / (BN / TN);

    for (int k0 = 0; k0 < K; k0 += BK) {
        // A tile -> As[k][m] (transposed in smem for vector a-loads)
        for (int idx = tid; idx < BM * (BK / 4); idx += NT) {
            int row = idx / (BK / 4);
            int kq  = idx % (BK / 4);
            float4 t = *reinterpret_cast<const float4*>(
                A + (size_t)(m0 + row) * lda + k0 + kq * 4);
            As[(kq * 4 + 0) * BM + row] = t.x;
            As[(kq * 4 + 1) * BM + row] = t.y;
            As[(kq * 4 + 2) * BM + row] = t.z;
            As[(kq * 4 + 3) * BM + row] = t.w;
        }
        // B tile -> Bs[k][n]
        if (!TRANSB) {
            for (int idx = tid; idx < BK * (BN / 4); idx += NT) {
                int k  = idx / (BN / 4);
                int nq = idx % (BN / 4);
                *reinterpret_cast<float4*>(Bs + k * BN + nq * 4) =
                    *reinterpret_cast<const float4*>(
                        Bp + (size_t)(k0 + k) * ldb + n0 + nq * 4);
            }
        } else {
            for (int idx = tid; idx < BN * (BK / 4); idx += NT) {
                int c  = idx / (BK / 4);
                int kq = idx % (BK / 4);
                float4 t = *reinterpret_cast<const float4*>(
                    Bp + (size_t)(n0 + c) * ldb + k0 + kq * 4);
                Bs[(kq * 4 + 0) * BN + c] = t.x;
                Bs[(kq * 4 + 1) * BN + c] = t.y;
                Bs[(kq * 4 + 2) * BN + c] = t.z;
                Bs[(kq * 4 + 3) * BN + c] = t.w;
            }
        }
        __syncthreads();

        #pragma unroll
        for (int k = 0; k < BK; ++k) {
            float a[TM], b[TN];
            #pragma unroll
            for (int i = 0; i < TM; i += 4) {
                float4 t = *reinterpret_cast<const float4*>(&As[k * BM + ty * TM + i]);
                a[i + 0] = t.x; a[i + 1] = t.y; a[i + 2] = t.z; a[i + 3] = t.w;
            }
            #pragma unroll
            for (int j = 0; j < TN; j += 4) {
                float4 t = *reinterpret_cast<const float4*>(&Bs[k * BN + tx * TN + j]);
                b[j + 0] = t.x; b[j + 1] = t.y; b[j + 2] = t.z; b[j + 3] = t.w;
            }
            #pragma unroll
            for (int i = 0; i < TM; ++i)
                #pragma unroll
                for (int j = 0; j < TN; ++j)
                    acc[i][j] = fmaf(SIGN > 0 ? a[i] : -a[i], b[j], acc[i][j]);
        }
        __syncthreads();
    }
}

// ---------------- weight repack: 5x [N,H,D] -> [H, 5*N*D] --------------------
__global__ __launch_bounds__(NT) void repack_kernel(
    const float* __restrict__ Wqr, const float* __restrict__ Wqi,
    const float* __restrict__ Wkr, const float* __restrict__ Wki,
    const float* __restrict__ Wv)
{
    const int per = Nn * Hh * Dd;                 // 1048576
    int idx = blockIdx.x * NT + threadIdx.x;
    if (idx >= 5 * per) return;
    int p = idx / per;
    int r = idx % per;
    const float* W = (p == 0) ? Wqr : (p == 1) ? Wqi : (p == 2) ? Wkr
                    : (p == 3) ? Wki : Wv;
    int n = r >> 16;           // r / (H*D)
    int k = (r >> 6) & 1023;   // (r % (H*D)) / D
    int d = r & 63;
    g_wpack[(size_t)k * 5120 + (p << 10) + (n << 6) + d] = W[r];
}

// ---------------- fused QKV/V projection GEMM --------------------------------
__global__ __launch_bounds__(NT) void gemm_proj_kernel(
    const float* __restrict__ x,
    const float* __restrict__ bqr, const float* __restrict__ bqi,
    const float* __restrict__ bkr, const float* __restrict__ bki,
    const float* __restrict__ bvv,
    const float* __restrict__ pqr, const float* __restrict__ pqi,
    const float* __restrict__ pkr, const float* __restrict__ pki)
{
    constexpr int BM = 128, BN = 128, BK = 8, TM = 8, TN = 8;
    __shared__ float As[BK * BM], Bs[BK * BN];
    float acc[TM][TN] = {};
    int m0 = blockIdx.y * BM, n0 = blockIdx.x * BN;
    gemm_acc<BM, BN, BK, TM, TN, false, 1>(x, Hh, g_wpack, 5120, Hh, m0, n0, acc, As, Bs);

    int tx = threadIdx.x % (BN / TN), ty = threadIdx.x / (BN / TN);
    int c0 = n0 + tx * TN;                 // 8 consecutive cols: same proj/head
    int p = c0 >> 10, n = (c0 >> 6) & 15, dbase = c0 & 63;

    const float* bias; const float* pos; float mul; float* out;
    switch (p) {
        case 0:  bias = bqr; pos = pqr;     mul = SCALE; out = g_qr; break;
        case 1:  bias = bqi; pos = pqi;     mul = SCALE; out = g_qi; break;
        case 2:  bias = bkr; pos = pkr;     mul = 1.0f;  out = g_kr; break;
        case 3:  bias = bki; pos = pki;     mul = 1.0f;  out = g_ki; break;
        default: bias = bvv; pos = nullptr; mul = 1.0f;  out = g_v;  break;
    }
    const float* brow = bias + n * Dd + dbase;
    #pragma unroll
    for (int i = 0; i < TM; ++i) {
        int m = m0 + ty * TM + i;
        int b = m >> 10, s = m & 1023;
        float* orow = out + ((((size_t)b * Nn + n) << 10) + s) * Dd + dbase;
        const float* prow = pos ? pos + (((size_t)n << 10) + s) * Dd + dbase : nullptr;
        #pragma unroll
        for (int j = 0; j < TN; ++j) {
            float val = (acc[i][j] + brow[j]) * mul;
            if (prow) val += prow[j];
            orow[j] = val;
        }
    }
}

// ---------------- complex scores: (qr krT - qi kiT) * scale ------------------
__global__ __launch_bounds__(NT) void gemm_scores_kernel()
{
    constexpr int BM = 128, BN = 128, BK = 8, TM = 8, TN = 8;
    __shared__ float As[BK * BM], Bs[BK * BN];
    float acc[TM][TN] = {};
    int bh = blockIdx.z;
    int m0 = blockIdx.y * BM, n0 = blockIdx.x * BN;
    const float* qr = g_qr + (size_t)bh * Ss * Dd;
    const float* qi = g_qi + (size_t)bh * Ss * Dd;
    const float* kr = g_kr + (size_t)bh * Ss * Dd;
    const float* ki = g_ki + (size_t)bh * Ss * Dd;
    gemm_acc<BM, BN, BK, TM, TN, true,  1>(qr, Dd, kr, Dd, Dd, m0, n0, acc, As, Bs);
    gemm_acc<BM, BN, BK, TM, TN, true, -1>(qi, Dd, ki, Dd, Dd, m0, n0, acc, As, Bs);

    int tx = threadIdx.x % (BN / TN), ty = threadIdx.x / (BN / TN);
    float* base = g_scores + (size_t)bh * Ss * Ss;
    #pragma unroll
    for (int i = 0; i < TM; ++i) {
        int m = m0 + ty * TM + i;
        float* orow = base + (size_t)m * Ss + n0 + tx * TN;
        #pragma unroll
        for (int j = 0; j < TN; ++j) orow[j] = acc[i][j] * SCALE;
    }
}

// ---------------- row softmax over S=1024, in place --------------------------
__global__ __launch_bounds__(NT) void softmax_kernel()
{
    float4* rp = reinterpret_cast<float4*>(g_scores + (size_t)blockIdx.x * Ss);
    float4 v = rp[threadIdx.x];
    int lane = threadIdx.x & 31, wid = threadIdx.x >> 5;
    __shared__ float red[8];

    float m = fmaxf(fmaxf(v.x, v.y), fmaxf(v.z, v.w));
    #pragma unroll
    for (int o = 16; o; o >>= 1) m = fmaxf(m, __shfl_xor_sync(0xffffffffu, m, o));
    if (lane == 0) red[wid] = m;
    __syncthreads();
    float M = red[0];
    #pragma unroll
    for (int i = 1; i < 8; ++i) M = fmaxf(M, red[i]);

    v.x = __expf(v.x - M); v.y = __expf(v.y - M);
    v.z = __expf(v.z - M); v.w = __expf(v.w - M);
    float s = v.x + v.y + v.z + v.w;
    #pragma unroll
    for (int o = 16; o; o >>= 1) s += __shfl_xor_sync(0xffffffffu, s, o);
    __syncthreads();                 // protect red[] reuse
    if (lane == 0) red[wid] = s;
    __syncthreads();
    float Z = 0.f;
    #pragma unroll
    for (int i = 0; i < 8; ++i) Z += red[i];
    float inv = 1.0f / Z;
    v.x *= inv; v.y *= inv; v.z *= inv; v.w *= inv;
    rp[threadIdx.x] = v;
}

// ---------------- P @ V, scattered into concat layout ------------------------
__global__ __launch_bounds__(NT) void gemm_pv_kernel()
{
    constexpr int BM = 128, BN = 64, BK = 8, TM = 8, TN = 4;
    __shared__ float As[BK * BM], Bs[BK * BN];
    float acc[TM][TN] = {};
    int bh = blockIdx.z; int b = bh >> 4, n = bh & 15;
    int m0 = blockIdx.y * BM;
    const float* P = g_scores + (size_t)bh * Ss * Ss;
    const float* V = g_v      + (size_t)bh * Ss * Dd;
    gemm_acc<BM, BN, BK, TM, TN, false, 1>(P, Ss, V, Dd, Ss, m0, 0, acc, As, Bs);

    int tx = threadIdx.x % (BN / TN), ty = threadIdx.x / (BN / TN);
    int dbase = tx * TN;
    #pragma unroll
    for (int i = 0; i < TM; ++i) {
        int s = m0 + ty * TM + i;
        float* orow = g_concat + ((size_t)(b * Ss + s)) * Hh + n * Dd + dbase;
        #pragma unroll
        for (int j = 0; j < TN; ++j) orow[j] = acc[i][j];
    }
}

// ---------------- Wo GEMM + bias + residual(x) -> g_tmp ----------------------
__global__ __launch_bounds__(NT) void gemm_wo_kernel(
    const float* __restrict__ Wo, const float* __restrict__ bo,
    const float* __restrict__ x)
{
    constexpr int BM = 128, BN = 128, BK = 8, TM = 8, TN = 8;
    __shared__ float As[BK * BM], Bs[BK * BN];
    float acc[TM][TN] = {};
    int m0 = blockIdx.y * BM, n0 = blockIdx.x * BN;
    gemm_acc<BM, BN, BK, TM, TN, false, 1>(g_concat, Hh, Wo, Hh, Hh, m0, n0, acc, As, Bs);

    int tx = threadIdx.x % (BN / TN), ty = threadIdx.x / (BN / TN);
    int c0 = n0 + tx * TN;
    #pragma unroll
    for (int i = 0; i < TM; ++i) {
        int m = m0 + ty * TM + i;
        size_t off = (size_t)m * Hh + c0;
        #pragma unroll
        for (int j = 0; j < TN; ++j)
            g_tmp[off + j] = acc[i][j] + bo[c0 + j] + x[off + j];
    }
}

// ---------------- FFN 1: relu(h1 @ W1 + b1) -> g_ff --------------------------
__global__ __launch_bounds__(NT) void gemm_ff1_kernel(
    const float* __restrict__ W1, const float* __restrict__ b1)
{
    constexpr int BM = 128, BN = 128, BK = 8, TM = 8, TN = 8;
    __shared__ float As[BK * BM], Bs[BK * BN];
    float acc[TM][TN] = {};
    int m0 = blockIdx.y * BM, n0 = blockIdx.x * BN;
    gemm_acc<BM, BN, BK, TM, TN, false, 1>(g_h1, Hh, W1, FFd, Hh, m0, n0, acc, As, Bs);

    int tx = threadIdx.x % (BN / TN), ty = threadIdx.x / (BN / TN);
    int c0 = n0 + tx * TN;
    #pragma unroll
    for (int i = 0; i < TM; ++i) {
        int m = m0 + ty * TM + i;
        size_t off = (size_t)m * FFd + c0;
        #pragma unroll
        for (int j = 0; j < TN; ++j)
            g_ff[off + j] = fmaxf(acc[i][j] + b1[c0 + j], 0.0f);
    }
}

// ---------------- FFN 2: g_ff @ W2 + b2 + h1 -> g_tmp ------------------------
__global__ __launch_bounds__(NT) void gemm_ff2_kernel(
    const float* __restrict__ W2, const float* __restrict__ b2)
{
    constexpr int BM = 128, BN = 128, BK = 8, TM = 8, TN = 8;
    __shared__ float As[BK * BM], Bs[BK * BN];
    float acc[TM][TN] = {};
    int m0 = blockIdx.y * BM, n0 = blockIdx.x * BN;
    gemm_acc<BM, BN, BK, TM, TN, false, 1>(g_ff, FFd, W2, Hh, FFd, m0, n0, acc, As, Bs);

    int tx = threadIdx.x % (BN / TN), ty = threadIdx.x / (BN / TN);
    int c0 = n0 + tx * TN;
    #pragma unroll
    for (int i = 0; i < TM; ++i) {
        int m = m0 + ty * TM + i;
        size_t off = (size_t)m * Hh + c0;
        #pragma unroll
        for (int j = 0; j < TN; ++j)
            g_tmp[off + j] = acc[i][j] + b2[c0 + j] + g_h1[off + j];
    }
}

// ---------------- LayerNorm over H=1024 --------------------------------------
__device__ __forceinline__ void ln_row(
    const float* __restrict__ in, const float* __restrict__ gw,
    const float* __restrict__ bw, float* __restrict__ out)
{
    int row = blockIdx.x;
    const float4* rp = reinterpret_cast<const float4*>(in + (size_t)row * Hh);
    float4 v = rp[threadIdx.x];
    float s  = v.x + v.y + v.z + v.w;
    float s2 = v.x * v.x + v.y * v.y + v.z * v.z + v.w * v.w;
    #pragma unroll
    for (int o = 16; o; o >>= 1) {
        s  += __shfl_xor_sync(0xffffffffu, s,  o);
        s2 += __shfl_xor_sync(0xffffffffu, s2, o);
    }
    __shared__ float rs[8], rs2[8];
    int lane = threadIdx.x & 31, wid = threadIdx.x >> 5;
    if (lane == 0) { rs[wid] = s; rs2[wid] = s2; }
    __syncthreads();
    s = 0.f; s2 = 0.f;
    #pragma unroll
    for (int i = 0; i < 8; ++i) { s += rs[i]; s2 += rs2[i]; }
    float mu  = s  * (1.0f / Hh);
    float var = s2 * (1.0f / Hh) - mu * mu;
    float inv = rsqrtf(var + EPSLN);
    float4 g4 = reinterpret_cast<const float4*>(gw)[threadIdx.x];
    float4 b4 = reinterpret_cast<const float4*>(bw)[threadIdx.x];
    float4 o4;
    o4.x = (v.x - mu) * inv * g4.x + b4.x;
    o4.y = (v.y - mu) * inv * g4.y + b4.y;
    o4.z = (v.z - mu) * inv * g4.z + b4.z;
    o4.w = (v.w - mu) * inv * g4.w + b4.w;
    reinterpret_cast<float4*>(out + (size_t)row * Hh)[threadIdx.x] = o4;
}

__global__ __launch_bounds__(NT) void layernorm1_kernel(
    const float* __restrict__ gw, const float* __restrict__ bw)
{
    ln_row(g_tmp, gw, bw, g_h1);
}

__global__ __launch_bounds__(NT) void layernorm2_kernel(
    const float* __restrict__ gw, const float* __restrict__ bw,
    float* __restrict__ out)
{
    ln_row(g_tmp, gw, bw, out);
}

// ---------------- entry ------------------------------------------------------
extern "C" void kernel_launch(void* const* d_in, const int* in_sizes, int n_in,
                              void* d_out, int out_size)
{
    const float* x   = (const float*)d_in[0];
    const float* Wqr = (const float*)d_in[1];
    const float* Wqi = (const float*)d_in[2];
    const float* bqr = (const float*)d_in[3];
    const float* bqi = (const float*)d_in[4];
    const float* Wkr = (const float*)d_in[5];
    const float* Wki = (const float*)d_in[6];
    const float* bkr = (const float*)d_in[7];
    const float* bki = (const float*)d_in[8];
    const float* Wv  = (const float*)d_in[9];
    const float* bvv = (const float*)d_in[10];
    const float* pqr = (const float*)d_in[11];
    const float* pqi = (const float*)d_in[12];
    const float* pkr = (const float*)d_in[13];
    const float* pki = (const float*)d_in[14];
    const float* Wo  = (const float*)d_in[15];
    const float* bo  = (const float*)d_in[16];
    const float* W1  = (const float*)d_in[17];
    const float* b1  = (const float*)d_in[18];
    const float* W2  = (const float*)d_in[19];
    const float* b2  = (const float*)d_in[20];
    const float* g1  = (const float*)d_in[21];
    const float* be1 = (const float*)d_in[22];
    const float* g2  = (const float*)d_in[23];
    const float* be2 = (const float*)d_in[24];
    float* out = (float*)d_out;

    // 1. repack projection weights -> [H, 5*N*D]
    repack_kernel<<<(5 * Nn * Hh * Dd + NT - 1) / NT, NT>>>(Wqr, Wqi, Wkr, Wki, Wv);
    // 2. all five projections as one GEMM [4096,1024]x[1024,5120], fused epilogue
    gemm_proj_kernel<<<dim3(5120 / 128, (Bb * Ss) / 128), NT>>>(
        x, bqr, bqi, bkr, bki, bvv, pqr, pqi, pkr, pki);
    // 3. complex attention scores
    gemm_scores_kernel<<<dim3(Ss / 128, Ss / 128, Bb * Nn), NT>>>();
    // 4. softmax
    softmax_kernel<<<Bb * Nn * Ss, NT>>>();
    // 5. P @ V -> concat
    gemm_pv_kernel<<<dim3(1, Ss / 128, Bb * Nn), NT>>>();
    // 6. Wo + bias + residual
    gemm_wo_kernel<<<dim3(Hh / 128, (Bb * Ss) / 128), NT>>>(Wo, bo, x);
    // 7. LN1 -> h1
    layernorm1_kernel<<<Bb * Ss, NT>>>(g1, be1);
    // 8. FFN
    gemm_ff1_kernel<<<dim3(FFd / 128, (Bb * Ss) / 128), NT>>>(W1, b1);
    gemm_ff2_kernel<<<dim3(Hh / 128, (Bb * Ss) / 128), NT>>>(W2, b2);
    // 9. LN2 -> output
    layernorm2_kernel<<<Bb * Ss, NT>>>(g2, be2, out);
}

// round 2
// speedup vs baseline: 2.5260x; 2.5260x over previous
#include <cuda_runtime.h>
#include <math.h>
#include <stdint.h>

#define THREADS 256
constexpr int Bb  = 4;
constexpr int Ss  = 1024;
constexpr int Hh  = 1024;
constexpr int Nn  = 16;
constexpr int Dd  = 64;
constexpr int FFd = 4096;
constexpr float SCALE = 0.125f;   // 1/sqrt(64)
constexpr float EPSLN = 1e-5f;

// ---------------- scratch ----------------------------------------------------
__device__ float g_wpack[1024 * 5120];
__device__ float g_qr[Bb * Nn * Ss * Dd];
__device__ float g_qi[Bb * Nn * Ss * Dd];   // holds -qi_total*SCALE
__device__ float g_kr[Bb * Nn * Ss * Dd];
__device__ float g_ki[Bb * Nn * Ss * Dd];
__device__ float g_v [Bb * Nn * Ss * Dd];
__device__ float g_scores[(size_t)Bb * Nn * Ss * Ss];
__device__ float g_concat[Bb * Ss * Hh];
__device__ float g_h1[Bb * Ss * Hh];
__device__ float g_tmp[Bb * Ss * Hh];
__device__ float g_ff[(size_t)Bb * Ss * FFd];

// ---------------- tf32 helpers ------------------------------------------------
__device__ __forceinline__ uint32_t f2tf32(float x) {
    uint32_t r;
    asm("cvt.rna.tf32.f32 %0, %1;" : "=r"(r) : "f"(x));
    return r;
}

__device__ __forceinline__ void mma_tf32(float (&c)[4], const uint32_t (&a)[4],
                                         const uint32_t (&b)[2]) {
    asm volatile(
        "mma.sync.aligned.m16n8k8.row.col.f32.tf32.tf32.f32 "
        "{%0,%1,%2,%3}, {%4,%5,%6,%7}, {%8,%9}, {%0,%1,%2,%3};"
        : "+f"(c[0]), "+f"(c[1]), "+f"(c[2]), "+f"(c[3])
        : "r"(a[0]), "r"(a[1]), "r"(a[2]), "r"(a[3]), "r"(b[0]), "r"(b[1]));
}

// ---------------- tf32 tensor-core GEMM core ----------------------------------
// C(BM,BN) += A(M,K) @ B   (B row-major [K,N], or [N,K] if TRANSB -> A@B^T)
// 256 threads = 8 warps (WM x WN). Warp tile = MT*16 x NTT*8.
// Double-buffered smem, register-staged global loads, RNA tf32 conversion at
// smem store. Fragment layouts are bank-conflict free (A stride BK+4, B stride BN+8).
template<int BM, int BN, int BK, int MT, int NTT, int WM, int WN, bool TRANSB>
__device__ __forceinline__ void gemm_tf32(
    const float* __restrict__ A, int lda,
    const float* __restrict__ B, int ldb,
    int K, int m0, int n0,
    float (&acc)[MT][NTT][4],
    uint32_t* __restrict__ AsAll, uint32_t* __restrict__ BsAll)
{
    constexpr int SAK = BK + 4;
    constexpr int SBN = BN + 8;
    constexpr int ASZ = BM * SAK;
    constexpr int BSZ = BK * SBN;
    constexpr int A_LD = BM * BK / 4 / THREADS;
    constexpr int B_LD = BN * BK / 4 / THREADS;

    const int tid  = threadIdx.x;
    const int lane = tid & 31, wid = tid >> 5;
    const int wm = wid / WN, wn = wid % WN;
    const int g = lane >> 2, t = lane & 3;

    float4 ra[A_LD], rb[B_LD];

    auto load_g = [&](int k0) {
        #pragma unroll
        for (int u = 0; u < A_LD; ++u) {
            int idx = tid + u * THREADS;
            int m = idx >> 2, kq = idx & 3;
            ra[u] = *reinterpret_cast<const float4*>(
                A + (size_t)(m0 + m) * lda + k0 + kq * 4);
        }
        #pragma unroll
        for (int u = 0; u < B_LD; ++u) {
            int idx = tid + u * THREADS;
            if (!TRANSB) {
                int k = idx / (BN / 4), nq = idx % (BN / 4);
                rb[u] = *reinterpret_cast<const float4*>(
                    B + (size_t)(k0 + k) * ldb + n0 + nq * 4);
            } else {
                int n = idx >> 2, kq = idx & 3;
                rb[u] = *reinterpret_cast<const float4*>(
                    B + (size_t)(n0 + n) * ldb + k0 + kq * 4);
            }
        }
    };

    auto store_s = [&](int buf) {
        uint32_t* As = AsAll + buf * ASZ;
        uint32_t* Bs = BsAll + buf * BSZ;
        #pragma unroll
        for (int u = 0; u < A_LD; ++u) {
            int idx = tid + u * THREADS;
            int m = idx >> 2, kq = idx & 3;
            uint4 v = make_uint4(f2tf32(ra[u].x), f2tf32(ra[u].y),
                                 f2tf32(ra[u].z), f2tf32(ra[u].w));
            *reinterpret_cast<uint4*>(As + m * SAK + kq * 4) = v;
        }
        #pragma unroll
        for (int u = 0; u < B_LD; ++u) {
            int idx = tid + u * THREADS;
            if (!TRANSB) {
                int k = idx / (BN / 4), nq = idx % (BN / 4);
                uint4 v = make_uint4(f2tf32(rb[u].x), f2tf32(rb[u].y),
                                     f2tf32(rb[u].z), f2tf32(rb[u].w));
                *reinterpret_cast<uint4*>(Bs + k * SBN + nq * 4) = v;
            } else {
                int n = idx >> 2, kq = idx & 3;
                Bs[(kq * 4 + 0) * SBN + n] = f2tf32(rb[u].x);
                Bs[(kq * 4 + 1) * SBN + n] = f2tf32(rb[u].y);
                Bs[(kq * 4 + 2) * SBN + n] = f2tf32(rb[u].z);
                Bs[(kq * 4 + 3) * SBN + n] = f2tf32(rb[u].w);
            }
        }
    };

    auto compute = [&](int buf) {
        uint32_t* As = AsAll + buf * ASZ;
        uint32_t* Bs = BsAll + buf * BSZ;
        #pragma unroll
        for (int kk = 0; kk < BK; kk += 8) {
            uint32_t af[MT][4], bf[NTT][2];
            #pragma unroll
            for (int i = 0; i < MT; ++i) {
                int mr = (wm * MT + i) * 16 + g;
                af[i][0] = As[mr * SAK + kk + t];
                af[i][1] = As[(mr + 8) * SAK + kk + t];
                af[i][2] = As[mr * SAK + kk + t + 4];
                af[i][3] = As[(mr + 8) * SAK + kk + t + 4];
            }
            #pragma unroll
            for (int j = 0; j < NTT; ++j) {
                int nc = (wn * NTT + j) * 8 + g;
                bf[j][0] = Bs[(kk + t) * SBN + nc];
                bf[j][1] = Bs[(kk + t + 4) * SBN + nc];
            }
            #pragma unroll
            for (int i = 0; i < MT; ++i)
                #pragma unroll
                for (int j = 0; j < NTT; ++j)
                    mma_tf32(acc[i][j], af[i], bf[j]);
        }
    };

    load_g(0);
    store_s(0);
    __syncthreads();
    int buf = 0;
    for (int k0 = BK; k0 < K; k0 += BK) {
        load_g(k0);
        compute(buf);
        store_s(buf ^ 1);
        __syncthreads();
        buf ^= 1;
    }
    compute(buf);
}

// Standard config used by the big GEMMs
constexpr int gBM = 128, gBN = 128, gBK = 16, gMT = 4, gNT = 4, gWM = 2, gWN = 4;
constexpr int gSAK = gBK + 4, gSBN = gBN + 8;
constexpr int gASZ = gBM * gSAK, gBSZ = gBK * gSBN;

// ---------------- weight repack: 5x [N,H,D] -> [H, 5*N*D] ----------------------
__global__ __launch_bounds__(THREADS) void repack_kernel(
    const float* __restrict__ Wqr, const float* __restrict__ Wqi,
    const float* __restrict__ Wkr, const float* __restrict__ Wki,
    const float* __restrict__ Wv)
{
    const int per = Nn * Hh * Dd;
    int idx = blockIdx.x * THREADS + threadIdx.x;
    if (idx >= 5 * per) return;
    int p = idx / per;
    int r = idx % per;
    const float* W = (p == 0) ? Wqr : (p == 1) ? Wqi : (p == 2) ? Wkr
                    : (p == 3) ? Wki : Wv;
    int n = r >> 16;
    int k = (r >> 6) & 1023;
    int d = r & 63;
    g_wpack[(size_t)k * 5120 + (p << 10) + (n << 6) + d] = W[r];
}

// ---------------- fused QKV/V projection --------------------------------------
__global__ __launch_bounds__(THREADS) void gemm_proj_kernel(
    const float* __restrict__ x,
    const float* __restrict__ bqr, const float* __restrict__ bqi,
    const float* __restrict__ bkr, const float* __restrict__ bki,
    const float* __restrict__ bvv,
    const float* __restrict__ pqr, const float* __restrict__ pqi,
    const float* __restrict__ pkr, const float* __restrict__ pki)
{
    __shared__ __align__(16) uint32_t As[2 * gASZ];
    __shared__ __align__(16) uint32_t Bs[2 * gBSZ];
    float acc[gMT][gNT][4] = {};
    int m0 = blockIdx.y * gBM, n0 = blockIdx.x * gBN;
    gemm_tf32<gBM, gBN, gBK, gMT, gNT, gWM, gWN, false>(
        x, Hh, g_wpack, 5120, Hh, m0, n0, acc, As, Bs);

    const int lane = threadIdx.x & 31, wid = threadIdx.x >> 5;
    const int wm = wid / gWN, wn = wid % gWN;
    const int g = lane >> 2, t = lane & 3;

    auto emit = [&](int row, int col, float v0, float v1) {
        int p = col >> 10, n = (col >> 6) & 15, d = col & 63;
        int b = row >> 10, s = row & 1023;
        size_t pidx = (((size_t)n << 10) + s) * Dd + d;
        const float* bias = (p == 0) ? bqr : (p == 1) ? bqi : (p == 2) ? bkr
                           : (p == 3) ? bki : bvv;
        float* out = (p == 0) ? g_qr : (p == 1) ? g_qi : (p == 2) ? g_kr
                    : (p == 3) ? g_ki : g_v;
        float x0 = v0 + bias[n * Dd + d];
        float x1 = v1 + bias[n * Dd + d + 1];
        if (p == 0) {
            x0 = (x0 * SCALE + pqr[pidx]) * SCALE;
            x1 = (x1 * SCALE + pqr[pidx + 1]) * SCALE;
        } else if (p == 1) {
            x0 = -((x0 * SCALE + pqi[pidx]) * SCALE);
            x1 = -((x1 * SCALE + pqi[pidx + 1]) * SCALE);
        } else if (p == 2) {
            x0 += pkr[pidx]; x1 += pkr[pidx + 1];
        } else if (p == 3) {
            x0 += pki[pidx]; x1 += pki[pidx + 1];
        }
        size_t o = ((((size_t)b * Nn + n) << 10) + s) * Dd + d;
        out[o] = x0; out[o + 1] = x1;
    };

    #pragma unroll
    for (int i = 0; i < gMT; ++i) {
        int r0 = m0 + (wm * gMT + i) * 16 + g;
        #pragma unroll
        for (int j = 0; j < gNT; ++j) {
            int c0 = n0 + (wn * gNT + j) * 8 + 2 * t;
            emit(r0,     c0, acc[i][j][0], acc[i][j][1]);
            emit(r0 + 8, c0, acc[i][j][2], acc[i][j][3]);
        }
    }
}

// ---------------- complex scores: qr@krT + (-qi)@kiT (scales pre-folded) ------
__global__ __launch_bounds__(THREADS) void gemm_scores_kernel()
{
    __shared__ __align__(16) uint32_t As[2 * gASZ];
    __shared__ __align__(16) uint32_t Bs[2 * gBSZ];
    float acc[gMT][gNT][4] = {};
    int bh = blockIdx.z;
    int m0 = blockIdx.y * gBM, n0 = blockIdx.x * gBN;
    const float* qr = g_qr + (size_t)bh * Ss * Dd;
    const float* qi = g_qi + (size_t)bh * Ss * Dd;
    const float* kr = g_kr + (size_t)bh * Ss * Dd;
    const float* ki = g_ki + (size_t)bh * Ss * Dd;
    gemm_tf32<gBM, gBN, gBK, gMT, gNT, gWM, gWN, true>(
        qr, Dd, kr, Dd, Dd, m0, n0, acc, As, Bs);
    __syncthreads();
    gemm_tf32<gBM, gBN, gBK, gMT, gNT, gWM, gWN, true>(
        qi, Dd, ki, Dd, Dd, m0, n0, acc, As, Bs);

    const int lane = threadIdx.x & 31, wid = threadIdx.x >> 5;
    const int wm = wid / gWN, wn = wid % gWN;
    const int g = lane >> 2, t = lane & 3;
    float* base = g_scores + (size_t)bh * Ss * Ss;
    #pragma unroll
    for (int i = 0; i < gMT; ++i) {
        int r0 = m0 + (wm * gMT + i) * 16 + g;
        #pragma unroll
        for (int j = 0; j < gNT; ++j) {
            int c0 = n0 + (wn * gNT + j) * 8 + 2 * t;
            *reinterpret_cast<float2*>(base + (size_t)r0 * Ss + c0) =
                make_float2(acc[i][j][0], acc[i][j][1]);
            *reinterpret_cast<float2*>(base + (size_t)(r0 + 8) * Ss + c0) =
                make_float2(acc[i][j][2], acc[i][j][3]);
        }
    }
}

// ---------------- row softmax over S=1024, in place ----------------------------
__global__ __launch_bounds__(THREADS) void softmax_kernel()
{
    float4* rp = reinterpret_cast<float4*>(g_scores + (size_t)blockIdx.x * Ss);
    float4 v = rp[threadIdx.x];
    int lane = threadIdx.x & 31, wid = threadIdx.x >> 5;
    __shared__ float red[8];

    float m = fmaxf(fmaxf(v.x, v.y), fmaxf(v.z, v.w));
    #pragma unroll
    for (int o = 16; o; o >>= 1) m = fmaxf(m, __shfl_xor_sync(0xffffffffu, m, o));
    if (lane == 0) red[wid] = m;
    __syncthreads();
    float M = red[0];
    #pragma unroll
    for (int i = 1; i < 8; ++i) M = fmaxf(M, red[i]);

    v.x = __expf(v.x - M); v.y = __expf(v.y - M);
    v.z = __expf(v.z - M); v.w = __expf(v.w - M);
    float s = v.x + v.y + v.z + v.w;
    #pragma unroll
    for (int o = 16; o; o >>= 1) s += __shfl_xor_sync(0xffffffffu, s, o);
    __syncthreads();
    if (lane == 0) red[wid] = s;
    __syncthreads();
    float Z = 0.f;
    #pragma unroll
    for (int i = 0; i < 8; ++i) Z += red[i];
    float inv = 1.0f / Z;
    v.x *= inv; v.y *= inv; v.z *= inv; v.w *= inv;
    rp[threadIdx.x] = v;
}

// ---------------- P @ V -> concat ----------------------------------------------
__global__ __launch_bounds__(THREADS) void gemm_pv_kernel()
{
    constexpr int BN = 64, NTT = 2;
    constexpr int SBN = BN + 8, BSZ = gBK * SBN;
    __shared__ __align__(16) uint32_t As[2 * gASZ];
    __shared__ __align__(16) uint32_t Bs[2 * BSZ];
    float acc[gMT][NTT][4] = {};
    int bh = blockIdx.z; int b = bh >> 4, n = bh & 15;
    int m0 = blockIdx.y * gBM;
    const float* P = g_scores + (size_t)bh * Ss * Ss;
    const float* V = g_v      + (size_t)bh * Ss * Dd;
    gemm_tf32<gBM, BN, gBK, gMT, NTT, gWM, gWN, false>(
        P, Ss, V, Dd, Ss, m0, 0, acc, As, Bs);

    const int lane = threadIdx.x & 31, wid = threadIdx.x >> 5;
    const int wm = wid / gWN, wn = wid % gWN;
    const int g = lane >> 2, t = lane & 3;
    #pragma unroll
    for (int i = 0; i < gMT; ++i) {
        int s = m0 + (wm * gMT + i) * 16 + g;
        #pragma unroll
        for (int j = 0; j < NTT; ++j) {
            int c0 = (wn * NTT + j) * 8 + 2 * t;
            float* o0 = g_concat + ((size_t)(b * Ss + s)) * Hh + n * Dd + c0;
            float* o1 = g_concat + ((size_t)(b * Ss + s + 8)) * Hh + n * Dd + c0;
            *reinterpret_cast<float2*>(o0) = make_float2(acc[i][j][0], acc[i][j][1]);
            *reinterpret_cast<float2*>(o1) = make_float2(acc[i][j][2], acc[i][j][3]);
        }
    }
}

// ---------------- Wo + bias + residual(x) -> g_tmp ------------------------------
__global__ __launch_bounds__(THREADS) void gemm_wo_kernel(
    const float* __restrict__ Wo, const float* __restrict__ bo,
    const float* __restrict__ x)
{
    __shared__ __align__(16) uint32_t As[2 * gASZ];
    __shared__ __align__(16) uint32_t Bs[2 * gBSZ];
    float acc[gMT][gNT][4] = {};
    int m0 = blockIdx.y * gBM, n0 = blockIdx.x * gBN;
    gemm_tf32<gBM, gBN, gBK, gMT, gNT, gWM, gWN, false>(
        g_concat, Hh, Wo, Hh, Hh, m0, n0, acc, As, Bs);

    const int lane = threadIdx.x & 31, wid = threadIdx.x >> 5;
    const int wm = wid / gWN, wn = wid % gWN;
    const int g = lane >> 2, t = lane & 3;
    #pragma unroll
    for (int i = 0; i < gMT; ++i) {
        int r0 = m0 + (wm * gMT + i) * 16 + g;
        #pragma unroll
        for (int j = 0; j < gNT; ++j) {
            int c0 = n0 + (wn * gNT + j) * 8 + 2 * t;
            size_t o0 = (size_t)r0 * Hh + c0, o1 = (size_t)(r0 + 8) * Hh + c0;
            g_tmp[o0]     = acc[i][j][0] + bo[c0]     + x[o0];
            g_tmp[o0 + 1] = acc[i][j][1] + bo[c0 + 1] + x[o0 + 1];
            g_tmp[o1]     = acc[i][j][2] + bo[c0]     + x[o1];
            g_tmp[o1 + 1] = acc[i][j][3] + bo[c0 + 1] + x[o1 + 1];
        }
    }
}

// ---------------- FFN 1: relu(h1 @ W1 + b1) ------------------------------------
__global__ __launch_bounds__(THREADS) void gemm_ff1_kernel(
    const float* __restrict__ W1, const float* __restrict__ b1)
{
    __shared__ __align__(16) uint32_t As[2 * gASZ];
    __shared__ __align__(16) uint32_t Bs[2 * gBSZ];
    float acc[gMT][gNT][4] = {};
    int m0 = blockIdx.y * gBM, n0 = blockIdx.x * gBN;
    gemm_tf32<gBM, gBN, gBK, gMT, gNT, gWM, gWN, false>(
        g_h1, Hh, W1, FFd, Hh, m0, n0, acc, As, Bs);

    const int lane = threadIdx.x & 31, wid = threadIdx.x >> 5;
    const int wm = wid / gWN, wn = wid % gWN;
    const int g = lane >> 2, t = lane & 3;
    #pragma unroll
    for (int i = 0; i < gMT; ++i) {
        int r0 = m0 + (wm * gMT + i) * 16 + g;
        #pragma unroll
        for (int j = 0; j < gNT; ++j) {
            int c0 = n0 + (wn * gNT + j) * 8 + 2 * t;
            size_t o0 = (size_t)r0 * FFd + c0, o1 = (size_t)(r0 + 8) * FFd + c0;
            g_ff[o0]     = fmaxf(acc[i][j][0] + b1[c0],     0.f);
            g_ff[o0 + 1] = fmaxf(acc[i][j][1] + b1[c0 + 1], 0.f);
            g_ff[o1]     = fmaxf(acc[i][j][2] + b1[c0],     0.f);
            g_ff[o1 + 1] = fmaxf(acc[i][j][3] + b1[c0 + 1], 0.f);
        }
    }
}

// ---------------- FFN 2: g_ff @ W2 + b2 + h1 -> g_tmp ---------------------------
__global__ __launch_bounds__(THREADS) void gemm_ff2_kernel(
    const float* __restrict__ W2, const float* __restrict__ b2)
{
    __shared__ __align__(16) uint32_t As[2 * gASZ];
    __shared__ __align__(16) uint32_t Bs[2 * gBSZ];
    float acc[gMT][gNT][4] = {};
    int m0 = blockIdx.y * gBM, n0 = blockIdx.x * gBN;
    gemm_tf32<gBM, gBN, gBK, gMT, gNT, gWM, gWN, false>(
        g_ff, FFd, W2, Hh, FFd, m0, n0, acc, As, Bs);

    const int lane = threadIdx.x & 31, wid = threadIdx.x >> 5;
    const int wm = wid / gWN, wn = wid % gWN;
    const int g = lane >> 2, t = lane & 3;
    #pragma unroll
    for (int i = 0; i < gMT; ++i) {
        int r0 = m0 + (wm * gMT + i) * 16 + g;
        #pragma unroll
        for (int j = 0; j < gNT; ++j) {
            int c0 = n0 + (wn * gNT + j) * 8 + 2 * t;
            size_t o0 = (size_t)r0 * Hh + c0, o1 = (size_t)(r0 + 8) * Hh + c0;
            g_tmp[o0]     = acc[i][j][0] + b2[c0]     + g_h1[o0];
            g_tmp[o0 + 1] = acc[i][j][1] + b2[c0 + 1] + g_h1[o0 + 1];
            g_tmp[o1]     = acc[i][j][2] + b2[c0]     + g_h1[o1];
            g_tmp[o1 + 1] = acc[i][j][3] + b2[c0 + 1] + g_h1[o1 + 1];
        }
    }
}

// ---------------- LayerNorm over H=1024 ----------------------------------------
__device__ __forceinline__ void ln_row(
    const float* __restrict__ in, const float* __restrict__ gw,
    const float* __restrict__ bw, float* __restrict__ out)
{
    int row = blockIdx.x;
    const float4* rp = reinterpret_cast<const float4*>(in + (size_t)row * Hh);
    float4 v = rp[threadIdx.x];
    float s  = v.x + v.y + v.z + v.w;
    float s2 = v.x * v.x + v.y * v.y + v.z * v.z + v.w * v.w;
    #pragma unroll
    for (int o = 16; o; o >>= 1) {
        s  += __shfl_xor_sync(0xffffffffu, s,  o);
        s2 += __shfl_xor_sync(0xffffffffu, s2, o);
    }
    __shared__ float rs[8], rs2[8];
    int lane = threadIdx.x & 31, wid = threadIdx.x >> 5;
    if (lane == 0) { rs[wid] = s; rs2[wid] = s2; }
    __syncthreads();
    s = 0.f; s2 = 0.f;
    #pragma unroll
    for (int i = 0; i < 8; ++i) { s += rs[i]; s2 += rs2[i]; }
    float mu  = s  * (1.0f / Hh);
    float var = s2 * (1.0f / Hh) - mu * mu;
    float inv = rsqrtf(var + EPSLN);
    float4 g4 = reinterpret_cast<const float4*>(gw)[threadIdx.x];
    float4 b4 = reinterpret_cast<const float4*>(bw)[threadIdx.x];
    float4 o4;
    o4.x = (v.x - mu) * inv * g4.x + b4.x;
    o4.y = (v.y - mu) * inv * g4.y + b4.y;
    o4.z = (v.z - mu) * inv * g4.z + b4.z;
    o4.w = (v.w - mu) * inv * g4.w + b4.w;
    reinterpret_cast<float4*>(out + (size_t)row * Hh)[threadIdx.x] = o4;
}

__global__ __launch_bounds__(THREADS) void layernorm1_kernel(
    const float* __restrict__ gw, const float* __restrict__ bw)
{
    ln_row(g_tmp, gw, bw, g_h1);
}

__global__ __launch_bounds__(THREADS) void layernorm2_kernel(
    const float* __restrict__ gw, const float* __restrict__ bw,
    float* __restrict__ out)
{
    ln_row(g_tmp, gw, bw, out);
}

// ---------------- entry ---------------------------------------------------------
extern "C" void kernel_launch(void* const* d_in, const int* in_sizes, int n_in,
                              void* d_out, int out_size)
{
    const float* x   = (const float*)d_in[0];
    const float* Wqr = (const float*)d_in[1];
    const float* Wqi = (const float*)d_in[2];
    const float* bqr = (const float*)d_in[3];
    const float* bqi = (const float*)d_in[4];
    const float* Wkr = (const float*)d_in[5];
    const float* Wki = (const float*)d_in[6];
    const float* bkr = (const float*)d_in[7];
    const float* bki = (const float*)d_in[8];
    const float* Wv  = (const float*)d_in[9];
    const float* bvv = (const float*)d_in[10];
    const float* pqr = (const float*)d_in[11];
    const float* pqi = (const float*)d_in[12];
    const float* pkr = (const float*)d_in[13];
    const float* pki = (const float*)d_in[14];
    const float* Wo  = (const float*)d_in[15];
    const float* bo  = (const float*)d_in[16];
    const float* W1  = (const float*)d_in[17];
    const float* b1  = (const float*)d_in[18];
    const float* W2  = (const float*)d_in[19];
    const float* b2  = (const float*)d_in[20];
    const float* g1  = (const float*)d_in[21];
    const float* be1 = (const float*)d_in[22];
    const float* g2  = (const float*)d_in[23];
    const float* be2 = (const float*)d_in[24];
    float* out = (float*)d_out;

    repack_kernel<<<(5 * Nn * Hh * Dd + THREADS - 1) / THREADS, THREADS>>>(
        Wqr, Wqi, Wkr, Wki, Wv);
    gemm_proj_kernel<<<dim3(5120 / gBN, (Bb * Ss) / gBM), THREADS>>>(
        x, bqr, bqi, bkr, bki, bvv, pqr, pqi, pkr, pki);
    gemm_scores_kernel<<<dim3(Ss / gBN, Ss / gBM, Bb * Nn), THREADS>>>();
    softmax_kernel<<<Bb * Nn * Ss, THREADS>>>();
    gemm_pv_kernel<<<dim3(1, Ss / gBM, Bb * Nn), THREADS>>>();
    gemm_wo_kernel<<<dim3(Hh / gBN, (Bb * Ss) / gBM), THREADS>>>(Wo, bo, x);
    layernorm1_kernel<<<Bb * Ss, THREADS>>>(g1, be1);
    gemm_ff1_kernel<<<dim3(FFd / gBN, (Bb * Ss) / gBM), THREADS>>>(W1, b1);
    gemm_ff2_kernel<<<dim3(Hh / gBN, (Bb * Ss) / gBM), THREADS>>>(W2, b2);
    layernorm2_kernel<<<Bb * Ss, THREADS>>>(g2, be2, out);
}

// round 3
// speedup vs baseline: 2.9707x; 1.1760x over previous
#include <cuda_runtime.h>
#include <math.h>
#include <stdint.h>

#define THREADS 256
constexpr int Bb  = 4;
constexpr int Ss  = 1024;
constexpr int Hh  = 1024;
constexpr int Nn  = 16;
constexpr int Dd  = 64;
constexpr int FFd = 4096;
constexpr float SCALE = 0.125f;
constexpr float EPSLN = 1e-5f;

// ---------------- scratch -----------------------------------------------------
// tf32-bit operand buffers (uint32) and f32 buffers
__device__ uint32_t g_wpack[1024 * 5120];
__device__ uint32_t g_xt  [Bb * Ss * Hh];
__device__ uint32_t g_wot [Hh * Hh];
__device__ uint32_t g_w1t [Hh * FFd];
__device__ uint32_t g_w2t [FFd * Hh];
__device__ uint32_t g_qr[Bb * Nn * Ss * Dd];
__device__ uint32_t g_qi[Bb * Nn * Ss * Dd];   // holds tf32(-qi_total*SCALE)
__device__ uint32_t g_kr[Bb * Nn * Ss * Dd];
__device__ uint32_t g_ki[Bb * Nn * Ss * Dd];
__device__ uint32_t g_v [Bb * Nn * Ss * Dd];
__device__ float    g_scores[(size_t)Bb * Nn * Ss * Ss]; // softmax rewrites as tf32 bits
__device__ uint32_t g_concat[Bb * Ss * Hh];
__device__ float    g_h1 [Bb * Ss * Hh];
__device__ uint32_t g_h1t[Bb * Ss * Hh];
__device__ float    g_tmp[Bb * Ss * Hh];
__device__ uint32_t g_ff[(size_t)Bb * Ss * FFd];

// ---------------- helpers ------------------------------------------------------
__device__ __forceinline__ uint32_t f2tf32(float x) {
    uint32_t r;
    asm("cvt.rna.tf32.f32 %0, %1;" : "=r"(r) : "f"(x));
    return r;
}
__device__ __forceinline__ void mma_tf32(float (&c)[4], const uint32_t (&a)[4],
                                         const uint32_t (&b)[2]) {
    asm volatile(
        "mma.sync.aligned.m16n8k8.row.col.f32.tf32.tf32.f32 "
        "{%0,%1,%2,%3}, {%4,%5,%6,%7}, {%8,%9}, {%0,%1,%2,%3};"
        : "+f"(c[0]), "+f"(c[1]), "+f"(c[2]), "+f"(c[3])
        : "r"(a[0]), "r"(a[1]), "r"(a[2]), "r"(a[3]), "r"(b[0]), "r"(b[1]));
}
__device__ __forceinline__ uint32_t smem_u32(const void* p) {
    return (uint32_t)__cvta_generic_to_shared(p);
}
__device__ __forceinline__ void cp16(uint32_t dst, const void* src) {
    asm volatile("cp.async.cg.shared.global [%0], [%1], 16;" :: "r"(dst), "l"(src));
}
__device__ __forceinline__ void cp_commit() {
    asm volatile("cp.async.commit_group;");
}
template<int N> __device__ __forceinline__ void cp_wait() {
    asm volatile("cp.async.wait_group %0;" :: "n"(N));
}

// ---------------- tf32 tensor-core GEMM core (cp.async, 3-stage) ----------------
// Operands are PRE-CONVERTED tf32 bit patterns (uint32).
// A row-major [M,K] (lda). B row-major [K,N] (ldb), or [N,K] if TRANSB (A@B^T).
// 8 warps (WM x WN), warp tile MT*16 x NTT*8. Conflict-free smem layouts.
template<int BM, int BN, int BK, int MT, int NTT, int WM, int WN, bool TRANSB,
         int STAGES>
__device__ __forceinline__ void gemm_tc(
    const uint32_t* __restrict__ A, int lda,
    const uint32_t* __restrict__ B, int ldb,
    int K, int m0, int n0,
    float (&acc)[MT][NTT][4], uint32_t* sA, uint32_t* sB)
{
    constexpr int SAK = BK + 4;                 // A smem row stride ([m][k])
    constexpr int SBN = BN + 8;                 // B smem row stride ([k][n])
    constexpr int SBK = BK + 4;                 // B smem row stride ([n][k], TRANSB)
    constexpr int ASZ = BM * SAK;
    constexpr int BSZ = TRANSB ? BN * SBK : BK * SBN;
    constexpr int A_LD = BM * BK / 4 / THREADS;
    constexpr int B_LD = BN * BK / 4 / THREADS;

    const int tid  = threadIdx.x;
    const int lane = tid & 31, wid = tid >> 5;
    const int wm = wid / WN, wn = wid % WN;
    const int g = lane >> 2, t = lane & 3;

    auto load_tile = [&](int stg, int k0) {
        uint32_t aB = smem_u32(sA + stg * ASZ);
        uint32_t bB = smem_u32(sB + stg * BSZ);
        #pragma unroll
        for (int u = 0; u < A_LD; ++u) {
            int idx = tid + u * THREADS;
            int m = idx >> 2, kq = idx & 3;
            cp16(aB + (m * SAK + kq * 4) * 4,
                 A + (size_t)(m0 + m) * lda + k0 + kq * 4);
        }
        #pragma unroll
        for (int u = 0; u < B_LD; ++u) {
            int idx = tid + u * THREADS;
            if (!TRANSB) {
                int k = idx / (BN / 4), nq = idx % (BN / 4);
                cp16(bB + (k * SBN + nq * 4) * 4,
                     B + (size_t)(k0 + k) * ldb + n0 + nq * 4);
            } else {
                int n = idx >> 2, kq = idx & 3;
                cp16(bB + (n * SBK + kq * 4) * 4,
                     B + (size_t)(n0 + n) * ldb + k0 + kq * 4);
            }
        }
    };

    auto compute = [&](int stg) {
        uint32_t* As = sA + stg * ASZ;
        uint32_t* Bs = sB + stg * BSZ;
        #pragma unroll
        for (int kk = 0; kk < BK; kk += 8) {
            uint32_t af[MT][4], bf[NTT][2];
            #pragma unroll
            for (int i = 0; i < MT; ++i) {
                int mr = (wm * MT + i) * 16 + g;
                af[i][0] = As[mr * SAK + kk + t];
                af[i][1] = As[(mr + 8) * SAK + kk + t];
                af[i][2] = As[mr * SAK + kk + t + 4];
                af[i][3] = As[(mr + 8) * SAK + kk + t + 4];
            }
            #pragma unroll
            for (int j = 0; j < NTT; ++j) {
                int nc = (wn * NTT + j) * 8 + g;
                if (!TRANSB) {
                    bf[j][0] = Bs[(kk + t) * SBN + nc];
                    bf[j][1] = Bs[(kk + t + 4) * SBN + nc];
                } else {
                    bf[j][0] = Bs[nc * SBK + kk + t];
                    bf[j][1] = Bs[nc * SBK + kk + t + 4];
                }
            }
            #pragma unroll
            for (int i = 0; i < MT; ++i)
                #pragma unroll
                for (int j = 0; j < NTT; ++j)
                    mma_tf32(acc[i][j], af[i], bf[j]);
        }
    };

    const int k_tiles = K / BK;
    #pragma unroll
    for (int s = 0; s < STAGES - 1; ++s) {
        if (s < k_tiles) load_tile(s, s * BK);
        cp_commit();
    }
    for (int tI = 0; tI < k_tiles; ++tI) {
        int nt = tI + STAGES - 1;
        if (nt < k_tiles) load_tile(nt % STAGES, nt * BK);
        cp_commit();
        cp_wait<STAGES - 2>();
        __syncthreads();
        compute(tI % STAGES);
        __syncthreads();
    }
}

// GEMM config
constexpr int gBM = 128, gBN = 128, gBK = 16, gMT = 4, gNT = 4;
constexpr int gWM = 2, gWN = 4, gST = 3;
constexpr int gASZ = gBM * (gBK + 4);
constexpr int gBSZ_N = gBK * (gBN + 8);        // non-trans
constexpr int gBSZ_T = gBN * (gBK + 4);        // trans
constexpr size_t SM_STD  = (size_t)(gASZ + gBSZ_N) * gST * 4;   // 56832 B
constexpr size_t SM_TR   = (size_t)(gASZ + gBSZ_T) * gST * 4;   // 61440 B
constexpr int pBN = 64;
constexpr int pBSZ = gBK * (pBN + 8);
constexpr size_t SM_PV   = (size_t)(gASZ + pBSZ) * gST * 4;     // 44544 B

// ---------------- pre-conversion kernels ----------------------------------------
__global__ __launch_bounds__(THREADS) void convert_kernel(
    const float4* __restrict__ src, uint4* __restrict__ dst, int n4)
{
    int i = blockIdx.x * THREADS + threadIdx.x;
    if (i >= n4) return;
    float4 v = src[i];
    dst[i] = make_uint4(f2tf32(v.x), f2tf32(v.y), f2tf32(v.z), f2tf32(v.w));
}

__global__ __launch_bounds__(THREADS) void repack_kernel(
    const float* __restrict__ Wqr, const float* __restrict__ Wqi,
    const float* __restrict__ Wkr, const float* __restrict__ Wki,
    const float* __restrict__ Wv)
{
    const int per = Nn * Hh * Dd;
    int idx = blockIdx.x * THREADS + threadIdx.x;
    if (idx >= 5 * per) return;
    int p = idx / per;
    int r = idx % per;
    const float* W = (p == 0) ? Wqr : (p == 1) ? Wqi : (p == 2) ? Wkr
                    : (p == 3) ? Wki : Wv;
    int n = r >> 16;
    int k = (r >> 6) & 1023;
    int d = r & 63;
    g_wpack[(size_t)k * 5120 + (p << 10) + (n << 6) + d] = f2tf32(W[r]);
}

// ---------------- fused QKV/V projection -----------------------------------------
__global__ __launch_bounds__(THREADS) void gemm_proj_kernel(
    const float* __restrict__ bqr, const float* __restrict__ bqi,
    const float* __restrict__ bkr, const float* __restrict__ bki,
    const float* __restrict__ bvv,
    const float* __restrict__ pqr, const float* __restrict__ pqi,
    const float* __restrict__ pkr, const float* __restrict__ pki)
{
    extern __shared__ uint32_t sm[];
    uint32_t* sA = sm;
    uint32_t* sB = sm + gST * gASZ;
    float acc[gMT][gNT][4] = {};
    int m0 = blockIdx.y * gBM, n0 = blockIdx.x * gBN;
    gemm_tc<gBM, gBN, gBK, gMT, gNT, gWM, gWN, false, gST>(
        g_xt, Hh, g_wpack, 5120, Hh, m0, n0, acc, sA, sB);

    const int lane = threadIdx.x & 31, wid = threadIdx.x >> 5;
    const int wm = wid / gWN, wn = wid % gWN;
    const int g = lane >> 2, t = lane & 3;

    auto emit = [&](int row, int col, float v0, float v1) {
        int p = col >> 10, n = (col >> 6) & 15, d = col & 63;
        int b = row >> 10, s = row & 1023;
        size_t pidx = (((size_t)n << 10) + s) * Dd + d;
        const float* bias = (p == 0) ? bqr : (p == 1) ? bqi : (p == 2) ? bkr
                           : (p == 3) ? bki : bvv;
        uint32_t* out = (p == 0) ? g_qr : (p == 1) ? g_qi : (p == 2) ? g_kr
                       : (p == 3) ? g_ki : g_v;
        float x0 = v0 + bias[n * Dd + d];
        float x1 = v1 + bias[n * Dd + d + 1];
        if (p == 0) {
            x0 = (x0 * SCALE + pqr[pidx]) * SCALE;
            x1 = (x1 * SCALE + pqr[pidx + 1]) * SCALE;
        } else if (p == 1) {
            x0 = -((x0 * SCALE + pqi[pidx]) * SCALE);
            x1 = -((x1 * SCALE + pqi[pidx + 1]) * SCALE);
        } else if (p == 2) {
            x0 += pkr[pidx]; x1 += pkr[pidx + 1];
        } else if (p == 3) {
            x0 += pki[pidx]; x1 += pki[pidx + 1];
        }
        size_t o = ((((size_t)b * Nn + n) << 10) + s) * Dd + d;
        out[o] = f2tf32(x0); out[o + 1] = f2tf32(x1);
    };

    #pragma unroll
    for (int i = 0; i < gMT; ++i) {
        int r0 = m0 + (wm * gMT + i) * 16 + g;
        #pragma unroll
        for (int j = 0; j < gNT; ++j) {
            int c0 = n0 + (wn * gNT + j) * 8 + 2 * t;
            emit(r0,     c0, acc[i][j][0], acc[i][j][1]);
            emit(r0 + 8, c0, acc[i][j][2], acc[i][j][3]);
        }
    }
}

// ---------------- complex scores: qr@krT + (-qi)@kiT ------------------------------
__global__ __launch_bounds__(THREADS) void gemm_scores_kernel()
{
    extern __shared__ uint32_t sm[];
    uint32_t* sA = sm;
    uint32_t* sB = sm + gST * gASZ;
    float acc[gMT][gNT][4] = {};
    int bh = blockIdx.z;
    int m0 = blockIdx.y * gBM, n0 = blockIdx.x * gBN;
    const uint32_t* qr = g_qr + (size_t)bh * Ss * Dd;
    const uint32_t* qi = g_qi + (size_t)bh * Ss * Dd;
    const uint32_t* kr = g_kr + (size_t)bh * Ss * Dd;
    const uint32_t* ki = g_ki + (size_t)bh * Ss * Dd;
    gemm_tc<gBM, gBN, gBK, gMT, gNT, gWM, gWN, true, gST>(
        qr, Dd, kr, Dd, Dd, m0, n0, acc, sA, sB);
    gemm_tc<gBM, gBN, gBK, gMT, gNT, gWM, gWN, true, gST>(
        qi, Dd, ki, Dd, Dd, m0, n0, acc, sA, sB);

    const int lane = threadIdx.x & 31, wid = threadIdx.x >> 5;
    const int wm = wid / gWN, wn = wid % gWN;
    const int g = lane >> 2, t = lane & 3;
    float* base = g_scores + (size_t)bh * Ss * Ss;
    #pragma unroll
    for (int i = 0; i < gMT; ++i) {
        int r0 = m0 + (wm * gMT + i) * 16 + g;
        #pragma unroll
        for (int j = 0; j < gNT; ++j) {
            int c0 = n0 + (wn * gNT + j) * 8 + 2 * t;
            *reinterpret_cast<float2*>(base + (size_t)r0 * Ss + c0) =
                make_float2(acc[i][j][0], acc[i][j][1]);
            *reinterpret_cast<float2*>(base + (size_t)(r0 + 8) * Ss + c0) =
                make_float2(acc[i][j][2], acc[i][j][3]);
        }
    }
}

// ---------------- row softmax, emits tf32 bits in place ----------------------------
__global__ __launch_bounds__(THREADS) void softmax_kernel()
{
    float4* rp = reinterpret_cast<float4*>(g_scores + (size_t)blockIdx.x * Ss);
    float4 v = rp[threadIdx.x];
    int lane = threadIdx.x & 31, wid = threadIdx.x >> 5;
    __shared__ float red[8];

    float m = fmaxf(fmaxf(v.x, v.y), fmaxf(v.z, v.w));
    #pragma unroll
    for (int o = 16; o; o >>= 1) m = fmaxf(m, __shfl_xor_sync(0xffffffffu, m, o));
    if (lane == 0) red[wid] = m;
    __syncthreads();
    float M = red[0];
    #pragma unroll
    for (int i = 1; i < 8; ++i) M = fmaxf(M, red[i]);

    v.x = __expf(v.x - M); v.y = __expf(v.y - M);
    v.z = __expf(v.z - M); v.w = __expf(v.w - M);
    float s = v.x + v.y + v.z + v.w;
    #pragma unroll
    for (int o = 16; o; o >>= 1) s += __shfl_xor_sync(0xffffffffu, s, o);
    __syncthreads();
    if (lane == 0) red[wid] = s;
    __syncthreads();
    float Z = 0.f;
    #pragma unroll
    for (int i = 0; i < 8; ++i) Z += red[i];
    float inv = 1.0f / Z;
    uint4 o4 = make_uint4(f2tf32(v.x * inv), f2tf32(v.y * inv),
                          f2tf32(v.z * inv), f2tf32(v.w * inv));
    reinterpret_cast<uint4*>(rp)[threadIdx.x] = o4;
}

// ---------------- P @ V -> concat (tf32 out) ----------------------------------------
__global__ __launch_bounds__(THREADS) void gemm_pv_kernel()
{
    constexpr int NTT = 2;
    extern __shared__ uint32_t sm[];
    uint32_t* sA = sm;
    uint32_t* sB = sm + gST * gASZ;
    float acc[gMT][NTT][4] = {};
    int bh = blockIdx.z; int b = bh >> 4, n = bh & 15;
    int m0 = blockIdx.y * gBM;
    const uint32_t* P = reinterpret_cast<const uint32_t*>(g_scores) + (size_t)bh * Ss * Ss;
    const uint32_t* V = g_v + (size_t)bh * Ss * Dd;
    gemm_tc<gBM, pBN, gBK, gMT, NTT, gWM, gWN, false, gST>(
        P, Ss, V, Dd, Ss, m0, 0, acc, sA, sB);

    const int lane = threadIdx.x & 31, wid = threadIdx.x >> 5;
    const int wm = wid / gWN, wn = wid % gWN;
    const int g = lane >> 2, t = lane & 3;
    #pragma unroll
    for (int i = 0; i < gMT; ++i) {
        int s = m0 + (wm * gMT + i) * 16 + g;
        #pragma unroll
        for (int j = 0; j < NTT; ++j) {
            int c0 = (wn * NTT + j) * 8 + 2 * t;
            uint32_t* o0 = g_concat + ((size_t)(b * Ss + s)) * Hh + n * Dd + c0;
            uint32_t* o1 = g_concat + ((size_t)(b * Ss + s + 8)) * Hh + n * Dd + c0;
            o0[0] = f2tf32(acc[i][j][0]); o0[1] = f2tf32(acc[i][j][1]);
            o1[0] = f2tf32(acc[i][j][2]); o1[1] = f2tf32(acc[i][j][3]);
        }
    }
}

// ---------------- Wo + bias + residual(x) -> g_tmp -----------------------------------
__global__ __launch_bounds__(THREADS) void gemm_wo_kernel(
    const float* __restrict__ bo, const float* __restrict__ x)
{
    extern __shared__ uint32_t sm[];
    uint32_t* sA = sm;
    uint32_t* sB = sm + gST * gASZ;
    float acc[gMT][gNT][4] = {};
    int m0 = blockIdx.y * gBM, n0 = blockIdx.x * gBN;
    gemm_tc<gBM, gBN, gBK, gMT, gNT, gWM, gWN, false, gST>(
        g_concat, Hh, g_wot, Hh, Hh, m0, n0, acc, sA, sB);

    const int lane = threadIdx.x & 31, wid = threadIdx.x >> 5;
    const int wm = wid / gWN, wn = wid % gWN;
    const int g = lane >> 2, t = lane & 3;
    #pragma unroll
    for (int i = 0; i < gMT; ++i) {
        int r0 = m0 + (wm * gMT + i) * 16 + g;
        #pragma unroll
        for (int j = 0; j < gNT; ++j) {
            int c0 = n0 + (wn * gNT + j) * 8 + 2 * t;
            size_t o0 = (size_t)r0 * Hh + c0, o1 = (size_t)(r0 + 8) * Hh + c0;
            g_tmp[o0]     = acc[i][j][0] + bo[c0]     + x[o0];
            g_tmp[o0 + 1] = acc[i][j][1] + bo[c0 + 1] + x[o0 + 1];
            g_tmp[o1]     = acc[i][j][2] + bo[c0]     + x[o1];
            g_tmp[o1 + 1] = acc[i][j][3] + bo[c0 + 1] + x[o1 + 1];
        }
    }
}

// ---------------- FFN 1: relu(h1 @ W1 + b1) -> tf32 -----------------------------------
__global__ __launch_bounds__(THREADS) void gemm_ff1_kernel(const float* __restrict__ b1)
{
    extern __shared__ uint32_t sm[];
    uint32_t* sA = sm;
    uint32_t* sB = sm + gST * gASZ;
    float acc[gMT][gNT][4] = {};
    int m0 = blockIdx.y * gBM, n0 = blockIdx.x * gBN;
    gemm_tc<gBM, gBN, gBK, gMT, gNT, gWM, gWN, false, gST>(
        g_h1t, Hh, g_w1t, FFd, Hh, m0, n0, acc, sA, sB);

    const int lane = threadIdx.x & 31, wid = threadIdx.x >> 5;
    const int wm = wid / gWN, wn = wid % gWN;
    const int g = lane >> 2, t = lane & 3;
    #pragma unroll
    for (int i = 0; i < gMT; ++i) {
        int r0 = m0 + (wm * gMT + i) * 16 + g;
        #pragma unroll
        for (int j = 0; j < gNT; ++j) {
            int c0 = n0 + (wn * gNT + j) * 8 + 2 * t;
            size_t o0 = (size_t)r0 * FFd + c0, o1 = (size_t)(r0 + 8) * FFd + c0;
            g_ff[o0]     = f2tf32(fmaxf(acc[i][j][0] + b1[c0],     0.f));
            g_ff[o0 + 1] = f2tf32(fmaxf(acc[i][j][1] + b1[c0 + 1], 0.f));
            g_ff[o1]     = f2tf32(fmaxf(acc[i][j][2] + b1[c0],     0.f));
            g_ff[o1 + 1] = f2tf32(fmaxf(acc[i][j][3] + b1[c0 + 1], 0.f));
        }
    }
}

// ---------------- FFN 2: g_ff @ W2 + b2 + h1 -> g_tmp ----------------------------------
__global__ __launch_bounds__(THREADS) void gemm_ff2_kernel(const float* __restrict__ b2)
{
    extern __shared__ uint32_t sm[];
    uint32_t* sA = sm;
    uint32_t* sB = sm + gST * gASZ;
    float acc[gMT][gNT][4] = {};
    int m0 = blockIdx.y * gBM, n0 = blockIdx.x * gBN;
    gemm_tc<gBM, gBN, gBK, gMT, gNT, gWM, gWN, false, gST>(
        g_ff, FFd, g_w2t, Hh, FFd, m0, n0, acc, sA, sB);

    const int lane = threadIdx.x & 31, wid = threadIdx.x >> 5;
    const int wm = wid / gWN, wn = wid % gWN;
    const int g = lane >> 2, t = lane & 3;
    #pragma unroll
    for (int i = 0; i < gMT; ++i) {
        int r0 = m0 + (wm * gMT + i) * 16 + g;
        #pragma unroll
        for (int j = 0; j < gNT; ++j) {
            int c0 = n0 + (wn * gNT + j) * 8 + 2 * t;
            size_t o0 = (size_t)r0 * Hh + c0, o1 = (size_t)(r0 + 8) * Hh + c0;
            g_tmp[o0]     = acc[i][j][0] + b2[c0]     + g_h1[o0];
            g_tmp[o0 + 1] = acc[i][j][1] + b2[c0 + 1] + g_h1[o0 + 1];
            g_tmp[o1]     = acc[i][j][2] + b2[c0]     + g_h1[o1];
            g_tmp[o1 + 1] = acc[i][j][3] + b2[c0 + 1] + g_h1[o1 + 1];
        }
    }
}

// ---------------- LayerNorm over H=1024 --------------------------------------------
// ln1 writes f32 h1 (for ff2 residual) AND tf32 copy (ff1 GEMM input).
__global__ __launch_bounds__(THREADS) void layernorm1_kernel(
    const float* __restrict__ gw, const float* __restrict__ bw)
{
    int row = blockIdx.x;
    const float4* rp = reinterpret_cast<const float4*>(g_tmp + (size_t)row * Hh);
    float4 v = rp[threadIdx.x];
    float s  = v.x + v.y + v.z + v.w;
    float s2 = v.x * v.x + v.y * v.y + v.z * v.z + v.w * v.w;
    #pragma unroll
    for (int o = 16; o; o >>= 1) {
        s  += __shfl_xor_sync(0xffffffffu, s,  o);
        s2 += __shfl_xor_sync(0xffffffffu, s2, o);
    }
    __shared__ float rs[8], rs2[8];
    int lane = threadIdx.x & 31, wid = threadIdx.x >> 5;
    if (lane == 0) { rs[wid] = s; rs2[wid] = s2; }
    __syncthreads();
    s = 0.f; s2 = 0.f;
    #pragma unroll
    for (int i = 0; i < 8; ++i) { s += rs[i]; s2 += rs2[i]; }
    float mu  = s  * (1.0f / Hh);
    float var = s2 * (1.0f / Hh) - mu * mu;
    float inv = rsqrtf(var + EPSLN);
    float4 g4 = reinterpret_cast<const float4*>(gw)[threadIdx.x];
    float4 b4 = reinterpret_cast<const float4*>(bw)[threadIdx.x];
    float4 o4;
    o4.x = (v.x - mu) * inv * g4.x + b4.x;
    o4.y = (v.y - mu) * inv * g4.y + b4.y;
    o4.z = (v.z - mu) * inv * g4.z + b4.z;
    o4.w = (v.w - mu) * inv * g4.w + b4.w;
    reinterpret_cast<float4*>(g_h1 + (size_t)row * Hh)[threadIdx.x] = o4;
    reinterpret_cast<uint4*>(g_h1t + (size_t)row * Hh)[threadIdx.x] =
        make_uint4(f2tf32(o4.x), f2tf32(o4.y), f2tf32(o4.z), f2tf32(o4.w));
}

__global__ __launch_bounds__(THREADS) void layernorm2_kernel(
    const float* __restrict__ gw, const float* __restrict__ bw,
    float* __restrict__ out)
{
    int row = blockIdx.x;
    const float4* rp = reinterpret_cast<const float4*>(g_tmp + (size_t)row * Hh);
    float4 v = rp[threadIdx.x];
    float s  = v.x + v.y + v.z + v.w;
    float s2 = v.x * v.x + v.y * v.y + v.z * v.z + v.w * v.w;
    #pragma unroll
    for (int o = 16; o; o >>= 1) {
        s  += __shfl_xor_sync(0xffffffffu, s,  o);
        s2 += __shfl_xor_sync(0xffffffffu, s2, o);
    }
    __shared__ float rs[8], rs2[8];
    int lane = threadIdx.x & 31, wid = threadIdx.x >> 5;
    if (lane == 0) { rs[wid] = s; rs2[wid] = s2; }
    __syncthreads();
    s = 0.f; s2 = 0.f;
    #pragma unroll
    for (int i = 0; i < 8; ++i) { s += rs[i]; s2 += rs2[i]; }
    float mu  = s  * (1.0f / Hh);
    float var = s2 * (1.0f / Hh) - mu * mu;
    float inv = rsqrtf(var + EPSLN);
    float4 g4 = reinterpret_cast<const float4*>(gw)[threadIdx.x];
    float4 b4 = reinterpret_cast<const float4*>(bw)[threadIdx.x];
    float4 o4;
    o4.x = (v.x - mu) * inv * g4.x + b4.x;
    o4.y = (v.y - mu) * inv * g4.y + b4.y;
    o4.z = (v.z - mu) * inv * g4.z + b4.z;
    o4.w = (v.w - mu) * inv * g4.w + b4.w;
    reinterpret_cast<float4*>(out + (size_t)row * Hh)[threadIdx.x] = o4;
}

// ---------------- entry ---------------------------------------------------------------
extern "C" void kernel_launch(void* const* d_in, const int* in_sizes, int n_in,
                              void* d_out, int out_size)
{
    const float* x   = (const float*)d_in[0];
    const float* Wqr = (const float*)d_in[1];
    const float* Wqi = (const float*)d_in[2];
    const float* bqr = (const float*)d_in[3];
    const float* bqi = (const float*)d_in[4];
    const float* Wkr = (const float*)d_in[5];
    const float* Wki = (const float*)d_in[6];
    const float* bkr = (const float*)d_in[7];
    const float* bki = (const float*)d_in[8];
    const float* Wv  = (const float*)d_in[9];
    const float* bvv = (const float*)d_in[10];
    const float* pqr = (const float*)d_in[11];
    const float* pqi = (const float*)d_in[12];
    const float* pkr = (const float*)d_in[13];
    const float* pki = (const float*)d_in[14];
    const float* Wo  = (const float*)d_in[15];
    const float* bo  = (const float*)d_in[16];
    const float* W1  = (const float*)d_in[17];
    const float* b1  = (const float*)d_in[18];
    const float* W2  = (const float*)d_in[19];
    const float* b2  = (const float*)d_in[20];
    const float* g1  = (const float*)d_in[21];
    const float* be1 = (const float*)d_in[22];
    const float* g2  = (const float*)d_in[23];
    const float* be2 = (const float*)d_in[24];
    float* out = (float*)d_out;

    static bool attr_done = false;
    if (!attr_done) {
        cudaFuncSetAttribute(gemm_proj_kernel,
            cudaFuncAttributeMaxDynamicSharedMemorySize, (int)SM_STD);
        cudaFuncSetAttribute(gemm_scores_kernel,
            cudaFuncAttributeMaxDynamicSharedMemorySize, (int)SM_TR);
        cudaFuncSetAttribute(gemm_pv_kernel,
            cudaFuncAttributeMaxDynamicSharedMemorySize, (int)SM_PV);
        cudaFuncSetAttribute(gemm_wo_kernel,
            cudaFuncAttributeMaxDynamicSharedMemorySize, (int)SM_STD);
        cudaFuncSetAttribute(gemm_ff1_kernel,
            cudaFuncAttributeMaxDynamicSharedMemorySize, (int)SM_STD);
        cudaFuncSetAttribute(gemm_ff2_kernel,
            cudaFuncAttributeMaxDynamicSharedMemorySize, (int)SM_STD);
        attr_done = true;
    }

    // pre-conversions (weights + x) to tf32 bit patterns
    uint32_t* xt  = nullptr; cudaGetSymbolAddress((void**)&xt,  g_xt);
    uint32_t* wot = nullptr; cudaGetSymbolAddress((void**)&wot, g_wot);
    uint32_t* w1t = nullptr; cudaGetSymbolAddress((void**)&w1t, g_w1t);
    uint32_t* w2t = nullptr; cudaGetSymbolAddress((void**)&w2t, g_w2t);

    convert_kernel<<<(Bb * Ss * Hh / 4 + THREADS - 1) / THREADS, THREADS>>>(
        (const float4*)x, (uint4*)xt, Bb * Ss * Hh / 4);
    convert_kernel<<<(Hh * Hh / 4 + THREADS - 1) / THREADS, THREADS>>>(
        (const float4*)Wo, (uint4*)wot, Hh * Hh / 4);
    convert_kernel<<<(Hh * FFd / 4 + THREADS - 1) / THREADS, THREADS>>>(
        (const float4*)W1, (uint4*)w1t, Hh * FFd / 4);
    convert_kernel<<<(FFd * Hh / 4 + THREADS - 1) / THREADS, THREADS>>>(
        (const float4*)W2, (uint4*)w2t, FFd * Hh / 4);
    repack_kernel<<<(5 * Nn * Hh * Dd + THREADS - 1) / THREADS, THREADS>>>(
        Wqr, Wqi, Wkr, Wki, Wv);

    gemm_proj_kernel<<<dim3(5120 / gBN, (Bb * Ss) / gBM), THREADS, SM_STD>>>(
        bqr, bqi, bkr, bki, bvv, pqr, pqi, pkr, pki);
    gemm_scores_kernel<<<dim3(Ss / gBN, Ss / gBM, Bb * Nn), THREADS, SM_TR>>>();
    softmax_kernel<<<Bb * Nn * Ss, THREADS>>>();
    gemm_pv_kernel<<<dim3(1, Ss / gBM, Bb * Nn), THREADS, SM_PV>>>();
    gemm_wo_kernel<<<dim3(Hh / gBN, (Bb * Ss) / gBM), THREADS, SM_STD>>>(bo, x);
    layernorm1_kernel<<<Bb * Ss, THREADS>>>(g1, be1);
    gemm_ff1_kernel<<<dim3(FFd / gBN, (Bb * Ss) / gBM), THREADS, SM_STD>>>(b1);
    gemm_ff2_kernel<<<dim3(Hh / gBN, (Bb * Ss) / gBM), THREADS, SM_STD>>>(b2);
    layernorm2_kernel<<<Bb * Ss, THREADS>>>(g2, be2, out);
}

// round 4
// speedup vs baseline: 3.2429x; 1.0916x over previous
#include <cuda_runtime.h>
#include <math.h>
#include <stdint.h>

#define THREADS 256
constexpr int Bb  = 4;
constexpr int Ss  = 1024;
constexpr int Hh  = 1024;
constexpr int Nn  = 16;
constexpr int Dd  = 64;
constexpr int FFd = 4096;
constexpr float SCALE = 0.125f;
constexpr float EPSLN = 1e-5f;

// ---------------- scratch -----------------------------------------------------
__device__ uint32_t g_wpack[1024 * 5120];
__device__ uint32_t g_xt  [Bb * Ss * Hh];
__device__ uint32_t g_wot [Hh * Hh];
__device__ uint32_t g_w1t [Hh * FFd];
__device__ uint32_t g_w2t [FFd * Hh];
__device__ uint32_t g_qr[Bb * Nn * Ss * Dd];   // tf32((qr*s+pos)*s)
__device__ uint32_t g_qi[Bb * Nn * Ss * Dd];   // tf32(-(qi*s+pos)*s)
__device__ uint32_t g_kr[Bb * Nn * Ss * Dd];
__device__ uint32_t g_ki[Bb * Nn * Ss * Dd];
__device__ uint32_t g_v [Bb * Nn * Ss * Dd];
__device__ uint32_t g_concat[Bb * Ss * Hh];
__device__ float    g_h1 [Bb * Ss * Hh];
__device__ uint32_t g_h1t[Bb * Ss * Hh];
__device__ float    g_tmp[Bb * Ss * Hh];
__device__ uint32_t g_ff[(size_t)Bb * Ss * FFd];

// ---------------- helpers ------------------------------------------------------
__device__ __forceinline__ uint32_t f2tf32(float x) {
    uint32_t r;
    asm("cvt.rna.tf32.f32 %0, %1;" : "=r"(r) : "f"(x));
    return r;
}
__device__ __forceinline__ void mma_tf32(float (&c)[4], const uint32_t (&a)[4],
                                         const uint32_t (&b)[2]) {
    asm volatile(
        "mma.sync.aligned.m16n8k8.row.col.f32.tf32.tf32.f32 "
        "{%0,%1,%2,%3}, {%4,%5,%6,%7}, {%8,%9}, {%0,%1,%2,%3};"
        : "+f"(c[0]), "+f"(c[1]), "+f"(c[2]), "+f"(c[3])
        : "r"(a[0]), "r"(a[1]), "r"(a[2]), "r"(a[3]), "r"(b[0]), "r"(b[1]));
}
__device__ __forceinline__ uint32_t smem_u32(const void* p) {
    return (uint32_t)__cvta_generic_to_shared(p);
}
__device__ __forceinline__ void cp16(uint32_t dst, const void* src) {
    asm volatile("cp.async.cg.shared.global [%0], [%1], 16;" :: "r"(dst), "l"(src));
}
__device__ __forceinline__ void cp_commit() {
    asm volatile("cp.async.commit_group;");
}
template<int N> __device__ __forceinline__ void cp_wait() {
    asm volatile("cp.async.wait_group %0;" :: "n"(N));
}

// ---------------- tf32 tensor-core GEMM core (cp.async pipeline) ----------------
template<int BM, int BN, int BK, int MT, int NTT, int WM, int WN, bool TRANSB,
         int STAGES>
__device__ __forceinline__ void gemm_tc(
    const uint32_t* __restrict__ A, int lda,
    const uint32_t* __restrict__ B, int ldb,
    int K, int m0, int n0,
    float (&acc)[MT][NTT][4], uint32_t* sA, uint32_t* sB)
{
    constexpr int SAK = BK + 4;
    constexpr int SBN = BN + 8;
    constexpr int SBK = BK + 4;
    constexpr int ASZ = BM * SAK;
    constexpr int BSZ = TRANSB ? BN * SBK : BK * SBN;
    constexpr int A_LD = BM * BK / 4 / THREADS;
    constexpr int B_LD = BN * BK / 4 / THREADS;

    const int tid  = threadIdx.x;
    const int lane = tid & 31, wid = tid >> 5;
    const int wm = wid / WN, wn = wid % WN;
    const int g = lane >> 2, t = lane & 3;

    auto load_tile = [&](int stg, int k0) {
        uint32_t aB = smem_u32(sA + stg * ASZ);
        uint32_t bB = smem_u32(sB + stg * BSZ);
        #pragma unroll
        for (int u = 0; u < A_LD; ++u) {
            int idx = tid + u * THREADS;
            int m = idx >> 2, kq = idx & 3;
            cp16(aB + (m * SAK + kq * 4) * 4,
                 A + (size_t)(m0 + m) * lda + k0 + kq * 4);
        }
        #pragma unroll
        for (int u = 0; u < B_LD; ++u) {
            int idx = tid + u * THREADS;
            if (!TRANSB) {
                int k = idx / (BN / 4), nq = idx % (BN / 4);
                cp16(bB + (k * SBN + nq * 4) * 4,
                     B + (size_t)(k0 + k) * ldb + n0 + nq * 4);
            } else {
                int n = idx >> 2, kq = idx & 3;
                cp16(bB + (n * SBK + kq * 4) * 4,
                     B + (size_t)(n0 + n) * ldb + k0 + kq * 4);
            }
        }
    };

    auto compute = [&](int stg) {
        uint32_t* As = sA + stg * ASZ;
        uint32_t* Bs = sB + stg * BSZ;
        #pragma unroll
        for (int kk = 0; kk < BK; kk += 8) {
            uint32_t af[MT][4], bf[NTT][2];
            #pragma unroll
            for (int i = 0; i < MT; ++i) {
                int mr = (wm * MT + i) * 16 + g;
                af[i][0] = As[mr * SAK + kk + t];
                af[i][1] = As[(mr + 8) * SAK + kk + t];
                af[i][2] = As[mr * SAK + kk + t + 4];
                af[i][3] = As[(mr + 8) * SAK + kk + t + 4];
            }
            #pragma unroll
            for (int j = 0; j < NTT; ++j) {
                int nc = (wn * NTT + j) * 8 + g;
                if (!TRANSB) {
                    bf[j][0] = Bs[(kk + t) * SBN + nc];
                    bf[j][1] = Bs[(kk + t + 4) * SBN + nc];
                } else {
                    bf[j][0] = Bs[nc * SBK + kk + t];
                    bf[j][1] = Bs[nc * SBK + kk + t + 4];
                }
            }
            #pragma unroll
            for (int i = 0; i < MT; ++i)
                #pragma unroll
                for (int j = 0; j < NTT; ++j)
                    mma_tf32(acc[i][j], af[i], bf[j]);
        }
    };

    const int k_tiles = K / BK;
    #pragma unroll
    for (int s = 0; s < STAGES - 1; ++s) {
        if (s < k_tiles) load_tile(s, s * BK);
        cp_commit();
    }
    for (int tI = 0; tI < k_tiles; ++tI) {
        int nt = tI + STAGES - 1;
        if (nt < k_tiles) load_tile(nt % STAGES, nt * BK);
        cp_commit();
        cp_wait<STAGES - 2>();
        __syncthreads();
        compute(tI % STAGES);
        __syncthreads();
    }
}

constexpr int gBM = 128, gBN = 128, gBK = 16, gMT = 4, gNT = 4;
constexpr int gWM = 2, gWN = 4, gST = 3;
constexpr int gASZ = gBM * (gBK + 4);
constexpr int gBSZ_N = gBK * (gBN + 8);
constexpr size_t SM_STD = (size_t)(gASZ + gBSZ_N) * gST * 4;

// ---------------- flash attention smem layout -----------------------------------
constexpr int fSQ = 68;    // [m][k] stride for q tiles
constexpr int fSK = 68;    // [n][k] stride for k tiles
constexpr int fSV = 72;    // [k][n] stride for v tile
constexpr int fSP = 132;   // [m][k] stride for p tile (overlays K region)
constexpr int oQr = 0;
constexpr int oQi = oQr + 128 * fSQ;
constexpr int oKr = oQi + 128 * fSQ;   // P overlays oKr.. (needs 128*132=16896 <= 17408)
constexpr int oKi = oKr + 128 * fSK;
constexpr int oV  = oKi + 128 * fSK;
constexpr size_t SM_FLASH = (size_t)(oV + 128 * fSV) * 4;   // 176128 B

// ---------------- pre-conversion kernels ----------------------------------------
__global__ __launch_bounds__(THREADS) void convert_kernel(
    const float4* __restrict__ src, uint4* __restrict__ dst, int n4)
{
    int i = blockIdx.x * THREADS + threadIdx.x;
    if (i >= n4) return;
    float4 v = src[i];
    dst[i] = make_uint4(f2tf32(v.x), f2tf32(v.y), f2tf32(v.z), f2tf32(v.w));
}

__global__ __launch_bounds__(THREADS) void repack_kernel(
    const float* __restrict__ Wqr, const float* __restrict__ Wqi,
    const float* __restrict__ Wkr, const float* __restrict__ Wki,
    const float* __restrict__ Wv)
{
    const int per = Nn * Hh * Dd;
    int idx = blockIdx.x * THREADS + threadIdx.x;
    if (idx >= 5 * per) return;
    int p = idx / per;
    int r = idx % per;
    const float* W = (p == 0) ? Wqr : (p == 1) ? Wqi : (p == 2) ? Wkr
                    : (p == 3) ? Wki : Wv;
    int n = r >> 16;
    int k = (r >> 6) & 1023;
    int d = r & 63;
    g_wpack[(size_t)k * 5120 + (p << 10) + (n << 6) + d] = f2tf32(W[r]);
}

// ---------------- fused QKV/V projection -----------------------------------------
__global__ __launch_bounds__(THREADS) void gemm_proj_kernel(
    const float* __restrict__ bqr, const float* __restrict__ bqi,
    const float* __restrict__ bkr, const float* __restrict__ bki,
    const float* __restrict__ bvv,
    const float* __restrict__ pqr, const float* __restrict__ pqi,
    const float* __restrict__ pkr, const float* __restrict__ pki)
{
    extern __shared__ uint32_t sm[];
    uint32_t* sA = sm;
    uint32_t* sB = sm + gST * gASZ;
    float acc[gMT][gNT][4] = {};
    int m0 = blockIdx.y * gBM, n0 = blockIdx.x * gBN;
    gemm_tc<gBM, gBN, gBK, gMT, gNT, gWM, gWN, false, gST>(
        g_xt, Hh, g_wpack, 5120, Hh, m0, n0, acc, sA, sB);

    const int lane = threadIdx.x & 31, wid = threadIdx.x >> 5;
    const int wm = wid / gWN, wn = wid % gWN;
    const int g = lane >> 2, t = lane & 3;

    auto emit = [&](int row, int col, float v0, float v1) {
        int p = col >> 10, n = (col >> 6) & 15, d = col & 63;
        int b = row >> 10, s = row & 1023;
        size_t pidx = (((size_t)n << 10) + s) * Dd + d;
        const float* bias = (p == 0) ? bqr : (p == 1) ? bqi : (p == 2) ? bkr
                           : (p == 3) ? bki : bvv;
        uint32_t* out = (p == 0) ? g_qr : (p == 1) ? g_qi : (p == 2) ? g_kr
                       : (p == 3) ? g_ki : g_v;
        float x0 = v0 + bias[n * Dd + d];
        float x1 = v1 + bias[n * Dd + d + 1];
        if (p == 0) {
            x0 = (x0 * SCALE + pqr[pidx]) * SCALE;
            x1 = (x1 * SCALE + pqr[pidx + 1]) * SCALE;
        } else if (p == 1) {
            x0 = -((x0 * SCALE + pqi[pidx]) * SCALE);
            x1 = -((x1 * SCALE + pqi[pidx + 1]) * SCALE);
        } else if (p == 2) {
            x0 += pkr[pidx]; x1 += pkr[pidx + 1];
        } else if (p == 3) {
            x0 += pki[pidx]; x1 += pki[pidx + 1];
        }
        size_t o = ((((size_t)b * Nn + n) << 10) + s) * Dd + d;
        out[o] = f2tf32(x0); out[o + 1] = f2tf32(x1);
    };

    #pragma unroll
    for (int i = 0; i < gMT; ++i) {
        int r0 = m0 + (wm * gMT + i) * 16 + g;
        #pragma unroll
        for (int j = 0; j < gNT; ++j) {
            int c0 = n0 + (wn * gNT + j) * 8 + 2 * t;
            emit(r0,     c0, acc[i][j][0], acc[i][j][1]);
            emit(r0 + 8, c0, acc[i][j][2], acc[i][j][3]);
        }
    }
}

// ---------------- flash attention: scores + softmax + PV -> concat ----------------
// Grid: (Ss/128, Bb*Nn). 8 warps; warp w owns rows [w*16, w*16+16) x all 128 cols.
__global__ __launch_bounds__(THREADS, 1) void flash_attn_kernel()
{
    extern __shared__ uint32_t sm[];
    const int tid = threadIdx.x, lane = tid & 31, wid = tid >> 5;
    const int g = lane >> 2, t = lane & 3;
    const int bh = blockIdx.y;
    const int b = bh >> 4, head = bh & 15;
    const int m0 = blockIdx.x * 128;

    const uint32_t* Qr = g_qr + (size_t)bh * Ss * Dd;
    const uint32_t* Qi = g_qi + (size_t)bh * Ss * Dd;
    const uint32_t* Kr = g_kr + (size_t)bh * Ss * Dd;
    const uint32_t* Ki = g_ki + (size_t)bh * Ss * Dd;
    const uint32_t* Vv = g_v  + (size_t)bh * Ss * Dd;

    const uint32_t sQr = smem_u32(sm + oQr);
    const uint32_t sQi = smem_u32(sm + oQi);
    const uint32_t sKr = smem_u32(sm + oKr);
    const uint32_t sKi = smem_u32(sm + oKi);
    const uint32_t sVb = smem_u32(sm + oV);

    // Q tiles (128x64 each)
    #pragma unroll
    for (int u = 0; u < 8; ++u) {
        int idx = tid + u * THREADS;
        int m = idx >> 4, q = idx & 15;
        cp16(sQr + (m * fSQ + q * 4) * 4, Qr + (size_t)(m0 + m) * Dd + q * 4);
        cp16(sQi + (m * fSQ + q * 4) * 4, Qi + (size_t)(m0 + m) * Dd + q * 4);
    }

    auto load_kv = [&](int kt) {
        const uint32_t* kr = Kr + (size_t)kt * 128 * Dd;
        const uint32_t* ki = Ki + (size_t)kt * 128 * Dd;
        const uint32_t* vv = Vv + (size_t)kt * 128 * Dd;
        #pragma unroll
        for (int u = 0; u < 8; ++u) {
            int idx = tid + u * THREADS;
            int r = idx >> 4, q = idx & 15;
            cp16(sKr + (r * fSK + q * 4) * 4, kr + (size_t)r * Dd + q * 4);
            cp16(sKi + (r * fSK + q * 4) * 4, ki + (size_t)r * Dd + q * 4);
            cp16(sVb + (r * fSV + q * 4) * 4, vv + (size_t)r * Dd + q * 4);
        }
    };

    load_kv(0);
    cp_commit();

    float m_run0 = -1e30f, m_run1 = -1e30f;
    float l_run0 = 0.f, l_run1 = 0.f;
    float acc_o[8][4] = {};
    const int mr = wid * 16 + g;

    for (int kt = 0; kt < Ss / 128; ++kt) {
        cp_wait<0>();
        __syncthreads();

        // ---- scores tile [16 rows x 128 cols] per warp ----
        float acc_s[16][4];
        #pragma unroll
        for (int j = 0; j < 16; ++j) {
            acc_s[j][0] = 0.f; acc_s[j][1] = 0.f;
            acc_s[j][2] = 0.f; acc_s[j][3] = 0.f;
        }
        #pragma unroll
        for (int kk = 0; kk < Dd; kk += 8) {
            uint32_t ar[4], ai[4];
            ar[0] = sm[oQr + mr * fSQ + kk + t];
            ar[1] = sm[oQr + (mr + 8) * fSQ + kk + t];
            ar[2] = sm[oQr + mr * fSQ + kk + t + 4];
            ar[3] = sm[oQr + (mr + 8) * fSQ + kk + t + 4];
            ai[0] = sm[oQi + mr * fSQ + kk + t];
            ai[1] = sm[oQi + (mr + 8) * fSQ + kk + t];
            ai[2] = sm[oQi + mr * fSQ + kk + t + 4];
            ai[3] = sm[oQi + (mr + 8) * fSQ + kk + t + 4];
            #pragma unroll
            for (int j = 0; j < 16; ++j) {
                int nc = j * 8 + g;
                uint32_t br[2] = { sm[oKr + nc * fSK + kk + t],
                                   sm[oKr + nc * fSK + kk + t + 4] };
                mma_tf32(acc_s[j], ar, br);
                uint32_t bi[2] = { sm[oKi + nc * fSK + kk + t],
                                   sm[oKi + nc * fSK + kk + t + 4] };
                mma_tf32(acc_s[j], ai, bi);
            }
        }

        // ---- online softmax (rows g, g+8 of warp strip) ----
        float tm0 = -1e30f, tm1 = -1e30f;
        #pragma unroll
        for (int j = 0; j < 16; ++j) {
            tm0 = fmaxf(tm0, fmaxf(acc_s[j][0], acc_s[j][1]));
            tm1 = fmaxf(tm1, fmaxf(acc_s[j][2], acc_s[j][3]));
        }
        #pragma unroll
        for (int o = 1; o <= 2; o <<= 1) {
            tm0 = fmaxf(tm0, __shfl_xor_sync(0xffffffffu, tm0, o));
            tm1 = fmaxf(tm1, __shfl_xor_sync(0xffffffffu, tm1, o));
        }
        float mn0 = fmaxf(m_run0, tm0), mn1 = fmaxf(m_run1, tm1);
        float sc0 = __expf(m_run0 - mn0), sc1 = __expf(m_run1 - mn1);
        m_run0 = mn0; m_run1 = mn1;

        float rs0 = 0.f, rs1 = 0.f;
        #pragma unroll
        for (int j = 0; j < 16; ++j) {
            acc_s[j][0] = __expf(acc_s[j][0] - mn0);
            acc_s[j][1] = __expf(acc_s[j][1] - mn0);
            acc_s[j][2] = __expf(acc_s[j][2] - mn1);
            acc_s[j][3] = __expf(acc_s[j][3] - mn1);
            rs0 += acc_s[j][0] + acc_s[j][1];
            rs1 += acc_s[j][2] + acc_s[j][3];
        }
        #pragma unroll
        for (int o = 1; o <= 2; o <<= 1) {
            rs0 += __shfl_xor_sync(0xffffffffu, rs0, o);
            rs1 += __shfl_xor_sync(0xffffffffu, rs1, o);
        }
        l_run0 = l_run0 * sc0 + rs0;
        l_run1 = l_run1 * sc1 + rs1;
        #pragma unroll
        for (int j = 0; j < 8; ++j) {
            acc_o[j][0] *= sc0; acc_o[j][1] *= sc0;
            acc_o[j][2] *= sc1; acc_o[j][3] *= sc1;
        }

        // all warps done reading sK region before P overlays it
        __syncthreads();
        #pragma unroll
        for (int j = 0; j < 16; ++j) {
            int c = j * 8 + 2 * t;
            sm[oKr + mr * fSP + c]           = f2tf32(acc_s[j][0]);
            sm[oKr + mr * fSP + c + 1]       = f2tf32(acc_s[j][1]);
            sm[oKr + (mr + 8) * fSP + c]     = f2tf32(acc_s[j][2]);
            sm[oKr + (mr + 8) * fSP + c + 1] = f2tf32(acc_s[j][3]);
        }
        __syncwarp();

        // ---- PV: [16x128] x [128x64] ----
        #pragma unroll
        for (int kk = 0; kk < 128; kk += 8) {
            uint32_t a[4];
            a[0] = sm[oKr + mr * fSP + kk + t];
            a[1] = sm[oKr + (mr + 8) * fSP + kk + t];
            a[2] = sm[oKr + mr * fSP + kk + t + 4];
            a[3] = sm[oKr + (mr + 8) * fSP + kk + t + 4];
            #pragma unroll
            for (int j = 0; j < 8; ++j) {
                int nc = j * 8 + g;
                uint32_t bv[2] = { sm[oV + (kk + t) * fSV + nc],
                                   sm[oV + (kk + t + 4) * fSV + nc] };
                mma_tf32(acc_o[j], a, bv);
            }
        }

        __syncthreads();   // done with sP/sV before next tile load
        if (kt + 1 < Ss / 128) load_kv(kt + 1);
        cp_commit();
    }

    // ---- epilogue: divide by l, scatter tf32 into concat ----
    float inv0 = 1.0f / l_run0, inv1 = 1.0f / l_run1;
    int s0 = m0 + mr;
    #pragma unroll
    for (int j = 0; j < 8; ++j) {
        int c = j * 8 + 2 * t;
        uint32_t* o0 = g_concat + ((size_t)(b * Ss + s0)) * Hh + head * Dd + c;
        uint32_t* o1 = g_concat + ((size_t)(b * Ss + s0 + 8)) * Hh + head * Dd + c;
        o0[0] = f2tf32(acc_o[j][0] * inv0);
        o0[1] = f2tf32(acc_o[j][1] * inv0);
        o1[0] = f2tf32(acc_o[j][2] * inv1);
        o1[1] = f2tf32(acc_o[j][3] * inv1);
    }
}

// ---------------- Wo + bias + residual(x) -> g_tmp -----------------------------------
__global__ __launch_bounds__(THREADS) void gemm_wo_kernel(
    const float* __restrict__ bo, const float* __restrict__ x)
{
    extern __shared__ uint32_t sm[];
    uint32_t* sA = sm;
    uint32_t* sB = sm + gST * gASZ;
    float acc[gMT][gNT][4] = {};
    int m0 = blockIdx.y * gBM, n0 = blockIdx.x * gBN;
    gemm_tc<gBM, gBN, gBK, gMT, gNT, gWM, gWN, false, gST>(
        g_concat, Hh, g_wot, Hh, Hh, m0, n0, acc, sA, sB);

    const int lane = threadIdx.x & 31, wid = threadIdx.x >> 5;
    const int wm = wid / gWN, wn = wid % gWN;
    const int g = lane >> 2, t = lane & 3;
    #pragma unroll
    for (int i = 0; i < gMT; ++i) {
        int r0 = m0 + (wm * gMT + i) * 16 + g;
        #pragma unroll
        for (int j = 0; j < gNT; ++j) {
            int c0 = n0 + (wn * gNT + j) * 8 + 2 * t;
            size_t o0 = (size_t)r0 * Hh + c0, o1 = (size_t)(r0 + 8) * Hh + c0;
            g_tmp[o0]     = acc[i][j][0] + bo[c0]     + x[o0];
            g_tmp[o0 + 1] = acc[i][j][1] + bo[c0 + 1] + x[o0 + 1];
            g_tmp[o1]     = acc[i][j][2] + bo[c0]     + x[o1];
            g_tmp[o1 + 1] = acc[i][j][3] + bo[c0 + 1] + x[o1 + 1];
        }
    }
}

// ---------------- FFN 1: relu(h1 @ W1 + b1) -> tf32 -----------------------------------
__global__ __launch_bounds__(THREADS) void gemm_ff1_kernel(const float* __restrict__ b1)
{
    extern __shared__ uint32_t sm[];
    uint32_t* sA = sm;
    uint32_t* sB = sm + gST * gASZ;
    float acc[gMT][gNT][4] = {};
    int m0 = blockIdx.y * gBM, n0 = blockIdx.x * gBN;
    gemm_tc<gBM, gBN, gBK, gMT, gNT, gWM, gWN, false, gST>(
        g_h1t, Hh, g_w1t, FFd, Hh, m0, n0, acc, sA, sB);

    const int lane = threadIdx.x & 31, wid = threadIdx.x >> 5;
    const int wm = wid / gWN, wn = wid % gWN;
    const int g = lane >> 2, t = lane & 3;
    #pragma unroll
    for (int i = 0; i < gMT; ++i) {
        int r0 = m0 + (wm * gMT + i) * 16 + g;
        #pragma unroll
        for (int j = 0; j < gNT; ++j) {
            int c0 = n0 + (wn * gNT + j) * 8 + 2 * t;
            size_t o0 = (size_t)r0 * FFd + c0, o1 = (size_t)(r0 + 8) * FFd + c0;
            g_ff[o0]     = f2tf32(fmaxf(acc[i][j][0] + b1[c0],     0.f));
            g_ff[o0 + 1] = f2tf32(fmaxf(acc[i][j][1] + b1[c0 + 1], 0.f));
            g_ff[o1]     = f2tf32(fmaxf(acc[i][j][2] + b1[c0],     0.f));
            g_ff[o1 + 1] = f2tf32(fmaxf(acc[i][j][3] + b1[c0 + 1], 0.f));
        }
    }
}

// ---------------- FFN 2: g_ff @ W2 + b2 + h1 -> g_tmp ----------------------------------
__global__ __launch_bounds__(THREADS) void gemm_ff2_kernel(const float* __restrict__ b2)
{
    extern __shared__ uint32_t sm[];
    uint32_t* sA = sm;
    uint32_t* sB = sm + gST * gASZ;
    float acc[gMT][gNT][4] = {};
    int m0 = blockIdx.y * gBM, n0 = blockIdx.x * gBN;
    gemm_tc<gBM, gBN, gBK, gMT, gNT, gWM, gWN, false, gST>(
        g_ff, FFd, g_w2t, Hh, FFd, m0, n0, acc, sA, sB);

    const int lane = threadIdx.x & 31, wid = threadIdx.x >> 5;
    const int wm = wid / gWN, wn = wid % gWN;
    const int g = lane >> 2, t = lane & 3;
    #pragma unroll
    for (int i = 0; i < gMT; ++i) {
        int r0 = m0 + (wm * gMT + i) * 16 + g;
        #pragma unroll
        for (int j = 0; j < gNT; ++j) {
            int c0 = n0 + (wn * gNT + j) * 8 + 2 * t;
            size_t o0 = (size_t)r0 * Hh + c0, o1 = (size_t)(r0 + 8) * Hh + c0;
            g_tmp[o0]     = acc[i][j][0] + b2[c0]     + g_h1[o0];
            g_tmp[o0 + 1] = acc[i][j][1] + b2[c0 + 1] + g_h1[o0 + 1];
            g_tmp[o1]     = acc[i][j][2] + b2[c0]     + g_h1[o1];
            g_tmp[o1 + 1] = acc[i][j][3] + b2[c0 + 1] + g_h1[o1 + 1];
        }
    }
}

// ---------------- LayerNorms -------------------------------------------------------
__global__ __launch_bounds__(THREADS) void layernorm1_kernel(
    const float* __restrict__ gw, const float* __restrict__ bw)
{
    int row = blockIdx.x;
    const float4* rp = reinterpret_cast<const float4*>(g_tmp + (size_t)row * Hh);
    float4 v = rp[threadIdx.x];
    float s  = v.x + v.y + v.z + v.w;
    float s2 = v.x * v.x + v.y * v.y + v.z * v.z + v.w * v.w;
    #pragma unroll
    for (int o = 16; o; o >>= 1) {
        s  += __shfl_xor_sync(0xffffffffu, s,  o);
        s2 += __shfl_xor_sync(0xffffffffu, s2, o);
    }
    __shared__ float rs[8], rs2[8];
    int lane = threadIdx.x & 31, wid = threadIdx.x >> 5;
    if (lane == 0) { rs[wid] = s; rs2[wid] = s2; }
    __syncthreads();
    s = 0.f; s2 = 0.f;
    #pragma unroll
    for (int i = 0; i < 8; ++i) { s += rs[i]; s2 += rs2[i]; }
    float mu  = s  * (1.0f / Hh);
    float var = s2 * (1.0f / Hh) - mu * mu;
    float inv = rsqrtf(var + EPSLN);
    float4 g4 = reinterpret_cast<const float4*>(gw)[threadIdx.x];
    float4 b4 = reinterpret_cast<const float4*>(bw)[threadIdx.x];
    float4 o4;
    o4.x = (v.x - mu) * inv * g4.x + b4.x;
    o4.y = (v.y - mu) * inv * g4.y + b4.y;
    o4.z = (v.z - mu) * inv * g4.z + b4.z;
    o4.w = (v.w - mu) * inv * g4.w + b4.w;
    reinterpret_cast<float4*>(g_h1 + (size_t)row * Hh)[threadIdx.x] = o4;
    reinterpret_cast<uint4*>(g_h1t + (size_t)row * Hh)[threadIdx.x] =
        make_uint4(f2tf32(o4.x), f2tf32(o4.y), f2tf32(o4.z), f2tf32(o4.w));
}

__global__ __launch_bounds__(THREADS) void layernorm2_kernel(
    const float* __restrict__ gw, const float* __restrict__ bw,
    float* __restrict__ out)
{
    int row = blockIdx.x;
    const float4* rp = reinterpret_cast<const float4*>(g_tmp + (size_t)row * Hh);
    float4 v = rp[threadIdx.x];
    float s  = v.x + v.y + v.z + v.w;
    float s2 = v.x * v.x + v.y * v.y + v.z * v.z + v.w * v.w;
    #pragma unroll
    for (int o = 16; o; o >>= 1) {
        s  += __shfl_xor_sync(0xffffffffu, s,  o);
        s2 += __shfl_xor_sync(0xffffffffu, s2, o);
    }
    __shared__ float rs[8], rs2[8];
    int lane = threadIdx.x & 31, wid = threadIdx.x >> 5;
    if (lane == 0) { rs[wid] = s; rs2[wid] = s2; }
    __syncthreads();
    s = 0.f; s2 = 0.f;
    #pragma unroll
    for (int i = 0; i < 8; ++i) { s += rs[i]; s2 += rs2[i]; }
    float mu  = s  * (1.0f / Hh);
    float var = s2 * (1.0f / Hh) - mu * mu;
    float inv = rsqrtf(var + EPSLN);
    float4 g4 = reinterpret_cast<const float4*>(gw)[threadIdx.x];
    float4 b4 = reinterpret_cast<const float4*>(bw)[threadIdx.x];
    float4 o4;
    o4.x = (v.x - mu) * inv * g4.x + b4.x;
    o4.y = (v.y - mu) * inv * g4.y + b4.y;
    o4.z = (v.z - mu) * inv * g4.z + b4.z;
    o4.w = (v.w - mu) * inv * g4.w + b4.w;
    reinterpret_cast<float4*>(out + (size_t)row * Hh)[threadIdx.x] = o4;
}

// ---------------- entry ---------------------------------------------------------------
extern "C" void kernel_launch(void* const* d_in, const int* in_sizes, int n_in,
                              void* d_out, int out_size)
{
    const float* x   = (const float*)d_in[0];
    const float* Wqr = (const float*)d_in[1];
    const float* Wqi = (const float*)d_in[2];
    const float* bqr = (const float*)d_in[3];
    const float* bqi = (const float*)d_in[4];
    const float* Wkr = (const float*)d_in[5];
    const float* Wki = (const float*)d_in[6];
    const float* bkr = (const float*)d_in[7];
    const float* bki = (const float*)d_in[8];
    const float* Wv  = (const float*)d_in[9];
    const float* bvv = (const float*)d_in[10];
    const float* pqr = (const float*)d_in[11];
    const float* pqi = (const float*)d_in[12];
    const float* pkr = (const float*)d_in[13];
    const float* pki = (const float*)d_in[14];
    const float* bo  = (const float*)d_in[16];
    const float* b1  = (const float*)d_in[18];
    const float* b2  = (const float*)d_in[20];
    const float* g1  = (const float*)d_in[21];
    const float* be1 = (const float*)d_in[22];
    const float* g2  = (const float*)d_in[23];
    const float* be2 = (const float*)d_in[24];
    const float* Wo  = (const float*)d_in[15];
    const float* W1  = (const float*)d_in[17];
    const float* W2  = (const float*)d_in[19];
    float* out = (float*)d_out;

    static bool attr_done = false;
    if (!attr_done) {
        cudaFuncSetAttribute(gemm_proj_kernel,
            cudaFuncAttributeMaxDynamicSharedMemorySize, (int)SM_STD);
        cudaFuncSetAttribute(flash_attn_kernel,
            cudaFuncAttributeMaxDynamicSharedMemorySize, (int)SM_FLASH);
        cudaFuncSetAttribute(gemm_wo_kernel,
            cudaFuncAttributeMaxDynamicSharedMemorySize, (int)SM_STD);
        cudaFuncSetAttribute(gemm_ff1_kernel,
            cudaFuncAttributeMaxDynamicSharedMemorySize, (int)SM_STD);
        cudaFuncSetAttribute(gemm_ff2_kernel,
            cudaFuncAttributeMaxDynamicSharedMemorySize, (int)SM_STD);
        attr_done = true;
    }

    uint32_t* xt  = nullptr; cudaGetSymbolAddress((void**)&xt,  g_xt);
    uint32_t* wot = nullptr; cudaGetSymbolAddress((void**)&wot, g_wot);
    uint32_t* w1t = nullptr; cudaGetSymbolAddress((void**)&w1t, g_w1t);
    uint32_t* w2t = nullptr; cudaGetSymbolAddress((void**)&w2t, g_w2t);

    convert_kernel<<<(Bb * Ss * Hh / 4 + THREADS - 1) / THREADS, THREADS>>>(
        (const float4*)x, (uint4*)xt, Bb * Ss * Hh / 4);
    convert_kernel<<<(Hh * Hh / 4 + THREADS - 1) / THREADS, THREADS>>>(
        (const float4*)Wo, (uint4*)wot, Hh * Hh / 4);
    convert_kernel<<<(Hh * FFd / 4 + THREADS - 1) / THREADS, THREADS>>>(
        (const float4*)W1, (uint4*)w1t, Hh * FFd / 4);
    convert_kernel<<<(FFd * Hh / 4 + THREADS - 1) / THREADS, THREADS>>>(
        (const float4*)W2, (uint4*)w2t, FFd * Hh / 4);
    repack_kernel<<<(5 * Nn * Hh * Dd + THREADS - 1) / THREADS, THREADS>>>(
        Wqr, Wqi, Wkr, Wki, Wv);

    gemm_proj_kernel<<<dim3(5120 / gBN, (Bb * Ss) / gBM), THREADS, SM_STD>>>(
        bqr, bqi, bkr, bki, bvv, pqr, pqi, pkr, pki);
    flash_attn_kernel<<<dim3(Ss / 128, Bb * Nn), THREADS, SM_FLASH>>>();
    gemm_wo_kernel<<<dim3(Hh / gBN, (Bb * Ss) / gBM), THREADS, SM_STD>>>(bo, x);
    layernorm1_kernel<<<Bb * Ss, THREADS>>>(g1, be1);
    gemm_ff1_kernel<<<dim3(FFd / gBN, (Bb * Ss) / gBM), THREADS, SM_STD>>>(b1);
    gemm_ff2_kernel<<<dim3(Hh / gBN, (Bb * Ss) / gBM), THREADS, SM_STD>>>(b2);
    layernorm2_kernel<<<Bb * Ss, THREADS>>>(g2, be2, out);
}

// round 6
// speedup vs baseline: 6.1104x; 1.8842x over previous
#include <cuda_runtime.h>
#include <cuda_fp16.h>
#include <math.h>
#include <stdint.h>

#define THREADS 256
constexpr int Bb  = 4;
constexpr int Ss  = 1024;
constexpr int Hh  = 1024;
constexpr int Nn  = 16;
constexpr int Dd  = 64;
constexpr int FFd = 4096;
constexpr float SCALE = 0.125f;
constexpr float EPSLN = 1e-5f;

// ---------------- scratch (fp16 operands, fp32 residual path) -------------------
__device__ __half g_wpack[5120 * 1024];     // [N=5120][K=1024] qkv weights
__device__ __half g_xt  [Bb * Ss * Hh];     // [M][K]
__device__ __half g_wot [Hh * Hh];          // Wo^T [N][K]
__device__ __half g_w1t [FFd * Hh];         // W1^T
__device__ __half g_w2t [Hh * FFd];         // W2^T
__device__ __half g_q[Bb * Nn * Ss * 128];  // [qr*s2+pos*s | -(qi*s2+pos*s)] concat
__device__ __half g_k[Bb * Nn * Ss * 128];  // [kr+pos | ki+pos]
__device__ __half g_v[Bb * Nn * Ss * Dd];
__device__ __half g_concat[Bb * Ss * Hh];
__device__ float  g_h1 [Bb * Ss * Hh];
__device__ __half g_h1h[Bb * Ss * Hh];
__device__ float  g_tmp[Bb * Ss * Hh];
__device__ __half g_ff[(size_t)Bb * Ss * FFd];

// ---------------- helpers ---------------------------------------------------------
__device__ __forceinline__ uint32_t smem_u32(const void* p) {
    return (uint32_t)__cvta_generic_to_shared(p);
}
__device__ __forceinline__ void cp16(uint32_t dst, const void* src) {
    asm volatile("cp.async.cg.shared.global [%0], [%1], 16;" :: "r"(dst), "l"(src));
}
__device__ __forceinline__ void cp_commit() {
    asm volatile("cp.async.commit_group;");
}
template<int N> __device__ __forceinline__ void cp_wait() {
    asm volatile("cp.async.wait_group %0;" :: "n"(N));
}
__device__ __forceinline__ void mma16816(float (&c)[4], const uint32_t (&a)[4],
                                         const uint32_t (&b)[2]) {
    asm volatile(
        "mma.sync.aligned.m16n8k16.row.col.f32.f16.f16.f32 "
        "{%0,%1,%2,%3}, {%4,%5,%6,%7}, {%8,%9}, {%0,%1,%2,%3};"
        : "+f"(c[0]), "+f"(c[1]), "+f"(c[2]), "+f"(c[3])
        : "r"(a[0]), "r"(a[1]), "r"(a[2]), "r"(a[3]), "r"(b[0]), "r"(b[1]));
}
__device__ __forceinline__ void ldsm4(uint32_t (&r)[4], uint32_t addr) {
    asm volatile("ldmatrix.sync.aligned.m8n8.x4.shared.b16 {%0,%1,%2,%3}, [%4];"
        : "=r"(r[0]), "=r"(r[1]), "=r"(r[2]), "=r"(r[3]) : "r"(addr));
}
__device__ __forceinline__ void ldsm4t(uint32_t (&r)[4], uint32_t addr) {
    asm volatile("ldmatrix.sync.aligned.m8n8.x4.trans.shared.b16 {%0,%1,%2,%3}, [%4];"
        : "=r"(r[0]), "=r"(r[1]), "=r"(r[2]), "=r"(r[3]) : "r"(addr));
}
__device__ __forceinline__ uint32_t h2u(__half2 h) {
    return *reinterpret_cast<uint32_t*>(&h);
}

// ---------------- fp16 tensor-core GEMM core ---------------------------------------
// D[128x128] = A[m0..,K] @ B[n0..,K]^T ; A,B fp16 K-major. BK=64, 2-stage cp.async,
// one barrier per K-tile, ldmatrix fragments (row stride 144B -> conflict-free).
constexpr int hBK  = 64;
constexpr int hLDS = hBK + 8;                 // 72 halves = 144B rows
constexpr int hTILE = 128 * hLDS;             // halves per tile
constexpr size_t SM_HGEMM = (size_t)2 * 2 * hTILE * sizeof(__half);   // 73728 B

template<int KTOT, typename Epi>
__device__ __forceinline__ void hgemm(
    const __half* __restrict__ A, int lda,
    const __half* __restrict__ B, int ldb,
    int m0, int n0, Epi epi)
{
    extern __shared__ __half hsm[];
    const int tid = threadIdx.x, lane = tid & 31, wid = tid >> 5;
    const int wm = wid >> 2, wn = wid & 3;
    const int lrow = lane & 15, lhi = (lane >> 4) & 1;

    auto load_tile = [&](int buf, int kc) {
        __half* a = hsm + buf * (2 * hTILE);
        __half* b = a + hTILE;
        uint32_t ab = smem_u32(a), bb = smem_u32(b);
        #pragma unroll
        for (int u = 0; u < 4; ++u) {
            int idx = tid + u * THREADS;
            int m = idx >> 3, kq = idx & 7;
            cp16(ab + (m * hLDS + kq * 8) * 2,
                 A + (size_t)(m0 + m) * lda + kc * hBK + kq * 8);
        }
        #pragma unroll
        for (int u = 0; u < 4; ++u) {
            int idx = tid + u * THREADS;
            int n = idx >> 3, kq = idx & 7;
            cp16(bb + (n * hLDS + kq * 8) * 2,
                 B + (size_t)(n0 + n) * ldb + kc * hBK + kq * 8);
        }
    };

    float acc[4][4][4] = {};

    auto compute = [&](int buf) {
        __half* a = hsm + buf * (2 * hTILE);
        __half* b = a + hTILE;
        uint32_t ab = smem_u32(a), bb = smem_u32(b);
        #pragma unroll
        for (int ks = 0; ks < hBK / 16; ++ks) {
            int kk = ks * 16;
            uint32_t af[4][4];
            #pragma unroll
            for (int i = 0; i < 4; ++i) {
                int row = wm * 64 + i * 16 + lrow;
                ldsm4(af[i], ab + (row * hLDS + kk + lhi * 8) * 2);
            }
            #pragma unroll
            for (int p = 0; p < 2; ++p) {
                uint32_t bf[4];
                int nr = wn * 32 + p * 16 + lrow;
                ldsm4(bf, bb + (nr * hLDS + kk + lhi * 8) * 2);
                uint32_t b0[2] = { bf[0], bf[2] };
                uint32_t b1[2] = { bf[1], bf[3] };
                #pragma unroll
                for (int i = 0; i < 4; ++i) {
                    mma16816(acc[i][2 * p],     af[i], b0);
                    mma16816(acc[i][2 * p + 1], af[i], b1);
                }
            }
        }
    };

    constexpr int T = KTOT / hBK;
    load_tile(0, 0);
    cp_commit();
    for (int i = 0; i < T; ++i) {
        cp_wait<0>();
        __syncthreads();           // data ready + prev compute done (buffer reuse safe)
        if (i + 1 < T) { load_tile((i + 1) & 1, i + 1); cp_commit(); }
        compute(i & 1);
    }

    const int g = lane >> 2, t = lane & 3;
    #pragma unroll
    for (int i = 0; i < 4; ++i) {
        int r0 = m0 + (wm * 4 + i) * 16 + g;
        #pragma unroll
        for (int j = 0; j < 4; ++j) {
            int c0 = n0 + (wn * 4 + j) * 8 + 2 * t;
            epi(r0,     c0, acc[i][j][0], acc[i][j][1]);
            epi(r0 + 8, c0, acc[i][j][2], acc[i][j][3]);
        }
    }
}

// ---------------- pre-conversion kernels ------------------------------------------
__global__ __launch_bounds__(THREADS) void convert_h_kernel(
    const float4* __restrict__ src, uint2* __restrict__ dst, int n4)
{
    int i = blockIdx.x * THREADS + threadIdx.x;
    if (i >= n4) return;
    float4 v = src[i];
    dst[i] = make_uint2(h2u(__floats2half2_rn(v.x, v.y)),
                        h2u(__floats2half2_rn(v.z, v.w)));
}

// transpose: src [R][C] f32 -> dst [C][R] half
__global__ void trans_w_kernel(const float* __restrict__ src,
                               __half* __restrict__ dst, int R, int C)
{
    __shared__ float t[32][33];
    int c0 = blockIdx.x * 32, r0 = blockIdx.y * 32;
    for (int i = threadIdx.y; i < 32; i += 8)
        t[i][threadIdx.x] = src[(size_t)(r0 + i) * C + c0 + threadIdx.x];
    __syncthreads();
    for (int i = threadIdx.y; i < 32; i += 8)
        dst[(size_t)(c0 + i) * R + r0 + threadIdx.x] =
            __float2half_rn(t[threadIdx.x][i]);
}

// qkv weights: 5x [N,H,D] -> g_wpack [5120 rows (p*1024+n*64+d)][K=1024] half
__global__ void repack_t_kernel(
    const float* __restrict__ Wqr, const float* __restrict__ Wqi,
    const float* __restrict__ Wkr, const float* __restrict__ Wki,
    const float* __restrict__ Wv)
{
    __shared__ float t[32][33];
    int z = blockIdx.z;
    int p = z >> 4, n = z & 15;
    const float* W = (p == 0) ? Wqr : (p == 1) ? Wqi : (p == 2) ? Wkr
                    : (p == 3) ? Wki : Wv;
    W += (size_t)n * (Hh * Dd);
    int k0 = blockIdx.x * 32, d0 = blockIdx.y * 32;
    for (int i = threadIdx.y; i < 32; i += 8)
        t[i][threadIdx.x] = W[(size_t)(k0 + i) * Dd + d0 + threadIdx.x];
    __syncthreads();
    int rbase = p * 1024 + n * 64 + d0;
    for (int i = threadIdx.y; i < 32; i += 8)
        g_wpack[(size_t)(rbase + i) * 1024 + k0 + threadIdx.x] =
            __float2half_rn(t[threadIdx.x][i]);
}

// ---------------- GEMM kernels -----------------------------------------------------
__global__ __launch_bounds__(THREADS, 2) void hproj_kernel(
    const float* __restrict__ bqr, const float* __restrict__ bqi,
    const float* __restrict__ bkr, const float* __restrict__ bki,
    const float* __restrict__ bvv,
    const float* __restrict__ pqr, const float* __restrict__ pqi,
    const float* __restrict__ pkr, const float* __restrict__ pki)
{
    int m0 = blockIdx.y * 128, n0 = blockIdx.x * 128;
    hgemm<1024>(g_xt, Hh, g_wpack, 1024, m0, n0,
        [&](int row, int col, float v0, float v1) {
            int p = col >> 10, n = (col >> 6) & 15, d = col & 63;
            int bb = row >> 10, s = row & 1023;
            size_t pidx = (((size_t)n << 10) + s) * Dd + d;
            size_t rowoff = (((size_t)(bb * Nn + n)) << 10) + s;
            float x0, x1;
            __half* dst;
            if (p == 0) {
                x0 = ((v0 + bqr[n * Dd + d])     * SCALE + pqr[pidx])     * SCALE;
                x1 = ((v1 + bqr[n * Dd + d + 1]) * SCALE + pqr[pidx + 1]) * SCALE;
                dst = g_q + rowoff * 128 + d;
            } else if (p == 1) {
                x0 = -(((v0 + bqi[n * Dd + d])     * SCALE + pqi[pidx])     * SCALE);
                x1 = -(((v1 + bqi[n * Dd + d + 1]) * SCALE + pqi[pidx + 1]) * SCALE);
                dst = g_q + rowoff * 128 + 64 + d;
            } else if (p == 2) {
                x0 = v0 + bkr[n * Dd + d]     + pkr[pidx];
                x1 = v1 + bkr[n * Dd + d + 1] + pkr[pidx + 1];
                dst = g_k + rowoff * 128 + d;
            } else if (p == 3) {
                x0 = v0 + bki[n * Dd + d]     + pki[pidx];
                x1 = v1 + bki[n * Dd + d + 1] + pki[pidx + 1];
                dst = g_k + rowoff * 128 + 64 + d;
            } else {
                x0 = v0 + bvv[n * Dd + d];
                x1 = v1 + bvv[n * Dd + d + 1];
                dst = g_v + rowoff * Dd + d;
            }
            *reinterpret_cast<__half2*>(dst) = __floats2half2_rn(x0, x1);
        });
}

__global__ __launch_bounds__(THREADS, 2) void hwo_kernel(
    const float* __restrict__ bo, const float* __restrict__ x)
{
    int m0 = blockIdx.y * 128, n0 = blockIdx.x * 128;
    hgemm<1024>(g_concat, Hh, g_wot, 1024, m0, n0,
        [&](int row, int c0, float v0, float v1) {
            size_t o = (size_t)row * Hh + c0;
            g_tmp[o]     = v0 + bo[c0]     + x[o];
            g_tmp[o + 1] = v1 + bo[c0 + 1] + x[o + 1];
        });
}

__global__ __launch_bounds__(THREADS, 2) void hff1_kernel(const float* __restrict__ b1)
{
    int m0 = blockIdx.y * 128, n0 = blockIdx.x * 128;
    hgemm<1024>(g_h1h, Hh, g_w1t, 1024, m0, n0,
        [&](int row, int c0, float v0, float v1) {
            size_t o = (size_t)row * FFd + c0;
            *reinterpret_cast<__half2*>(g_ff + o) = __floats2half2_rn(
                fmaxf(v0 + b1[c0], 0.f), fmaxf(v1 + b1[c0 + 1], 0.f));
        });
}

__global__ __launch_bounds__(THREADS, 2) void hff2_kernel(const float* __restrict__ b2)
{
    int m0 = blockIdx.y * 128, n0 = blockIdx.x * 128;
    hgemm<4096>(g_ff, FFd, g_w2t, 4096, m0, n0,
        [&](int row, int c0, float v0, float v1) {
            size_t o = (size_t)row * Hh + c0;
            g_tmp[o]     = v0 + b2[c0]     + g_h1[o];
            g_tmp[o + 1] = v1 + b2[c0 + 1] + g_h1[o + 1];
        });
}

// ---------------- flash attention (fp16, concat-K complex scores) ------------------
constexpr int foQ = 0;
constexpr int foK = 17408;            // P overlays this region
constexpr int foV = 34816;
constexpr size_t SM_FLASH = (size_t)(34816 + 128 * 72) * sizeof(__half);  // 88064 B

__global__ __launch_bounds__(THREADS, 2) void flash_attn_kernel()
{
    extern __shared__ __half hsm[];
    const int tid = threadIdx.x, lane = tid & 31, wid = tid >> 5;
    const int g = lane >> 2, t = lane & 3;
    const int lrow = lane & 15, lhi = (lane >> 4) & 1;
    const int bh = blockIdx.y, b = bh >> 4, head = bh & 15;
    const int m0 = blockIdx.x * 128;

    const __half* Qg = g_q + (size_t)bh * Ss * 128;
    const __half* Kg = g_k + (size_t)bh * Ss * 128;
    const __half* Vg = g_v + (size_t)bh * Ss * Dd;

    const uint32_t sQ = smem_u32(hsm + foQ);
    const uint32_t sK = smem_u32(hsm + foK);
    const uint32_t sV = smem_u32(hsm + foV);

    #pragma unroll
    for (int u = 0; u < 8; ++u) {
        int idx = tid + u * THREADS;
        int m = idx >> 4, q = idx & 15;
        cp16(sQ + (m * 136 + q * 8) * 2, Qg + (size_t)(m0 + m) * 128 + q * 8);
    }
    auto load_kv = [&](int kt) {
        const __half* kp = Kg + (size_t)kt * 128 * 128;
        const __half* vp = Vg + (size_t)kt * 128 * Dd;
        #pragma unroll
        for (int u = 0; u < 8; ++u) {
            int idx = tid + u * THREADS;
            int r = idx >> 4, q = idx & 15;
            cp16(sK + (r * 136 + q * 8) * 2, kp + (size_t)r * 128 + q * 8);
        }
        #pragma unroll
        for (int u = 0; u < 4; ++u) {
            int idx = tid + u * THREADS;
            int r = idx >> 3, q = idx & 7;
            cp16(sV + (r * 72 + q * 8) * 2, vp + (size_t)r * Dd + q * 8);
        }
    };
    load_kv(0);
    cp_commit();

    float m_run0 = -1e30f, m_run1 = -1e30f;
    float l_run0 = 0.f, l_run1 = 0.f;
    float acc_o[8][4] = {};
    const int mr = wid * 16 + g;     // softmax/store row
    const int mq = wid * 16;         // ldmatrix strip base

    for (int kt = 0; kt < Ss / 128; ++kt) {
        cp_wait<0>();
        __syncthreads();

        // scores: [16 x 128] per warp, K=128 (complex real part, scales prefolded)
        float acc_s[16][4] = {};
        #pragma unroll
        for (int ks = 0; ks < 8; ++ks) {
            uint32_t a[4];
            ldsm4(a, sQ + ((mq + lrow) * 136 + ks * 16 + lhi * 8) * 2);
            #pragma unroll
            for (int p = 0; p < 8; ++p) {
                uint32_t bf[4];
                ldsm4(bf, sK + ((p * 16 + lrow) * 136 + ks * 16 + lhi * 8) * 2);
                uint32_t b0[2] = { bf[0], bf[2] };
                uint32_t b1[2] = { bf[1], bf[3] };
                mma16816(acc_s[2 * p],     a, b0);
                mma16816(acc_s[2 * p + 1], a, b1);
            }
        }

        // online softmax (rows mr, mr+8), quad reduction
        float tm0 = -1e30f, tm1 = -1e30f;
        #pragma unroll
        for (int j = 0; j < 16; ++j) {
            tm0 = fmaxf(tm0, fmaxf(acc_s[j][0], acc_s[j][1]));
            tm1 = fmaxf(tm1, fmaxf(acc_s[j][2], acc_s[j][3]));
        }
        #pragma unroll
        for (int o = 1; o <= 2; o <<= 1) {
            tm0 = fmaxf(tm0, __shfl_xor_sync(0xffffffffu, tm0, o));
            tm1 = fmaxf(tm1, __shfl_xor_sync(0xffffffffu, tm1, o));
        }
        float mn0 = fmaxf(m_run0, tm0), mn1 = fmaxf(m_run1, tm1);
        float sc0 = __expf(m_run0 - mn0), sc1 = __expf(m_run1 - mn1);
        m_run0 = mn0; m_run1 = mn1;

        float rs0 = 0.f, rs1 = 0.f;
        #pragma unroll
        for (int j = 0; j < 16; ++j) {
            acc_s[j][0] = __expf(acc_s[j][0] - mn0);
            acc_s[j][1] = __expf(acc_s[j][1] - mn0);
            acc_s[j][2] = __expf(acc_s[j][2] - mn1);
            acc_s[j][3] = __expf(acc_s[j][3] - mn1);
            rs0 += acc_s[j][0] + acc_s[j][1];
            rs1 += acc_s[j][2] + acc_s[j][3];
        }
        #pragma unroll
        for (int o = 1; o <= 2; o <<= 1) {
            rs0 += __shfl_xor_sync(0xffffffffu, rs0, o);
            rs1 += __shfl_xor_sync(0xffffffffu, rs1, o);
        }
        l_run0 = l_run0 * sc0 + rs0;
        l_run1 = l_run1 * sc1 + rs1;
        #pragma unroll
        for (int j = 0; j < 8; ++j) {
            acc_o[j][0] *= sc0; acc_o[j][1] *= sc0;
            acc_o[j][2] *= sc1; acc_o[j][3] *= sc1;
        }

        __syncthreads();   // all warps finished reading K before P overlays it
        #pragma unroll
        for (int j = 0; j < 16; ++j) {
            int c = j * 8 + 2 * t;
            *reinterpret_cast<__half2*>(hsm + foK + mr * 136 + c) =
                __floats2half2_rn(acc_s[j][0], acc_s[j][1]);
            *reinterpret_cast<__half2*>(hsm + foK + (mr + 8) * 136 + c) =
                __floats2half2_rn(acc_s[j][2], acc_s[j][3]);
        }
        __syncwarp();      // P rows are warp-private; warp-level visibility suffices

        // PV: [16 x 128] @ [128 x 64]
        #pragma unroll
        for (int ks = 0; ks < 8; ++ks) {
            uint32_t a[4];
            ldsm4(a, sK + ((mq + lrow) * 136 + ks * 16 + lhi * 8) * 2);
            #pragma unroll
            for (int p = 0; p < 4; ++p) {
                uint32_t bf[4];
                ldsm4t(bf, sV + ((ks * 16 + lrow) * 72 + p * 16 + lhi * 8) * 2);
                uint32_t b0[2] = { bf[0], bf[1] };
                uint32_t b1[2] = { bf[2], bf[3] };
                mma16816(acc_o[2 * p],     a, b0);
                mma16816(acc_o[2 * p + 1], a, b1);
            }
        }

        __syncthreads();   // done with P and V before next KV load
        if (kt + 1 < Ss / 128) { load_kv(kt + 1); cp_commit(); }
    }

    float inv0 = 1.0f / l_run0, inv1 = 1.0f / l_run1;
    int s0 = m0 + mr;
    #pragma unroll
    for (int j = 0; j < 8; ++j) {
        int c = j * 8 + 2 * t;
        __half* o0 = g_concat + ((size_t)(b * Ss + s0)) * Hh + head * Dd + c;
        __half* o1 = g_concat + ((size_t)(b * Ss + s0 + 8)) * Hh + head * Dd + c;
        *reinterpret_cast<__half2*>(o0) =
            __floats2half2_rn(acc_o[j][0] * inv0, acc_o[j][1] * inv0);
        *reinterpret_cast<__half2*>(o1) =
            __floats2half2_rn(acc_o[j][2] * inv1, acc_o[j][3] * inv1);
    }
}

// ---------------- LayerNorms --------------------------------------------------------
__global__ __launch_bounds__(THREADS) void layernorm1_kernel(
    const float* __restrict__ gw, const float* __restrict__ bw)
{
    int row = blockIdx.x;
    const float4* rp = reinterpret_cast<const float4*>(g_tmp + (size_t)row * Hh);
    float4 v = rp[threadIdx.x];
    float s  = v.x + v.y + v.z + v.w;
    float s2 = v.x * v.x + v.y * v.y + v.z * v.z + v.w * v.w;
    #pragma unroll
    for (int o = 16; o; o >>= 1) {
        s  += __shfl_xor_sync(0xffffffffu, s,  o);
        s2 += __shfl_xor_sync(0xffffffffu, s2, o);
    }
    __shared__ float rs[8], rs2[8];
    int lane = threadIdx.x & 31, wid = threadIdx.x >> 5;
    if (lane == 0) { rs[wid] = s; rs2[wid] = s2; }
    __syncthreads();
    s = 0.f; s2 = 0.f;
    #pragma unroll
    for (int i = 0; i < 8; ++i) { s += rs[i]; s2 += rs2[i]; }
    float mu  = s  * (1.0f / Hh);
    float var = s2 * (1.0f / Hh) - mu * mu;
    float inv = rsqrtf(var + EPSLN);
    float4 g4 = reinterpret_cast<const float4*>(gw)[threadIdx.x];
    float4 b4 = reinterpret_cast<const float4*>(bw)[threadIdx.x];
    float4 o4;
    o4.x = (v.x - mu) * inv * g4.x + b4.x;
    o4.y = (v.y - mu) * inv * g4.y + b4.y;
    o4.z = (v.z - mu) * inv * g4.z + b4.z;
    o4.w = (v.w - mu) * inv * g4.w + b4.w;
    reinterpret_cast<float4*>(g_h1 + (size_t)row * Hh)[threadIdx.x] = o4;
    uint2 hh = make_uint2(h2u(__floats2half2_rn(o4.x, o4.y)),
                          h2u(__floats2half2_rn(o4.z, o4.w)));
    reinterpret_cast<uint2*>(g_h1h + (size_t)row * Hh)[threadIdx.x] = hh;
}

__global__ __launch_bounds__(THREADS) void layernorm2_kernel(
    const float* __restrict__ gw, const float* __restrict__ bw,
    float* __restrict__ out)
{
    int row = blockIdx.x;
    const float4* rp = reinterpret_cast<const float4*>(g_tmp + (size_t)row * Hh);
    float4 v = rp[threadIdx.x];
    float s  = v.x + v.y + v.z + v.w;
    float s2 = v.x * v.x + v.y * v.y + v.z * v.z + v.w * v.w;
    #pragma unroll
    for (int o = 16; o; o >>= 1) {
        s  += __shfl_xor_sync(0xffffffffu, s,  o);
        s2 += __shfl_xor_sync(0xffffffffu, s2, o);
    }
    __shared__ float rs[8], rs2[8];
    int lane = threadIdx.x & 31, wid = threadIdx.x >> 5;
    if (lane == 0) { rs[wid] = s; rs2[wid] = s2; }
    __syncthreads();
    s = 0.f; s2 = 0.f;
    #pragma unroll
    for (int i = 0; i < 8; ++i) { s += rs[i]; s2 += rs2[i]; }
    float mu  = s  * (1.0f / Hh);
    float var = s2 * (1.0f / Hh) - mu * mu;
    float inv = rsqrtf(var + EPSLN);
    float4 g4 = reinterpret_cast<const float4*>(gw)[threadIdx.x];
    float4 b4 = reinterpret_cast<const float4*>(bw)[threadIdx.x];
    float4 o4;
    o4.x = (v.x - mu) * inv * g4.x + b4.x;
    o4.y = (v.y - mu) * inv * g4.y + b4.y;
    o4.z = (v.z - mu) * inv * g4.z + b4.z;
    o4.w = (v.w - mu) * inv * g4.w + b4.w;
    reinterpret_cast<float4*>(out + (size_t)row * Hh)[threadIdx.x] = o4;
}

// ---------------- entry ---------------------------------------------------------------
extern "C" void kernel_launch(void* const* d_in, const int* in_sizes, int n_in,
                              void* d_out, int out_size)
{
    const float* x   = (const float*)d_in[0];
    const float* Wqr = (const float*)d_in[1];
    const float* Wqi = (const float*)d_in[2];
    const float* bqr = (const float*)d_in[3];
    const float* bqi = (const float*)d_in[4];
    const float* Wkr = (const float*)d_in[5];
    const float* Wki = (const float*)d_in[6];
    const float* bkr = (const float*)d_in[7];
    const float* bki = (const float*)d_in[8];
    const float* Wv  = (const float*)d_in[9];
    const float* bvv = (const float*)d_in[10];
    const float* pqr = (const float*)d_in[11];
    const float* pqi = (const float*)d_in[12];
    const float* pkr = (const float*)d_in[13];
    const float* pki = (const float*)d_in[14];
    const float* Wo  = (const float*)d_in[15];
    const float* bo  = (const float*)d_in[16];
    const float* W1  = (const float*)d_in[17];
    const float* b1  = (const float*)d_in[18];
    const float* W2  = (const float*)d_in[19];
    const float* b2  = (const float*)d_in[20];
    const float* g1  = (const float*)d_in[21];
    const float* be1 = (const float*)d_in[22];
    const float* g2  = (const float*)d_in[23];
    const float* be2 = (const float*)d_in[24];
    float* out = (float*)d_out;

    static bool attr_done = false;
    if (!attr_done) {
        cudaFuncSetAttribute(hproj_kernel,
            cudaFuncAttributeMaxDynamicSharedMemorySize, (int)SM_HGEMM);
        cudaFuncSetAttribute(hwo_kernel,
            cudaFuncAttributeMaxDynamicSharedMemorySize, (int)SM_HGEMM);
        cudaFuncSetAttribute(hff1_kernel,
            cudaFuncAttributeMaxDynamicSharedMemorySize, (int)SM_HGEMM);
        cudaFuncSetAttribute(hff2_kernel,
            cudaFuncAttributeMaxDynamicSharedMemorySize, (int)SM_HGEMM);
        cudaFuncSetAttribute(flash_attn_kernel,
            cudaFuncAttributeMaxDynamicSharedMemorySize, (int)SM_FLASH);
        attr_done = true;
    }

    __half* xt  = nullptr; cudaGetSymbolAddress((void**)&xt,  g_xt);
    __half* wot = nullptr; cudaGetSymbolAddress((void**)&wot, g_wot);
    __half* w1t = nullptr; cudaGetSymbolAddress((void**)&w1t, g_w1t);
    __half* w2t = nullptr; cudaGetSymbolAddress((void**)&w2t, g_w2t);

    convert_h_kernel<<<(Bb * Ss * Hh / 4 + THREADS - 1) / THREADS, THREADS>>>(
        (const float4*)x, (uint2*)xt, Bb * Ss * Hh / 4);
    dim3 tb(32, 8);
    trans_w_kernel<<<dim3(Hh / 32, Hh / 32), tb>>>(Wo, wot, Hh, Hh);
    trans_w_kernel<<<dim3(FFd / 32, Hh / 32), tb>>>(W1, w1t, Hh, FFd);
    trans_w_kernel<<<dim3(Hh / 32, FFd / 32), tb>>>(W2, w2t, FFd, Hh);
    repack_t_kernel<<<dim3(Hh / 32, Dd / 32, 5 * Nn), tb>>>(Wqr, Wqi, Wkr, Wki, Wv);

    hproj_kernel<<<dim3(5120 / 128, (Bb * Ss) / 128), THREADS, SM_HGEMM>>>(
        bqr, bqi, bkr, bki, bvv, pqr, pqi, pkr, pki);
    flash_attn_kernel<<<dim3(Ss / 128, Bb * Nn), THREADS, SM_FLASH>>>();
    hwo_kernel<<<dim3(Hh / 128, (Bb * Ss) / 128), THREADS, SM_HGEMM>>>(bo, x);
    layernorm1_kernel<<<Bb * Ss, THREADS>>>(g1, be1);
    hff1_kernel<<<dim3(FFd / 128, (Bb * Ss) / 128), THREADS, SM_HGEMM>>>(b1);
    hff2_kernel<<<dim3(Hh / 128, (Bb * Ss) / 128), THREADS, SM_HGEMM>>>(b2);
    layernorm2_kernel<<<Bb * Ss, THREADS>>>(g2, be2, out);
}

// round 7
// speedup vs baseline: 6.2765x; 1.0272x over previous
#include <cuda_runtime.h>
#include <cuda_fp16.h>
#include <math.h>
#include <stdint.h>

#define THREADS 256
constexpr int Bb  = 4;
constexpr int Ss  = 1024;
constexpr int Hh  = 1024;
constexpr int Nn  = 16;
constexpr int Dd  = 64;
constexpr int FFd = 4096;
constexpr float SCALE = 0.125f;
constexpr float EPSLN = 1e-5f;

// ---------------- scratch (fp16 operands, fp32 residual path) -------------------
__device__ __half g_wpack[5120 * 1024];     // [N=5120][K=1024] qkv weights
__device__ __half g_xt  [Bb * Ss * Hh];     // [M][K]
__device__ __half g_wot [Hh * Hh];          // Wo^T [N][K]
__device__ __half g_w1t [FFd * Hh];         // W1^T
__device__ __half g_w2t [Hh * FFd];         // W2^T
__device__ __half g_q[Bb * Nn * Ss * 128];  // [qr*s2+pos*s | -(qi*s2+pos*s)] concat
__device__ __half g_k[Bb * Nn * Ss * 128];  // [kr+pos | ki+pos]
__device__ __half g_v[Bb * Nn * Ss * Dd];
__device__ __half g_concat[Bb * Ss * Hh];
__device__ float  g_h1 [Bb * Ss * Hh];
__device__ __half g_h1h[Bb * Ss * Hh];
__device__ float  g_tmp[Bb * Ss * Hh];
__device__ __half g_ff[(size_t)Bb * Ss * FFd];

// ---------------- helpers ---------------------------------------------------------
__device__ __forceinline__ uint32_t smem_u32(const void* p) {
    return (uint32_t)__cvta_generic_to_shared(p);
}
__device__ __forceinline__ void cp16(uint32_t dst, const void* src) {
    asm volatile("cp.async.cg.shared.global [%0], [%1], 16;" :: "r"(dst), "l"(src));
}
__device__ __forceinline__ void cp_commit() {
    asm volatile("cp.async.commit_group;");
}
template<int N> __device__ __forceinline__ void cp_wait() {
    asm volatile("cp.async.wait_group %0;" :: "n"(N));
}
__device__ __forceinline__ void mma16816(float (&c)[4], const uint32_t (&a)[4],
                                         const uint32_t (&b)[2]) {
    asm volatile(
        "mma.sync.aligned.m16n8k16.row.col.f32.f16.f16.f32 "
        "{%0,%1,%2,%3}, {%4,%5,%6,%7}, {%8,%9}, {%0,%1,%2,%3};"
        : "+f"(c[0]), "+f"(c[1]), "+f"(c[2]), "+f"(c[3])
        : "r"(a[0]), "r"(a[1]), "r"(a[2]), "r"(a[3]), "r"(b[0]), "r"(b[1]));
}
__device__ __forceinline__ void ldsm4(uint32_t (&r)[4], uint32_t addr) {
    asm volatile("ldmatrix.sync.aligned.m8n8.x4.shared.b16 {%0,%1,%2,%3}, [%4];"
        : "=r"(r[0]), "=r"(r[1]), "=r"(r[2]), "=r"(r[3]) : "r"(addr));
}
__device__ __forceinline__ void ldsm4t(uint32_t (&r)[4], uint32_t addr) {
    asm volatile("ldmatrix.sync.aligned.m8n8.x4.trans.shared.b16 {%0,%1,%2,%3}, [%4];"
        : "=r"(r[0]), "=r"(r[1]), "=r"(r[2]), "=r"(r[3]) : "r"(addr));
}
__device__ __forceinline__ uint32_t h2u(__half2 h) {
    return *reinterpret_cast<uint32_t*>(&h);
}

// ---------------- fp16 tensor-core GEMM core ---------------------------------------
constexpr int hBK  = 64;
constexpr int hLDS = hBK + 8;                 // 72 halves = 144B rows
constexpr int hTILE = 128 * hLDS;
constexpr size_t SM_HGEMM = (size_t)2 * 2 * hTILE * sizeof(__half);   // 73728 B

template<int KTOT, typename Epi>
__device__ __forceinline__ void hgemm(
    const __half* __restrict__ A, int lda,
    const __half* __restrict__ B, int ldb,
    int m0, int n0, Epi epi)
{
    extern __shared__ __half hsm[];
    const int tid = threadIdx.x, lane = tid & 31, wid = tid >> 5;
    const int wm = wid >> 2, wn = wid & 3;
    const int lrow = lane & 15, lhi = (lane >> 4) & 1;

    auto load_tile = [&](int buf, int kc) {
        __half* a = hsm + buf * (2 * hTILE);
        __half* b = a + hTILE;
        uint32_t ab = smem_u32(a), bb = smem_u32(b);
        #pragma unroll
        for (int u = 0; u < 4; ++u) {
            int idx = tid + u * THREADS;
            int m = idx >> 3, kq = idx & 7;
            cp16(ab + (m * hLDS + kq * 8) * 2,
                 A + (size_t)(m0 + m) * lda + kc * hBK + kq * 8);
        }
        #pragma unroll
        for (int u = 0; u < 4; ++u) {
            int idx = tid + u * THREADS;
            int n = idx >> 3, kq = idx & 7;
            cp16(bb + (n * hLDS + kq * 8) * 2,
                 B + (size_t)(n0 + n) * ldb + kc * hBK + kq * 8);
        }
    };

    float acc[4][4][4] = {};

    auto compute = [&](int buf) {
        __half* a = hsm + buf * (2 * hTILE);
        __half* b = a + hTILE;
        uint32_t ab = smem_u32(a), bb = smem_u32(b);
        #pragma unroll
        for (int ks = 0; ks < hBK / 16; ++ks) {
            int kk = ks * 16;
            uint32_t af[4][4];
            #pragma unroll
            for (int i = 0; i < 4; ++i) {
                int row = wm * 64 + i * 16 + lrow;
                ldsm4(af[i], ab + (row * hLDS + kk + lhi * 8) * 2);
            }
            #pragma unroll
            for (int p = 0; p < 2; ++p) {
                uint32_t bf[4];
                int nr = wn * 32 + p * 16 + lrow;
                ldsm4(bf, bb + (nr * hLDS + kk + lhi * 8) * 2);
                uint32_t b0[2] = { bf[0], bf[2] };
                uint32_t b1[2] = { bf[1], bf[3] };
                #pragma unroll
                for (int i = 0; i < 4; ++i) {
                    mma16816(acc[i][2 * p],     af[i], b0);
                    mma16816(acc[i][2 * p + 1], af[i], b1);
                }
            }
        }
    };

    constexpr int T = KTOT / hBK;
    load_tile(0, 0);
    cp_commit();
    for (int i = 0; i < T; ++i) {
        cp_wait<0>();
        __syncthreads();
        if (i + 1 < T) { load_tile((i + 1) & 1, i + 1); cp_commit(); }
        compute(i & 1);
    }

    const int g = lane >> 2, t = lane & 3;
    #pragma unroll
    for (int i = 0; i < 4; ++i) {
        int r0 = m0 + (wm * 4 + i) * 16 + g;
        #pragma unroll
        for (int j = 0; j < 4; ++j) {
            int c0 = n0 + (wn * 4 + j) * 8 + 2 * t;
            epi(r0,     c0, acc[i][j][0], acc[i][j][1]);
            epi(r0 + 8, c0, acc[i][j][2], acc[i][j][3]);
        }
    }
}

// ---------------- pre-conversion kernels (optimized) --------------------------------
__global__ __launch_bounds__(THREADS) void convert_h_kernel(
    const float4* __restrict__ src, uint2* __restrict__ dst, int n4)
{
    int base = blockIdx.x * (THREADS * 4) + threadIdx.x;
    #pragma unroll
    for (int u = 0; u < 4; ++u) {
        int i = base + u * THREADS;
        if (i < n4) {
            float4 v = src[i];
            dst[i] = make_uint2(h2u(__floats2half2_rn(v.x, v.y)),
                                h2u(__floats2half2_rn(v.z, v.w)));
        }
    }
}

// transpose+convert: src [R][C] f32 -> dst [C][R] half. Tile = 128 R-rows x 64 C-cols.
__global__ __launch_bounds__(THREADS) void trans_w_kernel(
    const float* __restrict__ src, __half* __restrict__ dst, int R, int C)
{
    __shared__ float t[64][133];
    const int tid = threadIdx.x;
    const int c0 = blockIdx.x * 64, r0 = blockIdx.y * 128;
    const int cc = tid & 63, rr = tid >> 6;
    #pragma unroll
    for (int u = 0; u < 32; ++u) {
        int r = rr + u * 4;
        t[cc][r] = src[(size_t)(r0 + r) * C + c0 + cc];
    }
    __syncthreads();
    const int k2 = (tid & 63) * 2, j0 = tid >> 6;
    #pragma unroll
    for (int u = 0; u < 16; ++u) {
        int j = j0 + u * 4;
        *reinterpret_cast<__half2*>(dst + (size_t)(c0 + j) * R + r0 + k2) =
            __floats2half2_rn(t[j][k2], t[j][k2 + 1]);
    }
}

// qkv weights: 5x [N,H,D] -> g_wpack rows (p*1024+n*64+d), K=1024. Tile 128x64.
__global__ __launch_bounds__(THREADS) void repack_t_kernel(
    const float* __restrict__ Wqr, const float* __restrict__ Wqi,
    const float* __restrict__ Wkr, const float* __restrict__ Wki,
    const float* __restrict__ Wv)
{
    __shared__ float t[64][133];
    const int tid = threadIdx.x;
    const int z = blockIdx.z;
    const int p = z >> 4, n = z & 15;
    const float* W = (p == 0) ? Wqr : (p == 1) ? Wqi : (p == 2) ? Wkr
                    : (p == 3) ? Wki : Wv;
    W += (size_t)n * (Hh * Dd);           // [K=1024][D=64]
    const int r0 = blockIdx.y * 128;      // K offset
    const int cc = tid & 63, rr = tid >> 6;
    #pragma unroll
    for (int u = 0; u < 32; ++u) {
        int r = rr + u * 4;
        t[cc][r] = W[(size_t)(r0 + r) * Dd + cc];
    }
    __syncthreads();
    const int rbase = p * 1024 + n * 64;
    const int k2 = (tid & 63) * 2, j0 = tid >> 6;
    #pragma unroll
    for (int u = 0; u < 16; ++u) {
        int j = j0 + u * 4;
        *reinterpret_cast<__half2*>(g_wpack + (size_t)(rbase + j) * 1024 + r0 + k2) =
            __floats2half2_rn(t[j][k2], t[j][k2 + 1]);
    }
}

// ---------------- GEMM kernels -----------------------------------------------------
__global__ __launch_bounds__(THREADS, 2) void hproj_kernel(
    const float* __restrict__ bqr, const float* __restrict__ bqi,
    const float* __restrict__ bkr, const float* __restrict__ bki,
    const float* __restrict__ bvv,
    const float* __restrict__ pqr, const float* __restrict__ pqi,
    const float* __restrict__ pkr, const float* __restrict__ pki)
{
    int m0 = blockIdx.y * 128, n0 = blockIdx.x * 128;
    hgemm<1024>(g_xt, Hh, g_wpack, 1024, m0, n0,
        [&](int row, int col, float v0, float v1) {
            int p = col >> 10, n = (col >> 6) & 15, d = col & 63;
            int bb = row >> 10, s = row & 1023;
            size_t pidx = (((size_t)n << 10) + s) * Dd + d;
            size_t rowoff = (((size_t)(bb * Nn + n)) << 10) + s;
            float x0, x1;
            __half* dst;
            if (p == 0) {
                x0 = ((v0 + bqr[n * Dd + d])     * SCALE + pqr[pidx])     * SCALE;
                x1 = ((v1 + bqr[n * Dd + d + 1]) * SCALE + pqr[pidx + 1]) * SCALE;
                dst = g_q + rowoff * 128 + d;
            } else if (p == 1) {
                x0 = -(((v0 + bqi[n * Dd + d])     * SCALE + pqi[pidx])     * SCALE);
                x1 = -(((v1 + bqi[n * Dd + d + 1]) * SCALE + pqi[pidx + 1]) * SCALE);
                dst = g_q + rowoff * 128 + 64 + d;
            } else if (p == 2) {
                x0 = v0 + bkr[n * Dd + d]     + pkr[pidx];
                x1 = v1 + bkr[n * Dd + d + 1] + pkr[pidx + 1];
                dst = g_k + rowoff * 128 + d;
            } else if (p == 3) {
                x0 = v0 + bki[n * Dd + d]     + pki[pidx];
                x1 = v1 + bki[n * Dd + d + 1] + pki[pidx + 1];
                dst = g_k + rowoff * 128 + 64 + d;
            } else {
                x0 = v0 + bvv[n * Dd + d];
                x1 = v1 + bvv[n * Dd + d + 1];
                dst = g_v + rowoff * Dd + d;
            }
            *reinterpret_cast<__half2*>(dst) = __floats2half2_rn(x0, x1);
        });
}

__global__ __launch_bounds__(THREADS, 2) void hwo_kernel(
    const float* __restrict__ bo, const float* __restrict__ x)
{
    int m0 = blockIdx.y * 128, n0 = blockIdx.x * 128;
    hgemm<1024>(g_concat, Hh, g_wot, 1024, m0, n0,
        [&](int row, int c0, float v0, float v1) {
            size_t o = (size_t)row * Hh + c0;
            g_tmp[o]     = v0 + bo[c0]     + x[o];
            g_tmp[o + 1] = v1 + bo[c0 + 1] + x[o + 1];
        });
}

__global__ __launch_bounds__(THREADS, 2) void hff1_kernel(const float* __restrict__ b1)
{
    int m0 = blockIdx.y * 128, n0 = blockIdx.x * 128;
    hgemm<1024>(g_h1h, Hh, g_w1t, 1024, m0, n0,
        [&](int row, int c0, float v0, float v1) {
            size_t o = (size_t)row * FFd + c0;
            *reinterpret_cast<__half2*>(g_ff + o) = __floats2half2_rn(
                fmaxf(v0 + b1[c0], 0.f), fmaxf(v1 + b1[c0 + 1], 0.f));
        });
}

__global__ __launch_bounds__(THREADS, 2) void hff2_kernel(const float* __restrict__ b2)
{
    int m0 = blockIdx.y * 128, n0 = blockIdx.x * 128;
    hgemm<4096>(g_ff, FFd, g_w2t, 4096, m0, n0,
        [&](int row, int c0, float v0, float v1) {
            size_t o = (size_t)row * Hh + c0;
            g_tmp[o]     = v0 + b2[c0]     + g_h1[o];
            g_tmp[o + 1] = v1 + b2[c0 + 1] + g_h1[o + 1];
        });
}

// ---------------- flash attention (P in registers, hoisted Q frags) ----------------
constexpr int foQ = 0;
constexpr int foK = 17408;
constexpr int foV = 34816;
constexpr size_t SM_FLASH = (size_t)(34816 + 128 * 72) * sizeof(__half);  // 88064 B

__global__ __launch_bounds__(THREADS) void flash_attn_kernel()
{
    extern __shared__ __half hsm[];
    const int tid = threadIdx.x, lane = tid & 31, wid = tid >> 5;
    const int g = lane >> 2, t = lane & 3;
    const int lrow = lane & 15, lhi = (lane >> 4) & 1;
    const int bh = blockIdx.y, b = bh >> 4, head = bh & 15;
    const int m0 = blockIdx.x * 128;

    const __half* Qg = g_q + (size_t)bh * Ss * 128;
    const __half* Kg = g_k + (size_t)bh * Ss * 128;
    const __half* Vg = g_v + (size_t)bh * Ss * Dd;

    const uint32_t sQ = smem_u32(hsm + foQ);
    const uint32_t sK = smem_u32(hsm + foK);
    const uint32_t sV = smem_u32(hsm + foV);

    #pragma unroll
    for (int u = 0; u < 8; ++u) {
        int idx = tid + u * THREADS;
        int m = idx >> 4, q = idx & 15;
        cp16(sQ + (m * 136 + q * 8) * 2, Qg + (size_t)(m0 + m) * 128 + q * 8);
    }
    cp_commit();

    auto load_kv = [&](int kt) {
        const __half* kp = Kg + (size_t)kt * 128 * 128;
        const __half* vp = Vg + (size_t)kt * 128 * Dd;
        #pragma unroll
        for (int u = 0; u < 8; ++u) {
            int idx = tid + u * THREADS;
            int r = idx >> 4, q = idx & 15;
            cp16(sK + (r * 136 + q * 8) * 2, kp + (size_t)r * 128 + q * 8);
        }
        #pragma unroll
        for (int u = 0; u < 4; ++u) {
            int idx = tid + u * THREADS;
            int r = idx >> 3, q = idx & 7;
            cp16(sV + (r * 72 + q * 8) * 2, vp + (size_t)r * Dd + q * 8);
        }
    };
    load_kv(0);
    cp_commit();

    // hoist Q fragments (loop-invariant)
    const int mq = wid * 16;
    cp_wait<1>();
    __syncthreads();
    uint32_t qf[8][4];
    #pragma unroll
    for (int ks = 0; ks < 8; ++ks)
        ldsm4(qf[ks], sQ + ((mq + lrow) * 136 + ks * 16 + lhi * 8) * 2);

    float m_run0 = -1e30f, m_run1 = -1e30f;
    float l_run0 = 0.f, l_run1 = 0.f;
    float acc_o[8][4] = {};
    const int mr = wid * 16 + g;

    for (int kt = 0; kt < Ss / 128; ++kt) {
        cp_wait<0>();
        __syncthreads();

        // scores: [16 x 128] per warp, K=128 (complex real part, scales prefolded)
        float acc_s[16][4] = {};
        #pragma unroll
        for (int ks = 0; ks < 8; ++ks) {
            #pragma unroll
            for (int p = 0; p < 8; ++p) {
                uint32_t bf[4];
                ldsm4(bf, sK + ((p * 16 + lrow) * 136 + ks * 16 + lhi * 8) * 2);
                uint32_t b0[2] = { bf[0], bf[2] };
                uint32_t b1[2] = { bf[1], bf[3] };
                mma16816(acc_s[2 * p],     qf[ks], b0);
                mma16816(acc_s[2 * p + 1], qf[ks], b1);
            }
        }

        // online softmax (rows mr, mr+8), quad reduction
        float tm0 = -1e30f, tm1 = -1e30f;
        #pragma unroll
        for (int j = 0; j < 16; ++j) {
            tm0 = fmaxf(tm0, fmaxf(acc_s[j][0], acc_s[j][1]));
            tm1 = fmaxf(tm1, fmaxf(acc_s[j][2], acc_s[j][3]));
        }
        #pragma unroll
        for (int o = 1; o <= 2; o <<= 1) {
            tm0 = fmaxf(tm0, __shfl_xor_sync(0xffffffffu, tm0, o));
            tm1 = fmaxf(tm1, __shfl_xor_sync(0xffffffffu, tm1, o));
        }
        float mn0 = fmaxf(m_run0, tm0), mn1 = fmaxf(m_run1, tm1);
        float sc0 = __expf(m_run0 - mn0), sc1 = __expf(m_run1 - mn1);
        m_run0 = mn0; m_run1 = mn1;

        float rs0 = 0.f, rs1 = 0.f;
        #pragma unroll
        for (int j = 0; j < 16; ++j) {
            acc_s[j][0] = __expf(acc_s[j][0] - mn0);
            acc_s[j][1] = __expf(acc_s[j][1] - mn0);
            acc_s[j][2] = __expf(acc_s[j][2] - mn1);
            acc_s[j][3] = __expf(acc_s[j][3] - mn1);
            rs0 += acc_s[j][0] + acc_s[j][1];
            rs1 += acc_s[j][2] + acc_s[j][3];
        }
        #pragma unroll
        for (int o = 1; o <= 2; o <<= 1) {
            rs0 += __shfl_xor_sync(0xffffffffu, rs0, o);
            rs1 += __shfl_xor_sync(0xffffffffu, rs1, o);
        }
        l_run0 = l_run0 * sc0 + rs0;
        l_run1 = l_run1 * sc1 + rs1;
        #pragma unroll
        for (int j = 0; j < 8; ++j) {
            acc_o[j][0] *= sc0; acc_o[j][1] *= sc0;
            acc_o[j][2] *= sc1; acc_o[j][3] *= sc1;
        }

        // pack P into A-fragments in registers (scores C-frag == PV A-frag layout)
        uint32_t pf[8][4];
        #pragma unroll
        for (int k2 = 0; k2 < 8; ++k2) {
            pf[k2][0] = h2u(__floats2half2_rn(acc_s[2 * k2][0],     acc_s[2 * k2][1]));
            pf[k2][1] = h2u(__floats2half2_rn(acc_s[2 * k2][2],     acc_s[2 * k2][3]));
            pf[k2][2] = h2u(__floats2half2_rn(acc_s[2 * k2 + 1][0], acc_s[2 * k2 + 1][1]));
            pf[k2][3] = h2u(__floats2half2_rn(acc_s[2 * k2 + 1][2], acc_s[2 * k2 + 1][3]));
        }

        // PV: [16 x 128] @ [128 x 64], P from registers
        #pragma unroll
        for (int ks = 0; ks < 8; ++ks) {
            #pragma unroll
            for (int p = 0; p < 4; ++p) {
                uint32_t bf[4];
                ldsm4t(bf, sV + ((ks * 16 + lrow) * 72 + p * 16 + lhi * 8) * 2);
                uint32_t b0[2] = { bf[0], bf[1] };
                uint32_t b1[2] = { bf[2], bf[3] };
                mma16816(acc_o[2 * p],     pf[ks], b0);
                mma16816(acc_o[2 * p + 1], pf[ks], b1);
            }
        }

        __syncthreads();   // done reading K/V before next tile load
        if (kt + 1 < Ss / 128) { load_kv(kt + 1); cp_commit(); }
    }

    float inv0 = 1.0f / l_run0, inv1 = 1.0f / l_run1;
    int s0 = m0 + mr;
    #pragma unroll
    for (int j = 0; j < 8; ++j) {
        int c = j * 8 + 2 * t;
        __half* o0 = g_concat + ((size_t)(b * Ss + s0)) * Hh + head * Dd + c;
        __half* o1 = g_concat + ((size_t)(b * Ss + s0 + 8)) * Hh + head * Dd + c;
        *reinterpret_cast<__half2*>(o0) =
            __floats2half2_rn(acc_o[j][0] * inv0, acc_o[j][1] * inv0);
        *reinterpret_cast<__half2*>(o1) =
            __floats2half2_rn(acc_o[j][2] * inv1, acc_o[j][3] * inv1);
    }
}

// ---------------- LayerNorms --------------------------------------------------------
__global__ __launch_bounds__(THREADS) void layernorm1_kernel(
    const float* __restrict__ gw, const float* __restrict__ bw)
{
    int row = blockIdx.x;
    const float4* rp = reinterpret_cast<const float4*>(g_tmp + (size_t)row * Hh);
    float4 v = rp[threadIdx.x];
    float s  = v.x + v.y + v.z + v.w;
    float s2 = v.x * v.x + v.y * v.y + v.z * v.z + v.w * v.w;
    #pragma unroll
    for (int o = 16; o; o >>= 1) {
        s  += __shfl_xor_sync(0xffffffffu, s,  o);
        s2 += __shfl_xor_sync(0xffffffffu, s2, o);
    }
    __shared__ float rs[8], rs2[8];
    int lane = threadIdx.x & 31, wid = threadIdx.x >> 5;
    if (lane == 0) { rs[wid] = s; rs2[wid] = s2; }
    __syncthreads();
    s = 0.f; s2 = 0.f;
    #pragma unroll
    for (int i = 0; i < 8; ++i) { s += rs[i]; s2 += rs2[i]; }
    float mu  = s  * (1.0f / Hh);
    float var = s2 * (1.0f / Hh) - mu * mu;
    float inv = rsqrtf(var + EPSLN);
    float4 g4 = reinterpret_cast<const float4*>(gw)[threadIdx.x];
    float4 b4 = reinterpret_cast<const float4*>(bw)[threadIdx.x];
    float4 o4;
    o4.x = (v.x - mu) * inv * g4.x + b4.x;
    o4.y = (v.y - mu) * inv * g4.y + b4.y;
    o4.z = (v.z - mu) * inv * g4.z + b4.z;
    o4.w = (v.w - mu) * inv * g4.w + b4.w;
    reinterpret_cast<float4*>(g_h1 + (size_t)row * Hh)[threadIdx.x] = o4;
    uint2 hh = make_uint2(h2u(__floats2half2_rn(o4.x, o4.y)),
                          h2u(__floats2half2_rn(o4.z, o4.w)));
    reinterpret_cast<uint2*>(g_h1h + (size_t)row * Hh)[threadIdx.x] = hh;
}

__global__ __launch_bounds__(THREADS) void layernorm2_kernel(
    const float* __restrict__ gw, const float* __restrict__ bw,
    float* __restrict__ out)
{
    int row = blockIdx.x;
    const float4* rp = reinterpret_cast<const float4*>(g_tmp + (size_t)row * Hh);
    float4 v = rp[threadIdx.x];
    float s  = v.x + v.y + v.z + v.w;
    float s2 = v.x * v.x + v.y * v.y + v.z * v.z + v.w * v.w;
    #pragma unroll
    for (int o = 16; o; o >>= 1) {
        s  += __shfl_xor_sync(0xffffffffu, s,  o);
        s2 += __shfl_xor_sync(0xffffffffu, s2, o);
    }
    __shared__ float rs[8], rs2[8];
    int lane = threadIdx.x & 31, wid = threadIdx.x >> 5;
    if (lane == 0) { rs[wid] = s; rs2[wid] = s2; }
    __syncthreads();
    s = 0.f; s2 = 0.f;
    #pragma unroll
    for (int i = 0; i < 8; ++i) { s += rs[i]; s2 += rs2[i]; }
    float mu  = s  * (1.0f / Hh);
    float var = s2 * (1.0f / Hh) - mu * mu;
    float inv = rsqrtf(var + EPSLN);
    float4 g4 = reinterpret_cast<const float4*>(gw)[threadIdx.x];
    float4 b4 = reinterpret_cast<const float4*>(bw)[threadIdx.x];
    float4 o4;
    o4.x = (v.x - mu) * inv * g4.x + b4.x;
    o4.y = (v.y - mu) * inv * g4.y + b4.y;
    o4.z = (v.z - mu) * inv * g4.z + b4.z;
    o4.w = (v.w - mu) * inv * g4.w + b4.w;
    reinterpret_cast<float4*>(out + (size_t)row * Hh)[threadIdx.x] = o4;
}

// ---------------- entry ---------------------------------------------------------------
extern "C" void kernel_launch(void* const* d_in, const int* in_sizes, int n_in,
                              void* d_out, int out_size)
{
    const float* x   = (const float*)d_in[0];
    const float* Wqr = (const float*)d_in[1];
    const float* Wqi = (const float*)d_in[2];
    const float* bqr = (const float*)d_in[3];
    const float* bqi = (const float*)d_in[4];
    const float* Wkr = (const float*)d_in[5];
    const float* Wki = (const float*)d_in[6];
    const float* bkr = (const float*)d_in[7];
    const float* bki = (const float*)d_in[8];
    const float* Wv  = (const float*)d_in[9];
    const float* bvv = (const float*)d_in[10];
    const float* pqr = (const float*)d_in[11];
    const float* pqi = (const float*)d_in[12];
    const float* pkr = (const float*)d_in[13];
    const float* pki = (const float*)d_in[14];
    const float* Wo  = (const float*)d_in[15];
    const float* bo  = (const float*)d_in[16];
    const float* W1  = (const float*)d_in[17];
    const float* b1  = (const float*)d_in[18];
    const float* W2  = (const float*)d_in[19];
    const float* b2  = (const float*)d_in[20];
    const float* g1  = (const float*)d_in[21];
    const float* be1 = (const float*)d_in[22];
    const float* g2  = (const float*)d_in[23];
    const float* be2 = (const float*)d_in[24];
    float* out = (float*)d_out;

    static bool attr_done = false;
    if (!attr_done) {
        cudaFuncSetAttribute(hproj_kernel,
            cudaFuncAttributeMaxDynamicSharedMemorySize, (int)SM_HGEMM);
        cudaFuncSetAttribute(hwo_kernel,
            cudaFuncAttributeMaxDynamicSharedMemorySize, (int)SM_HGEMM);
        cudaFuncSetAttribute(hff1_kernel,
            cudaFuncAttributeMaxDynamicSharedMemorySize, (int)SM_HGEMM);
        cudaFuncSetAttribute(hff2_kernel,
            cudaFuncAttributeMaxDynamicSharedMemorySize, (int)SM_HGEMM);
        cudaFuncSetAttribute(flash_attn_kernel,
            cudaFuncAttributeMaxDynamicSharedMemorySize, (int)SM_FLASH);
        attr_done = true;
    }

    __half* xt  = nullptr; cudaGetSymbolAddress((void**)&xt,  g_xt);
    __half* wot = nullptr; cudaGetSymbolAddress((void**)&wot, g_wot);
    __half* w1t = nullptr; cudaGetSymbolAddress((void**)&w1t, g_w1t);
    __half* w2t = nullptr; cudaGetSymbolAddress((void**)&w2t, g_w2t);

    int n4x = Bb * Ss * Hh / 4;
    convert_h_kernel<<<(n4x + THREADS * 4 - 1) / (THREADS * 4), THREADS>>>(
        (const float4*)x, (uint2*)xt, n4x);
    trans_w_kernel<<<dim3(Hh / 64, Hh / 128), THREADS>>>(Wo, wot, Hh, Hh);
    trans_w_kernel<<<dim3(FFd / 64, Hh / 128), THREADS>>>(W1, w1t, Hh, FFd);
    trans_w_kernel<<<dim3(Hh / 64, FFd / 128), THREADS>>>(W2, w2t, FFd, Hh);
    repack_t_kernel<<<dim3(1, Hh / 128, 5 * Nn), THREADS>>>(Wqr, Wqi, Wkr, Wki, Wv);

    hproj_kernel<<<dim3(5120 / 128, (Bb * Ss) / 128), THREADS, SM_HGEMM>>>(
        bqr, bqi, bkr, bki, bvv, pqr, pqi, pkr, pki);
    flash_attn_kernel<<<dim3(Ss / 128, Bb * Nn), THREADS, SM_FLASH>>>();
    hwo_kernel<<<dim3(Hh / 128, (Bb * Ss) / 128), THREADS, SM_HGEMM>>>(bo, x);
    layernorm1_kernel<<<Bb * Ss, THREADS>>>(g1, be1);
    hff1_kernel<<<dim3(FFd / 128, (Bb * Ss) / 128), THREADS, SM_HGEMM>>>(b1);
    hff2_kernel<<<dim3(Hh / 128, (Bb * Ss) / 128), THREADS, SM_HGEMM>>>(b2);
    layernorm2_kernel<<<Bb * Ss, THREADS>>>(g2, be2, out);
}

// round 8
// speedup vs baseline: 6.9231x; 1.1030x over previous
#include <cuda_runtime.h>
#include <cuda_fp16.h>
#include <math.h>
#include <stdint.h>

#define THREADS 256
constexpr int Bb  = 4;
constexpr int Ss  = 1024;
constexpr int Hh  = 1024;
constexpr int Nn  = 16;
constexpr int Dd  = 64;
constexpr int FFd = 4096;
constexpr float SCALE = 0.125f;
constexpr float EPSLN = 1e-5f;

// ---------------- scratch (fp16 operands, fp32 residual path) -------------------
__device__ __half g_wpack[1024 * 5120];     // [K=1024][N=5120] qkv weights
__device__ __half g_xt  [Bb * Ss * Hh];     // [M][K]
__device__ __half g_woh [Hh * Hh];          // Wo as-is [K=H][N=H]
__device__ __half g_w1h [Hh * FFd];         // W1 as-is [K=H][N=FF]
__device__ __half g_w2h [FFd * Hh];         // W2 as-is [K=FF][N=H]
__device__ __half g_q[Bb * Nn * Ss * 128];  // [qr*s2+pos*s | -(qi*s2+pos*s)]
__device__ __half g_k[Bb * Nn * Ss * 128];  // [kr+pos | ki+pos]
__device__ __half g_v[Bb * Nn * Ss * Dd];
__device__ __half g_concat[Bb * Ss * Hh];
__device__ float  g_h1 [Bb * Ss * Hh];
__device__ __half g_h1h[Bb * Ss * Hh];
__device__ float  g_tmp[Bb * Ss * Hh];
__device__ __half g_ff[(size_t)Bb * Ss * FFd];

// ---------------- helpers ---------------------------------------------------------
__device__ __forceinline__ uint32_t smem_u32(const void* p) {
    return (uint32_t)__cvta_generic_to_shared(p);
}
__device__ __forceinline__ void cp16(uint32_t dst, const void* src) {
    asm volatile("cp.async.cg.shared.global [%0], [%1], 16;" :: "r"(dst), "l"(src));
}
__device__ __forceinline__ void cp_commit() {
    asm volatile("cp.async.commit_group;");
}
template<int N> __device__ __forceinline__ void cp_wait() {
    asm volatile("cp.async.wait_group %0;" :: "n"(N));
}
__device__ __forceinline__ void mma16816(float (&c)[4], const uint32_t (&a)[4],
                                         const uint32_t (&b)[2]) {
    asm volatile(
        "mma.sync.aligned.m16n8k16.row.col.f32.f16.f16.f32 "
        "{%0,%1,%2,%3}, {%4,%5,%6,%7}, {%8,%9}, {%0,%1,%2,%3};"
        : "+f"(c[0]), "+f"(c[1]), "+f"(c[2]), "+f"(c[3])
        : "r"(a[0]), "r"(a[1]), "r"(a[2]), "r"(a[3]), "r"(b[0]), "r"(b[1]));
}
__device__ __forceinline__ void ldsm4(uint32_t (&r)[4], uint32_t addr) {
    asm volatile("ldmatrix.sync.aligned.m8n8.x4.shared.b16 {%0,%1,%2,%3}, [%4];"
        : "=r"(r[0]), "=r"(r[1]), "=r"(r[2]), "=r"(r[3]) : "r"(addr));
}
__device__ __forceinline__ void ldsm4t(uint32_t (&r)[4], uint32_t addr) {
    asm volatile("ldmatrix.sync.aligned.m8n8.x4.trans.shared.b16 {%0,%1,%2,%3}, [%4];"
        : "=r"(r[0]), "=r"(r[1]), "=r"(r[2]), "=r"(r[3]) : "r"(addr));
}
__device__ __forceinline__ uint32_t h2u(__half2 h) {
    return *reinterpret_cast<uint32_t*>(&h);
}

// ---------------- fp16 tensor-core GEMM core (B in [K][N] layout) -------------------
// D[128x128] = A[m0..,K] @ B[K, n0..] ; A [M][K], B [K][N] row-major fp16.
// BK=64 double-buffered cp.async. A-frags via ldsm4, B-frags via ldsm4t
// (pattern validated by the flash PV path).
constexpr int hLA  = 72;                  // A smem row stride (halves)
constexpr int hLB  = 136;                 // B smem row stride (halves)
constexpr int hASZ = 128 * hLA;           // 9216 halves
constexpr int hBSZ = 64 * hLB;            // 8704 halves
constexpr int hBUF = hASZ + hBSZ;         // 17920 halves
constexpr size_t SM_HGEMM = (size_t)2 * hBUF * sizeof(__half);   // 71680 B

template<int KTOT, typename Epi>
__device__ __forceinline__ void hgemm(
    const __half* __restrict__ A, int lda,
    const __half* __restrict__ B, int ldb,
    int m0, int n0, Epi epi)
{
    extern __shared__ __half hsm[];
    const int tid = threadIdx.x, lane = tid & 31, wid = tid >> 5;
    const int wm = wid >> 2, wn = wid & 3;
    const int lrow = lane & 15, lhi = (lane >> 4) & 1;

    auto load_tile = [&](int buf, int kc) {
        __half* a = hsm + buf * hBUF;
        __half* b = a + hASZ;
        uint32_t ab = smem_u32(a), bb = smem_u32(b);
        #pragma unroll
        for (int u = 0; u < 4; ++u) {
            int idx = tid + u * THREADS;
            int m = idx >> 3, kq = idx & 7;
            cp16(ab + (m * hLA + kq * 8) * 2,
                 A + (size_t)(m0 + m) * lda + kc * 64 + kq * 8);
        }
        #pragma unroll
        for (int u = 0; u < 4; ++u) {
            int idx = tid + u * THREADS;
            int r = idx >> 4, q = idx & 15;
            cp16(bb + (r * hLB + q * 8) * 2,
                 B + (size_t)(kc * 64 + r) * ldb + n0 + q * 8);
        }
    };

    float acc[4][4][4] = {};

    auto compute = [&](int buf) {
        __half* a = hsm + buf * hBUF;
        __half* b = a + hASZ;
        uint32_t ab = smem_u32(a), bb = smem_u32(b);
        #pragma unroll
        for (int ks = 0; ks < 4; ++ks) {
            int kk = ks * 16;
            uint32_t af[4][4];
            #pragma unroll
            for (int i = 0; i < 4; ++i) {
                int row = wm * 64 + i * 16 + lrow;
                ldsm4(af[i], ab + (row * hLA + kk + lhi * 8) * 2);
            }
            #pragma unroll
            for (int p = 0; p < 2; ++p) {
                uint32_t bf[4];
                ldsm4t(bf, bb + ((kk + lrow) * hLB + wn * 32 + p * 16 + lhi * 8) * 2);
                uint32_t b0[2] = { bf[0], bf[1] };
                uint32_t b1[2] = { bf[2], bf[3] };
                #pragma unroll
                for (int i = 0; i < 4; ++i) {
                    mma16816(acc[i][2 * p],     af[i], b0);
                    mma16816(acc[i][2 * p + 1], af[i], b1);
                }
            }
        }
    };

    constexpr int T = KTOT / 64;
    load_tile(0, 0);
    cp_commit();
    for (int i = 0; i < T; ++i) {
        cp_wait<0>();
        __syncthreads();
        if (i + 1 < T) { load_tile((i + 1) & 1, i + 1); cp_commit(); }
        compute(i & 1);
    }

    const int g = lane >> 2, t = lane & 3;
    #pragma unroll
    for (int i = 0; i < 4; ++i) {
        int r0 = m0 + (wm * 4 + i) * 16 + g;
        #pragma unroll
        for (int j = 0; j < 4; ++j) {
            int c0 = n0 + (wn * 4 + j) * 8 + 2 * t;
            epi(r0,     c0, acc[i][j][0], acc[i][j][1]);
            epi(r0 + 8, c0, acc[i][j][2], acc[i][j][3]);
        }
    }
}

// ---------------- pre-conversion kernels --------------------------------------------
__global__ __launch_bounds__(THREADS) void convert_h_kernel(
    const float4* __restrict__ src, uint2* __restrict__ dst, int n4)
{
    int base = blockIdx.x * (THREADS * 4) + threadIdx.x;
    #pragma unroll
    for (int u = 0; u < 4; ++u) {
        int i = base + u * THREADS;
        if (i < n4) {
            float4 v = src[i];
            dst[i] = make_uint2(h2u(__floats2half2_rn(v.x, v.y)),
                                h2u(__floats2half2_rn(v.z, v.w)));
        }
    }
}

// qkv weights gather: 5x [N,H,D] f32 -> g_wpack [K=1024][5120] half
__global__ __launch_bounds__(THREADS) void repack_g_kernel(
    const float* __restrict__ Wqr, const float* __restrict__ Wqi,
    const float* __restrict__ Wkr, const float* __restrict__ Wki,
    const float* __restrict__ Wv)
{
    int idx = blockIdx.x * THREADS + threadIdx.x;   // over 1024*5120/4
    int col4 = idx % 1280;
    int k    = idx / 1280;
    int c = col4 * 4;
    int p = c >> 10, n = (c >> 6) & 15, d = c & 63;
    const float* W = (p == 0) ? Wqr : (p == 1) ? Wqi : (p == 2) ? Wkr
                    : (p == 3) ? Wki : Wv;
    float4 v = *reinterpret_cast<const float4*>(
        W + (((size_t)n) << 16) + (size_t)k * 64 + d);
    *reinterpret_cast<uint2*>(g_wpack + (size_t)k * 5120 + c) =
        make_uint2(h2u(__floats2half2_rn(v.x, v.y)),
                   h2u(__floats2half2_rn(v.z, v.w)));
}

// ---------------- GEMM kernels -----------------------------------------------------
__global__ __launch_bounds__(THREADS, 2) void hproj_kernel(
    const float* __restrict__ bqr, const float* __restrict__ bqi,
    const float* __restrict__ bkr, const float* __restrict__ bki,
    const float* __restrict__ bvv,
    const float* __restrict__ pqr, const float* __restrict__ pqi,
    const float* __restrict__ pkr, const float* __restrict__ pki)
{
    int m0 = blockIdx.y * 128, n0 = blockIdx.x * 128;
    hgemm<1024>(g_xt, Hh, g_wpack, 5120, m0, n0,
        [&](int row, int col, float v0, float v1) {
            int p = col >> 10, n = (col >> 6) & 15, d = col & 63;
            int bb = row >> 10, s = row & 1023;
            size_t pidx = (((size_t)n << 10) + s) * Dd + d;
            size_t rowoff = (((size_t)(bb * Nn + n)) << 10) + s;
            float x0, x1;
            __half* dst;
            if (p == 0) {
                x0 = ((v0 + bqr[n * Dd + d])     * SCALE + pqr[pidx])     * SCALE;
                x1 = ((v1 + bqr[n * Dd + d + 1]) * SCALE + pqr[pidx + 1]) * SCALE;
                dst = g_q + rowoff * 128 + d;
            } else if (p == 1) {
                x0 = -(((v0 + bqi[n * Dd + d])     * SCALE + pqi[pidx])     * SCALE);
                x1 = -(((v1 + bqi[n * Dd + d + 1]) * SCALE + pqi[pidx + 1]) * SCALE);
                dst = g_q + rowoff * 128 + 64 + d;
            } else if (p == 2) {
                x0 = v0 + bkr[n * Dd + d]     + pkr[pidx];
                x1 = v1 + bkr[n * Dd + d + 1] + pkr[pidx + 1];
                dst = g_k + rowoff * 128 + d;
            } else if (p == 3) {
                x0 = v0 + bki[n * Dd + d]     + pki[pidx];
                x1 = v1 + bki[n * Dd + d + 1] + pki[pidx + 1];
                dst = g_k + rowoff * 128 + 64 + d;
            } else {
                x0 = v0 + bvv[n * Dd + d];
                x1 = v1 + bvv[n * Dd + d + 1];
                dst = g_v + rowoff * Dd + d;
            }
            *reinterpret_cast<__half2*>(dst) = __floats2half2_rn(x0, x1);
        });
}

__global__ __launch_bounds__(THREADS, 2) void hwo_kernel(
    const float* __restrict__ bo, const float* __restrict__ x)
{
    int m0 = blockIdx.y * 128, n0 = blockIdx.x * 128;
    hgemm<1024>(g_concat, Hh, g_woh, Hh, m0, n0,
        [&](int row, int c0, float v0, float v1) {
            size_t o = (size_t)row * Hh + c0;
            g_tmp[o]     = v0 + bo[c0]     + x[o];
            g_tmp[o + 1] = v1 + bo[c0 + 1] + x[o + 1];
        });
}

__global__ __launch_bounds__(THREADS, 2) void hff1_kernel(const float* __restrict__ b1)
{
    int m0 = blockIdx.y * 128, n0 = blockIdx.x * 128;
    hgemm<1024>(g_h1h, Hh, g_w1h, FFd, m0, n0,
        [&](int row, int c0, float v0, float v1) {
            size_t o = (size_t)row * FFd + c0;
            *reinterpret_cast<__half2*>(g_ff + o) = __floats2half2_rn(
                fmaxf(v0 + b1[c0], 0.f), fmaxf(v1 + b1[c0 + 1], 0.f));
        });
}

__global__ __launch_bounds__(THREADS, 2) void hff2_kernel(const float* __restrict__ b2)
{
    int m0 = blockIdx.y * 128, n0 = blockIdx.x * 128;
    hgemm<4096>(g_ff, FFd, g_w2h, Hh, m0, n0,
        [&](int row, int c0, float v0, float v1) {
            size_t o = (size_t)row * Hh + c0;
            g_tmp[o]     = v0 + b2[c0]     + g_h1[o];
            g_tmp[o + 1] = v1 + b2[c0 + 1] + g_h1[o + 1];
        });
}

// ---------------- flash attention (P in registers, hoisted Q frags) ----------------
constexpr int foQ = 0;
constexpr int foK = 17408;
constexpr int foV = 34816;
constexpr size_t SM_FLASH = (size_t)(34816 + 128 * 72) * sizeof(__half);  // 88064 B

__global__ __launch_bounds__(THREADS) void flash_attn_kernel()
{
    extern __shared__ __half hsm[];
    const int tid = threadIdx.x, lane = tid & 31, wid = tid >> 5;
    const int g = lane >> 2, t = lane & 3;
    const int lrow = lane & 15, lhi = (lane >> 4) & 1;
    const int bh = blockIdx.y, b = bh >> 4, head = bh & 15;
    const int m0 = blockIdx.x * 128;

    const __half* Qg = g_q + (size_t)bh * Ss * 128;
    const __half* Kg = g_k + (size_t)bh * Ss * 128;
    const __half* Vg = g_v + (size_t)bh * Ss * Dd;

    const uint32_t sQ = smem_u32(hsm + foQ);
    const uint32_t sK = smem_u32(hsm + foK);
    const uint32_t sV = smem_u32(hsm + foV);

    #pragma unroll
    for (int u = 0; u < 8; ++u) {
        int idx = tid + u * THREADS;
        int m = idx >> 4, q = idx & 15;
        cp16(sQ + (m * 136 + q * 8) * 2, Qg + (size_t)(m0 + m) * 128 + q * 8);
    }
    cp_commit();

    auto load_kv = [&](int kt) {
        const __half* kp = Kg + (size_t)kt * 128 * 128;
        const __half* vp = Vg + (size_t)kt * 128 * Dd;
        #pragma unroll
        for (int u = 0; u < 8; ++u) {
            int idx = tid + u * THREADS;
            int r = idx >> 4, q = idx & 15;
            cp16(sK + (r * 136 + q * 8) * 2, kp + (size_t)r * 128 + q * 8);
        }
        #pragma unroll
        for (int u = 0; u < 4; ++u) {
            int idx = tid + u * THREADS;
            int r = idx >> 3, q = idx & 7;
            cp16(sV + (r * 72 + q * 8) * 2, vp + (size_t)r * Dd + q * 8);
        }
    };
    load_kv(0);
    cp_commit();

    const int mq = wid * 16;
    cp_wait<1>();
    __syncthreads();
    uint32_t qf[8][4];
    #pragma unroll
    for (int ks = 0; ks < 8; ++ks)
        ldsm4(qf[ks], sQ + ((mq + lrow) * 136 + ks * 16 + lhi * 8) * 2);

    float m_run0 = -1e30f, m_run1 = -1e30f;
    float l_run0 = 0.f, l_run1 = 0.f;
    float acc_o[8][4] = {};
    const int mr = wid * 16 + g;

    for (int kt = 0; kt < Ss / 128; ++kt) {
        cp_wait<0>();
        __syncthreads();

        float acc_s[16][4] = {};
        #pragma unroll
        for (int ks = 0; ks < 8; ++ks) {
            #pragma unroll
            for (int p = 0; p < 8; ++p) {
                uint32_t bf[4];
                ldsm4(bf, sK + ((p * 16 + lrow) * 136 + ks * 16 + lhi * 8) * 2);
                uint32_t b0[2] = { bf[0], bf[2] };
                uint32_t b1[2] = { bf[1], bf[3] };
                mma16816(acc_s[2 * p],     qf[ks], b0);
                mma16816(acc_s[2 * p + 1], qf[ks], b1);
            }
        }

        float tm0 = -1e30f, tm1 = -1e30f;
        #pragma unroll
        for (int j = 0; j < 16; ++j) {
            tm0 = fmaxf(tm0, fmaxf(acc_s[j][0], acc_s[j][1]));
            tm1 = fmaxf(tm1, fmaxf(acc_s[j][2], acc_s[j][3]));
        }
        #pragma unroll
        for (int o = 1; o <= 2; o <<= 1) {
            tm0 = fmaxf(tm0, __shfl_xor_sync(0xffffffffu, tm0, o));
            tm1 = fmaxf(tm1, __shfl_xor_sync(0xffffffffu, tm1, o));
        }
        float mn0 = fmaxf(m_run0, tm0), mn1 = fmaxf(m_run1, tm1);
        float sc0 = __expf(m_run0 - mn0), sc1 = __expf(m_run1 - mn1);
        m_run0 = mn0; m_run1 = mn1;

        float rs0 = 0.f, rs1 = 0.f;
        #pragma unroll
        for (int j = 0; j < 16; ++j) {
            acc_s[j][0] = __expf(acc_s[j][0] - mn0);
            acc_s[j][1] = __expf(acc_s[j][1] - mn0);
            acc_s[j][2] = __expf(acc_s[j][2] - mn1);
            acc_s[j][3] = __expf(acc_s[j][3] - mn1);
            rs0 += acc_s[j][0] + acc_s[j][1];
            rs1 += acc_s[j][2] + acc_s[j][3];
        }
        #pragma unroll
        for (int o = 1; o <= 2; o <<= 1) {
            rs0 += __shfl_xor_sync(0xffffffffu, rs0, o);
            rs1 += __shfl_xor_sync(0xffffffffu, rs1, o);
        }
        l_run0 = l_run0 * sc0 + rs0;
        l_run1 = l_run1 * sc1 + rs1;
        #pragma unroll
        for (int j = 0; j < 8; ++j) {
            acc_o[j][0] *= sc0; acc_o[j][1] *= sc0;
            acc_o[j][2] *= sc1; acc_o[j][3] *= sc1;
        }

        uint32_t pf[8][4];
        #pragma unroll
        for (int k2 = 0; k2 < 8; ++k2) {
            pf[k2][0] = h2u(__floats2half2_rn(acc_s[2 * k2][0],     acc_s[2 * k2][1]));
            pf[k2][1] = h2u(__floats2half2_rn(acc_s[2 * k2][2],     acc_s[2 * k2][3]));
            pf[k2][2] = h2u(__floats2half2_rn(acc_s[2 * k2 + 1][0], acc_s[2 * k2 + 1][1]));
            pf[k2][3] = h2u(__floats2half2_rn(acc_s[2 * k2 + 1][2], acc_s[2 * k2 + 1][3]));
        }

        #pragma unroll
        for (int ks = 0; ks < 8; ++ks) {
            #pragma unroll
            for (int p = 0; p < 4; ++p) {
                uint32_t bf[4];
                ldsm4t(bf, sV + ((ks * 16 + lrow) * 72 + p * 16 + lhi * 8) * 2);
                uint32_t b0[2] = { bf[0], bf[1] };
                uint32_t b1[2] = { bf[2], bf[3] };
                mma16816(acc_o[2 * p],     pf[ks], b0);
                mma16816(acc_o[2 * p + 1], pf[ks], b1);
            }
        }

        __syncthreads();
        if (kt + 1 < Ss / 128) { load_kv(kt + 1); cp_commit(); }
    }

    float inv0 = 1.0f / l_run0, inv1 = 1.0f / l_run1;
    int s0 = m0 + mr;
    #pragma unroll
    for (int j = 0; j < 8; ++j) {
        int c = j * 8 + 2 * t;
        __half* o0 = g_concat + ((size_t)(b * Ss + s0)) * Hh + head * Dd + c;
        __half* o1 = g_concat + ((size_t)(b * Ss + s0 + 8)) * Hh + head * Dd + c;
        *reinterpret_cast<__half2*>(o0) =
            __floats2half2_rn(acc_o[j][0] * inv0, acc_o[j][1] * inv0);
        *reinterpret_cast<__half2*>(o1) =
            __floats2half2_rn(acc_o[j][2] * inv1, acc_o[j][3] * inv1);
    }
}

// ---------------- LayerNorms --------------------------------------------------------
__global__ __launch_bounds__(THREADS) void layernorm1_kernel(
    const float* __restrict__ gw, const float* __restrict__ bw)
{
    int row = blockIdx.x;
    const float4* rp = reinterpret_cast<const float4*>(g_tmp + (size_t)row * Hh);
    float4 v = rp[threadIdx.x];
    float s  = v.x + v.y + v.z + v.w;
    float s2 = v.x * v.x + v.y * v.y + v.z * v.z + v.w * v.w;
    #pragma unroll
    for (int o = 16; o; o >>= 1) {
        s  += __shfl_xor_sync(0xffffffffu, s,  o);
        s2 += __shfl_xor_sync(0xffffffffu, s2, o);
    }
    __shared__ float rs[8], rs2[8];
    int lane = threadIdx.x & 31, wid = threadIdx.x >> 5;
    if (lane == 0) { rs[wid] = s; rs2[wid] = s2; }
    __syncthreads();
    s = 0.f; s2 = 0.f;
    #pragma unroll
    for (int i = 0; i < 8; ++i) { s += rs[i]; s2 += rs2[i]; }
    float mu  = s  * (1.0f / Hh);
    float var = s2 * (1.0f / Hh) - mu * mu;
    float inv = rsqrtf(var + EPSLN);
    float4 g4 = reinterpret_cast<const float4*>(gw)[threadIdx.x];
    float4 b4 = reinterpret_cast<const float4*>(bw)[threadIdx.x];
    float4 o4;
    o4.x = (v.x - mu) * inv * g4.x + b4.x;
    o4.y = (v.y - mu) * inv * g4.y + b4.y;
    o4.z = (v.z - mu) * inv * g4.z + b4.z;
    o4.w = (v.w - mu) * inv * g4.w + b4.w;
    reinterpret_cast<float4*>(g_h1 + (size_t)row * Hh)[threadIdx.x] = o4;
    uint2 hh = make_uint2(h2u(__floats2half2_rn(o4.x, o4.y)),
                          h2u(__floats2half2_rn(o4.z, o4.w)));
    reinterpret_cast<uint2*>(g_h1h + (size_t)row * Hh)[threadIdx.x] = hh;
}

__global__ __launch_bounds__(THREADS) void layernorm2_kernel(
    const float* __restrict__ gw, const float* __restrict__ bw,
    float* __restrict__ out)
{
    int row = blockIdx.x;
    const float4* rp = reinterpret_cast<const float4*>(g_tmp + (size_t)row * Hh);
    float4 v = rp[threadIdx.x];
    float s  = v.x + v.y + v.z + v.w;
    float s2 = v.x * v.x + v.y * v.y + v.z * v.z + v.w * v.w;
    #pragma unroll
    for (int o = 16; o; o >>= 1) {
        s  += __shfl_xor_sync(0xffffffffu, s,  o);
        s2 += __shfl_xor_sync(0xffffffffu, s2, o);
    }
    __shared__ float rs[8], rs2[8];
    int lane = threadIdx.x & 31, wid = threadIdx.x >> 5;
    if (lane == 0) { rs[wid] = s; rs2[wid] = s2; }
    __syncthreads();
    s = 0.f; s2 = 0.f;
    #pragma unroll
    for (int i = 0; i < 8; ++i) { s += rs[i]; s2 += rs2[i]; }
    float mu  = s  * (1.0f / Hh);
    float var = s2 * (1.0f / Hh) - mu * mu;
    float inv = rsqrtf(var + EPSLN);
    float4 g4 = reinterpret_cast<const float4*>(gw)[threadIdx.x];
    float4 b4 = reinterpret_cast<const float4*>(bw)[threadIdx.x];
    float4 o4;
    o4.x = (v.x - mu) * inv * g4.x + b4.x;
    o4.y = (v.y - mu) * inv * g4.y + b4.y;
    o4.z = (v.z - mu) * inv * g4.z + b4.z;
    o4.w = (v.w - mu) * inv * g4.w + b4.w;
    reinterpret_cast<float4*>(out + (size_t)row * Hh)[threadIdx.x] = o4;
}

// ---------------- entry ---------------------------------------------------------------
extern "C" void kernel_launch(void* const* d_in, const int* in_sizes, int n_in,
                              void* d_out, int out_size)
{
    const float* x   = (const float*)d_in[0];
    const float* Wqr = (const float*)d_in[1];
    const float* Wqi = (const float*)d_in[2];
    const float* bqr = (const float*)d_in[3];
    const float* bqi = (const float*)d_in[4];
    const float* Wkr = (const float*)d_in[5];
    const float* Wki = (const float*)d_in[6];
    const float* bkr = (const float*)d_in[7];
    const float* bki = (const float*)d_in[8];
    const float* Wv  = (const float*)d_in[9];
    const float* bvv = (const float*)d_in[10];
    const float* pqr = (const float*)d_in[11];
    const float* pqi = (const float*)d_in[12];
    const float* pkr = (const float*)d_in[13];
    const float* pki = (const float*)d_in[14];
    const float* Wo  = (const float*)d_in[15];
    const float* bo  = (const float*)d_in[16];
    const float* W1  = (const float*)d_in[17];
    const float* b1  = (const float*)d_in[18];
    const float* W2  = (const float*)d_in[19];
    const float* b2  = (const float*)d_in[20];
    const float* g1  = (const float*)d_in[21];
    const float* be1 = (const float*)d_in[22];
    const float* g2  = (const float*)d_in[23];
    const float* be2 = (const float*)d_in[24];
    float* out = (float*)d_out;

    static bool attr_done = false;
    if (!attr_done) {
        cudaFuncSetAttribute(hproj_kernel,
            cudaFuncAttributeMaxDynamicSharedMemorySize, (int)SM_HGEMM);
        cudaFuncSetAttribute(hwo_kernel,
            cudaFuncAttributeMaxDynamicSharedMemorySize, (int)SM_HGEMM);
        cudaFuncSetAttribute(hff1_kernel,
            cudaFuncAttributeMaxDynamicSharedMemorySize, (int)SM_HGEMM);
        cudaFuncSetAttribute(hff2_kernel,
            cudaFuncAttributeMaxDynamicSharedMemorySize, (int)SM_HGEMM);
        cudaFuncSetAttribute(flash_attn_kernel,
            cudaFuncAttributeMaxDynamicSharedMemorySize, (int)SM_FLASH);
        attr_done = true;
    }

    __half* xt  = nullptr; cudaGetSymbolAddress((void**)&xt,  g_xt);
    __half* woh = nullptr; cudaGetSymbolAddress((void**)&woh, g_woh);
    __half* w1h = nullptr; cudaGetSymbolAddress((void**)&w1h, g_w1h);
    __half* w2h = nullptr; cudaGetSymbolAddress((void**)&w2h, g_w2h);

    const int U4 = THREADS * 4;
    int n4x = Bb * Ss * Hh / 4;
    convert_h_kernel<<<(n4x + U4 - 1) / U4, THREADS>>>(
        (const float4*)x, (uint2*)xt, n4x);
    int n4o = Hh * Hh / 4;
    convert_h_kernel<<<(n4o + U4 - 1) / U4, THREADS>>>(
        (const float4*)Wo, (uint2*)woh, n4o);
    int n4f = Hh * FFd / 4;
    convert_h_kernel<<<(n4f + U4 - 1) / U4, THREADS>>>(
        (const float4*)W1, (uint2*)w1h, n4f);
    convert_h_kernel<<<(n4f + U4 - 1) / U4, THREADS>>>(
        (const float4*)W2, (uint2*)w2h, n4f);
    repack_g_kernel<<<(1024 * 5120 / 4) / THREADS, THREADS>>>(
        Wqr, Wqi, Wkr, Wki, Wv);

    hproj_kernel<<<dim3(5120 / 128, (Bb * Ss) / 128), THREADS, SM_HGEMM>>>(
        bqr, bqi, bkr, bki, bvv, pqr, pqi, pkr, pki);
    flash_attn_kernel<<<dim3(Ss / 128, Bb * Nn), THREADS, SM_FLASH>>>();
    hwo_kernel<<<dim3(Hh / 128, (Bb * Ss) / 128), THREADS, SM_HGEMM>>>(bo, x);
    layernorm1_kernel<<<Bb * Ss, THREADS>>>(g1, be1);
    hff1_kernel<<<dim3(FFd / 128, (Bb * Ss) / 128), THREADS, SM_HGEMM>>>(b1);
    hff2_kernel<<<dim3(Hh / 128, (Bb * Ss) / 128), THREADS, SM_HGEMM>>>(b2);
    layernorm2_kernel<<<Bb * Ss, THREADS>>>(g2, be2, out);
}

// round 9
// speedup vs baseline: 7.0958x; 1.0249x over previous
#include <cuda_runtime.h>
#include <cuda_fp16.h>
#include <math.h>
#include <stdint.h>

#define THREADS 256
constexpr int Bb  = 4;
constexpr int Ss  = 1024;
constexpr int Hh  = 1024;
constexpr int Nn  = 16;
constexpr int Dd  = 64;
constexpr int FFd = 4096;
constexpr float SCALE = 0.125f;
constexpr float EPSLN = 1e-5f;

// ---------------- scratch (fp16 operands, fp32 residual path) -------------------
__device__ __half g_wpack[1024 * 5120];     // [K=1024][N=5120] qkv weights
__device__ __half g_xt  [Bb * Ss * Hh];     // [M][K]
__device__ __half g_woh [Hh * Hh];          // Wo as-is [K=H][N=H]
__device__ __half g_w1h [Hh * FFd];         // W1 as-is [K=H][N=FF]
__device__ __half g_w2h [FFd * Hh];         // W2 as-is [K=FF][N=H]
__device__ __half g_q[Bb * Nn * Ss * 128];  // [qr*s2+pos*s | -(qi*s2+pos*s)]
__device__ __half g_k[Bb * Nn * Ss * 128];  // [kr+pos | ki+pos]
__device__ __half g_v[Bb * Nn * Ss * Dd];
__device__ __half g_concat[Bb * Ss * Hh];
__device__ float  g_h1 [Bb * Ss * Hh];
__device__ __half g_h1h[Bb * Ss * Hh];
__device__ float  g_tmp[Bb * Ss * Hh];
__device__ __half g_ff[(size_t)Bb * Ss * FFd];

// ---------------- helpers ---------------------------------------------------------
__device__ __forceinline__ uint32_t smem_u32(const void* p) {
    return (uint32_t)__cvta_generic_to_shared(p);
}
__device__ __forceinline__ void cp16(uint32_t dst, const void* src) {
    asm volatile("cp.async.cg.shared.global [%0], [%1], 16;" :: "r"(dst), "l"(src));
}
__device__ __forceinline__ void cp_commit() {
    asm volatile("cp.async.commit_group;");
}
template<int N> __device__ __forceinline__ void cp_wait() {
    asm volatile("cp.async.wait_group %0;" :: "n"(N));
}
__device__ __forceinline__ void mma16816(float (&c)[4], const uint32_t (&a)[4],
                                         const uint32_t (&b)[2]) {
    asm volatile(
        "mma.sync.aligned.m16n8k16.row.col.f32.f16.f16.f32 "
        "{%0,%1,%2,%3}, {%4,%5,%6,%7}, {%8,%9}, {%0,%1,%2,%3};"
        : "+f"(c[0]), "+f"(c[1]), "+f"(c[2]), "+f"(c[3])
        : "r"(a[0]), "r"(a[1]), "r"(a[2]), "r"(a[3]), "r"(b[0]), "r"(b[1]));
}
__device__ __forceinline__ void ldsm4(uint32_t (&r)[4], uint32_t addr) {
    asm volatile("ldmatrix.sync.aligned.m8n8.x4.shared.b16 {%0,%1,%2,%3}, [%4];"
        : "=r"(r[0]), "=r"(r[1]), "=r"(r[2]), "=r"(r[3]) : "r"(addr));
}
__device__ __forceinline__ void ldsm4t(uint32_t (&r)[4], uint32_t addr) {
    asm volatile("ldmatrix.sync.aligned.m8n8.x4.trans.shared.b16 {%0,%1,%2,%3}, [%4];"
        : "=r"(r[0]), "=r"(r[1]), "=r"(r[2]), "=r"(r[3]) : "r"(addr));
}
__device__ __forceinline__ uint32_t h2u(__half2 h) {
    return *reinterpret_cast<uint32_t*>(&h);
}

// ---------------- fp16 tensor-core GEMM core (B in [K][N] layout) -------------------
constexpr int hLA  = 72;                  // A smem row stride (halves)
constexpr int hLB  = 136;                 // B smem row stride (halves)
constexpr int hASZ = 128 * hLA;
constexpr int hBSZ = 64 * hLB;
constexpr int hBUF = hASZ + hBSZ;
constexpr size_t SM_HGEMM = (size_t)2 * hBUF * sizeof(__half);   // 71680 B

template<int KTOT, typename Epi>
__device__ __forceinline__ void hgemm(
    const __half* __restrict__ A, int lda,
    const __half* __restrict__ B, int ldb,
    int m0, int n0, Epi epi)
{
    extern __shared__ __half hsm[];
    const int tid = threadIdx.x, lane = tid & 31, wid = tid >> 5;
    const int wm = wid >> 2, wn = wid & 3;
    const int lrow = lane & 15, lhi = (lane >> 4) & 1;

    auto load_tile = [&](int buf, int kc) {
        __half* a = hsm + buf * hBUF;
        __half* b = a + hASZ;
        uint32_t ab = smem_u32(a), bb = smem_u32(b);
        #pragma unroll
        for (int u = 0; u < 4; ++u) {
            int idx = tid + u * THREADS;
            int m = idx >> 3, kq = idx & 7;
            cp16(ab + (m * hLA + kq * 8) * 2,
                 A + (size_t)(m0 + m) * lda + kc * 64 + kq * 8);
        }
        #pragma unroll
        for (int u = 0; u < 4; ++u) {
            int idx = tid + u * THREADS;
            int r = idx >> 4, q = idx & 15;
            cp16(bb + (r * hLB + q * 8) * 2,
                 B + (size_t)(kc * 64 + r) * ldb + n0 + q * 8);
        }
    };

    float acc[4][4][4] = {};

    auto compute = [&](int buf) {
        __half* a = hsm + buf * hBUF;
        __half* b = a + hASZ;
        uint32_t ab = smem_u32(a), bb = smem_u32(b);
        #pragma unroll
        for (int ks = 0; ks < 4; ++ks) {
            int kk = ks * 16;
            uint32_t af[4][4];
            #pragma unroll
            for (int i = 0; i < 4; ++i) {
                int row = wm * 64 + i * 16 + lrow;
                ldsm4(af[i], ab + (row * hLA + kk + lhi * 8) * 2);
            }
            #pragma unroll
            for (int p = 0; p < 2; ++p) {
                uint32_t bf[4];
                ldsm4t(bf, bb + ((kk + lrow) * hLB + wn * 32 + p * 16 + lhi * 8) * 2);
                uint32_t b0[2] = { bf[0], bf[1] };
                uint32_t b1[2] = { bf[2], bf[3] };
                #pragma unroll
                for (int i = 0; i < 4; ++i) {
                    mma16816(acc[i][2 * p],     af[i], b0);
                    mma16816(acc[i][2 * p + 1], af[i], b1);
                }
            }
        }
    };

    constexpr int T = KTOT / 64;
    load_tile(0, 0);
    cp_commit();
    for (int i = 0; i < T; ++i) {
        cp_wait<0>();
        __syncthreads();
        if (i + 1 < T) { load_tile((i + 1) & 1, i + 1); cp_commit(); }
        compute(i & 1);
    }

    const int g = lane >> 2, t = lane & 3;
    #pragma unroll
    for (int i = 0; i < 4; ++i) {
        int r0 = m0 + (wm * 4 + i) * 16 + g;
        #pragma unroll
        for (int j = 0; j < 4; ++j) {
            int c0 = n0 + (wn * 4 + j) * 8 + 2 * t;
            epi(r0,     c0, acc[i][j][0], acc[i][j][1]);
            epi(r0 + 8, c0, acc[i][j][2], acc[i][j][3]);
        }
    }
}

// ---------------- pre-conversion kernels --------------------------------------------
// one fused convert: x -> g_xt, Wo -> g_woh, W1 -> g_w1h, W2 -> g_w2h
constexpr int N4_X  = Bb * Ss * Hh / 4;     // 1048576
constexpr int N4_WO = Hh * Hh / 4;          // 262144
constexpr int N4_W1 = Hh * FFd / 4;         // 1048576
constexpr int N4_ALL = N4_X + N4_WO + 2 * N4_W1;   // 3407872

__global__ __launch_bounds__(THREADS) void convert_all_kernel(
    const float4* __restrict__ x,  const float4* __restrict__ Wo,
    const float4* __restrict__ W1, const float4* __restrict__ W2)
{
    int base = blockIdx.x * (THREADS * 4) + threadIdx.x;
    #pragma unroll
    for (int u = 0; u < 4; ++u) {
        int i = base + u * THREADS;
        if (i >= N4_ALL) return;
        const float4* src;
        uint2* dst;
        int j;
        if (i < N4_X) {
            src = x;  dst = (uint2*)g_xt;  j = i;
        } else if (i < N4_X + N4_WO) {
            src = Wo; dst = (uint2*)g_woh; j = i - N4_X;
        } else if (i < N4_X + N4_WO + N4_W1) {
            src = W1; dst = (uint2*)g_w1h; j = i - N4_X - N4_WO;
        } else {
            src = W2; dst = (uint2*)g_w2h; j = i - N4_X - N4_WO - N4_W1;
        }
        float4 v = src[j];
        dst[j] = make_uint2(h2u(__floats2half2_rn(v.x, v.y)),
                            h2u(__floats2half2_rn(v.z, v.w)));
    }
}

// qkv weights gather: 5x [N,H,D] f32 -> g_wpack [K=1024][5120] half
__global__ __launch_bounds__(THREADS) void repack_g_kernel(
    const float* __restrict__ Wqr, const float* __restrict__ Wqi,
    const float* __restrict__ Wkr, const float* __restrict__ Wki,
    const float* __restrict__ Wv)
{
    int idx = blockIdx.x * THREADS + threadIdx.x;
    int col4 = idx % 1280;
    int k    = idx / 1280;
    int c = col4 * 4;
    int p = c >> 10, n = (c >> 6) & 15, d = c & 63;
    const float* W = (p == 0) ? Wqr : (p == 1) ? Wqi : (p == 2) ? Wkr
                    : (p == 3) ? Wki : Wv;
    float4 v = *reinterpret_cast<const float4*>(
        W + (((size_t)n) << 16) + (size_t)k * 64 + d);
    *reinterpret_cast<uint2*>(g_wpack + (size_t)k * 5120 + c) =
        make_uint2(h2u(__floats2half2_rn(v.x, v.y)),
                   h2u(__floats2half2_rn(v.z, v.w)));
}

// ---------------- GEMM kernels -----------------------------------------------------
__global__ __launch_bounds__(THREADS, 2) void hproj_kernel(
    const float* __restrict__ bqr, const float* __restrict__ bqi,
    const float* __restrict__ bkr, const float* __restrict__ bki,
    const float* __restrict__ bvv,
    const float* __restrict__ pqr, const float* __restrict__ pqi,
    const float* __restrict__ pkr, const float* __restrict__ pki)
{
    int m0 = blockIdx.y * 128, n0 = blockIdx.x * 128;
    hgemm<1024>(g_xt, Hh, g_wpack, 5120, m0, n0,
        [&](int row, int col, float v0, float v1) {
            int p = col >> 10, n = (col >> 6) & 15, d = col & 63;
            int bb = row >> 10, s = row & 1023;
            size_t pidx = (((size_t)n << 10) + s) * Dd + d;
            size_t rowoff = (((size_t)(bb * Nn + n)) << 10) + s;
            float x0, x1;
            __half* dst;
            if (p == 0) {
                x0 = ((v0 + bqr[n * Dd + d])     * SCALE + pqr[pidx])     * SCALE;
                x1 = ((v1 + bqr[n * Dd + d + 1]) * SCALE + pqr[pidx + 1]) * SCALE;
                dst = g_q + rowoff * 128 + d;
            } else if (p == 1) {
                x0 = -(((v0 + bqi[n * Dd + d])     * SCALE + pqi[pidx])     * SCALE);
                x1 = -(((v1 + bqi[n * Dd + d + 1]) * SCALE + pqi[pidx + 1]) * SCALE);
                dst = g_q + rowoff * 128 + 64 + d;
            } else if (p == 2) {
                x0 = v0 + bkr[n * Dd + d]     + pkr[pidx];
                x1 = v1 + bkr[n * Dd + d + 1] + pkr[pidx + 1];
                dst = g_k + rowoff * 128 + d;
            } else if (p == 3) {
                x0 = v0 + bki[n * Dd + d]     + pki[pidx];
                x1 = v1 + bki[n * Dd + d + 1] + pki[pidx + 1];
                dst = g_k + rowoff * 128 + 64 + d;
            } else {
                x0 = v0 + bvv[n * Dd + d];
                x1 = v1 + bvv[n * Dd + d + 1];
                dst = g_v + rowoff * Dd + d;
            }
            *reinterpret_cast<__half2*>(dst) = __floats2half2_rn(x0, x1);
        });
}

__global__ __launch_bounds__(THREADS, 2) void hwo_kernel(
    const float* __restrict__ bo, const float* __restrict__ x)
{
    int m0 = blockIdx.y * 128, n0 = blockIdx.x * 128;
    hgemm<1024>(g_concat, Hh, g_woh, Hh, m0, n0,
        [&](int row, int c0, float v0, float v1) {
            size_t o = (size_t)row * Hh + c0;
            g_tmp[o]     = v0 + bo[c0]     + x[o];
            g_tmp[o + 1] = v1 + bo[c0 + 1] + x[o + 1];
        });
}

__global__ __launch_bounds__(THREADS, 2) void hff1_kernel(const float* __restrict__ b1)
{
    int m0 = blockIdx.y * 128, n0 = blockIdx.x * 128;
    hgemm<1024>(g_h1h, Hh, g_w1h, FFd, m0, n0,
        [&](int row, int c0, float v0, float v1) {
            size_t o = (size_t)row * FFd + c0;
            *reinterpret_cast<__half2*>(g_ff + o) = __floats2half2_rn(
                fmaxf(v0 + b1[c0], 0.f), fmaxf(v1 + b1[c0 + 1], 0.f));
        });
}

__global__ __launch_bounds__(THREADS, 2) void hff2_kernel(const float* __restrict__ b2)
{
    int m0 = blockIdx.y * 128, n0 = blockIdx.x * 128;
    hgemm<4096>(g_ff, FFd, g_w2h, Hh, m0, n0,
        [&](int row, int c0, float v0, float v1) {
            size_t o = (size_t)row * Hh + c0;
            g_tmp[o]     = v0 + b2[c0]     + g_h1[o];
            g_tmp[o + 1] = v1 + b2[c0 + 1] + g_h1[o + 1];
        });
}

// ---------------- flash attention (double-buffered KV, P in registers) --------------
// smem (halves): Q [0,17408), KVbuf0 [17408, 44032), KVbuf1 [44032, 70656)
// KV buffer = K 128x136 (17408) + V 128x72 (9216) = 26624 halves
constexpr int fQ0   = 0;
constexpr int fKV0  = 17408;
constexpr int fKVSZ = 26624;
constexpr int fVOFF = 17408;               // V offset within a KV buffer
constexpr size_t SM_FLASH = (size_t)(17408 + 2 * 26624) * sizeof(__half); // 141312 B

__global__ __launch_bounds__(THREADS) void flash_attn_kernel()
{
    extern __shared__ __half hsm[];
    const int tid = threadIdx.x, lane = tid & 31, wid = tid >> 5;
    const int g = lane >> 2, t = lane & 3;
    const int lrow = lane & 15, lhi = (lane >> 4) & 1;
    const int bh = blockIdx.y, b = bh >> 4, head = bh & 15;
    const int m0 = blockIdx.x * 128;

    const __half* Qg = g_q + (size_t)bh * Ss * 128;
    const __half* Kg = g_k + (size_t)bh * Ss * 128;
    const __half* Vg = g_v + (size_t)bh * Ss * Dd;

    const uint32_t sQ = smem_u32(hsm + fQ0);

    #pragma unroll
    for (int u = 0; u < 8; ++u) {
        int idx = tid + u * THREADS;
        int m = idx >> 4, q = idx & 15;
        cp16(sQ + (m * 136 + q * 8) * 2, Qg + (size_t)(m0 + m) * 128 + q * 8);
    }
    cp_commit();

    auto load_kv = [&](int kt, int buf) {
        uint32_t sK = smem_u32(hsm + fKV0 + buf * fKVSZ);
        uint32_t sV = sK + fVOFF * 2;
        const __half* kp = Kg + (size_t)kt * 128 * 128;
        const __half* vp = Vg + (size_t)kt * 128 * Dd;
        #pragma unroll
        for (int u = 0; u < 8; ++u) {
            int idx = tid + u * THREADS;
            int r = idx >> 4, q = idx & 15;
            cp16(sK + (r * 136 + q * 8) * 2, kp + (size_t)r * 128 + q * 8);
        }
        #pragma unroll
        for (int u = 0; u < 4; ++u) {
            int idx = tid + u * THREADS;
            int r = idx >> 3, q = idx & 7;
            cp16(sV + (r * 72 + q * 8) * 2, vp + (size_t)r * Dd + q * 8);
        }
    };
    load_kv(0, 0);
    cp_commit();

    // hoist Q fragments (wait Q group; KV(0) may still be in flight)
    const int mq = wid * 16;
    cp_wait<1>();
    __syncthreads();
    uint32_t qf[8][4];
    #pragma unroll
    for (int ks = 0; ks < 8; ++ks)
        ldsm4(qf[ks], sQ + ((mq + lrow) * 136 + ks * 16 + lhi * 8) * 2);

    float m_run0 = -1e30f, m_run1 = -1e30f;
    float l_run0 = 0.f, l_run1 = 0.f;
    float acc_o[8][4] = {};
    const int mr = wid * 16 + g;

    for (int kt = 0; kt < Ss / 128; ++kt) {
        const int buf = kt & 1;
        cp_wait<0>();          // only KV(kt) outstanding here
        __syncthreads();       // visibility + prev-iter compute done (buffer reuse)
        if (kt + 1 < Ss / 128) { load_kv(kt + 1, buf ^ 1); cp_commit(); }

        const uint32_t sK = smem_u32(hsm + fKV0 + buf * fKVSZ);
        const uint32_t sV = sK + fVOFF * 2;

        // scores: [16 x 128] per warp, K=128 (complex real part, scales prefolded)
        float acc_s[16][4] = {};
        #pragma unroll
        for (int ks = 0; ks < 8; ++ks) {
            #pragma unroll
            for (int p = 0; p < 8; ++p) {
                uint32_t bf[4];
                ldsm4(bf, sK + ((p * 16 + lrow) * 136 + ks * 16 + lhi * 8) * 2);
                uint32_t b0[2] = { bf[0], bf[2] };
                uint32_t b1[2] = { bf[1], bf[3] };
                mma16816(acc_s[2 * p],     qf[ks], b0);
                mma16816(acc_s[2 * p + 1], qf[ks], b1);
            }
        }

        // online softmax (rows mr, mr+8), quad reduction
        float tm0 = -1e30f, tm1 = -1e30f;
        #pragma unroll
        for (int j = 0; j < 16; ++j) {
            tm0 = fmaxf(tm0, fmaxf(acc_s[j][0], acc_s[j][1]));
            tm1 = fmaxf(tm1, fmaxf(acc_s[j][2], acc_s[j][3]));
        }
        #pragma unroll
        for (int o = 1; o <= 2; o <<= 1) {
            tm0 = fmaxf(tm0, __shfl_xor_sync(0xffffffffu, tm0, o));
            tm1 = fmaxf(tm1, __shfl_xor_sync(0xffffffffu, tm1, o));
        }
        float mn0 = fmaxf(m_run0, tm0), mn1 = fmaxf(m_run1, tm1);
        float sc0 = __expf(m_run0 - mn0), sc1 = __expf(m_run1 - mn1);
        m_run0 = mn0; m_run1 = mn1;

        float rs0 = 0.f, rs1 = 0.f;
        #pragma unroll
        for (int j = 0; j < 16; ++j) {
            acc_s[j][0] = __expf(acc_s[j][0] - mn0);
            acc_s[j][1] = __expf(acc_s[j][1] - mn0);
            acc_s[j][2] = __expf(acc_s[j][2] - mn1);
            acc_s[j][3] = __expf(acc_s[j][3] - mn1);
            rs0 += acc_s[j][0] + acc_s[j][1];
            rs1 += acc_s[j][2] + acc_s[j][3];
        }
        #pragma unroll
        for (int o = 1; o <= 2; o <<= 1) {
            rs0 += __shfl_xor_sync(0xffffffffu, rs0, o);
            rs1 += __shfl_xor_sync(0xffffffffu, rs1, o);
        }
        l_run0 = l_run0 * sc0 + rs0;
        l_run1 = l_run1 * sc1 + rs1;
        #pragma unroll
        for (int j = 0; j < 8; ++j) {
            acc_o[j][0] *= sc0; acc_o[j][1] *= sc0;
            acc_o[j][2] *= sc1; acc_o[j][3] *= sc1;
        }

        // pack P into A-fragments in registers
        uint32_t pf[8][4];
        #pragma unroll
        for (int k2 = 0; k2 < 8; ++k2) {
            pf[k2][0] = h2u(__floats2half2_rn(acc_s[2 * k2][0],     acc_s[2 * k2][1]));
            pf[k2][1] = h2u(__floats2half2_rn(acc_s[2 * k2][2],     acc_s[2 * k2][3]));
            pf[k2][2] = h2u(__floats2half2_rn(acc_s[2 * k2 + 1][0], acc_s[2 * k2 + 1][1]));
            pf[k2][3] = h2u(__floats2half2_rn(acc_s[2 * k2 + 1][2], acc_s[2 * k2 + 1][3]));
        }

        // PV: [16 x 128] @ [128 x 64], P from registers
        #pragma unroll
        for (int ks = 0; ks < 8; ++ks) {
            #pragma unroll
            for (int p = 0; p < 4; ++p) {
                uint32_t bf[4];
                ldsm4t(bf, sV + ((ks * 16 + lrow) * 72 + p * 16 + lhi * 8) * 2);
                uint32_t b0[2] = { bf[0], bf[1] };
                uint32_t b1[2] = { bf[2], bf[3] };
                mma16816(acc_o[2 * p],     pf[ks], b0);
                mma16816(acc_o[2 * p + 1], pf[ks], b1);
            }
        }
        // no trailing sync: next iteration's top barrier guards buffer reuse
    }

    float inv0 = 1.0f / l_run0, inv1 = 1.0f / l_run1;
    int s0 = m0 + mr;
    #pragma unroll
    for (int j = 0; j < 8; ++j) {
        int c = j * 8 + 2 * t;
        __half* o0 = g_concat + ((size_t)(b * Ss + s0)) * Hh + head * Dd + c;
        __half* o1 = g_concat + ((size_t)(b * Ss + s0 + 8)) * Hh + head * Dd + c;
        *reinterpret_cast<__half2*>(o0) =
            __floats2half2_rn(acc_o[j][0] * inv0, acc_o[j][1] * inv0);
        *reinterpret_cast<__half2*>(o1) =
            __floats2half2_rn(acc_o[j][2] * inv1, acc_o[j][3] * inv1);
    }
}

// ---------------- LayerNorms --------------------------------------------------------
__global__ __launch_bounds__(THREADS) void layernorm1_kernel(
    const float* __restrict__ gw, const float* __restrict__ bw)
{
    int row = blockIdx.x;
    const float4* rp = reinterpret_cast<const float4*>(g_tmp + (size_t)row * Hh);
    float4 v = rp[threadIdx.x];
    float s  = v.x + v.y + v.z + v.w;
    float s2 = v.x * v.x + v.y * v.y + v.z * v.z + v.w * v.w;
    #pragma unroll
    for (int o = 16; o; o >>= 1) {
        s  += __shfl_xor_sync(0xffffffffu, s,  o);
        s2 += __shfl_xor_sync(0xffffffffu, s2, o);
    }
    __shared__ float rs[8], rs2[8];
    int lane = threadIdx.x & 31, wid = threadIdx.x >> 5;
    if (lane == 0) { rs[wid] = s; rs2[wid] = s2; }
    __syncthreads();
    s = 0.f; s2 = 0.f;
    #pragma unroll
    for (int i = 0; i < 8; ++i) { s += rs[i]; s2 += rs2[i]; }
    float mu  = s  * (1.0f / Hh);
    float var = s2 * (1.0f / Hh) - mu * mu;
    float inv = rsqrtf(var + EPSLN);
    float4 g4 = reinterpret_cast<const float4*>(gw)[threadIdx.x];
    float4 b4 = reinterpret_cast<const float4*>(bw)[threadIdx.x];
    float4 o4;
    o4.x = (v.x - mu) * inv * g4.x + b4.x;
    o4.y = (v.y - mu) * inv * g4.y + b4.y;
    o4.z = (v.z - mu) * inv * g4.z + b4.z;
    o4.w = (v.w - mu) * inv * g4.w + b4.w;
    reinterpret_cast<float4*>(g_h1 + (size_t)row * Hh)[threadIdx.x] = o4;
    uint2 hh = make_uint2(h2u(__floats2half2_rn(o4.x, o4.y)),
                          h2u(__floats2half2_rn(o4.z, o4.w)));
    reinterpret_cast<uint2*>(g_h1h + (size_t)row * Hh)[threadIdx.x] = hh;
}

__global__ __launch_bounds__(THREADS) void layernorm2_kernel(
    const float* __restrict__ gw, const float* __restrict__ bw,
    float* __restrict__ out)
{
    int row = blockIdx.x;
    const float4* rp = reinterpret_cast<const float4*>(g_tmp + (size_t)row * Hh);
    float4 v = rp[threadIdx.x];
    float s  = v.x + v.y + v.z + v.w;
    float s2 = v.x * v.x + v.y * v.y + v.z * v.z + v.w * v.w;
    #pragma unroll
    for (int o = 16; o; o >>= 1) {
        s  += __shfl_xor_sync(0xffffffffu, s,  o);
        s2 += __shfl_xor_sync(0xffffffffu, s2, o);
    }
    __shared__ float rs[8], rs2[8];
    int lane = threadIdx.x & 31, wid = threadIdx.x >> 5;
    if (lane == 0) { rs[wid] = s; rs2[wid] = s2; }
    __syncthreads();
    s = 0.f; s2 = 0.f;
    #pragma unroll
    for (int i = 0; i < 8; ++i) { s += rs[i]; s2 += rs2[i]; }
    float mu  = s  * (1.0f / Hh);
    float var = s2 * (1.0f / Hh) - mu * mu;
    float inv = rsqrtf(var + EPSLN);
    float4 g4 = reinterpret_cast<const float4*>(gw)[threadIdx.x];
    float4 b4 = reinterpret_cast<const float4*>(bw)[threadIdx.x];
    float4 o4;
    o4.x = (v.x - mu) * inv * g4.x + b4.x;
    o4.y = (v.y - mu) * inv * g4.y + b4.y;
    o4.z = (v.z - mu) * inv * g4.z + b4.z;
    o4.w = (v.w - mu) * inv * g4.w + b4.w;
    reinterpret_cast<float4*>(out + (size_t)row * Hh)[threadIdx.x] = o4;
}

// ---------------- entry ---------------------------------------------------------------
extern "C" void kernel_launch(void* const* d_in, const int* in_sizes, int n_in,
                              void* d_out, int out_size)
{
    const float* x   = (const float*)d_in[0];
    const float* Wqr = (const float*)d_in[1];
    const float* Wqi = (const float*)d_in[2];
    const float* bqr = (const float*)d_in[3];
    const float* bqi = (const float*)d_in[4];
    const float* Wkr = (const float*)d_in[5];
    const float* Wki = (const float*)d_in[6];
    const float* bkr = (const float*)d_in[7];
    const float* bki = (const float*)d_in[8];
    const float* Wv  = (const float*)d_in[9];
    const float* bvv = (const float*)d_in[10];
    const float* pqr = (const float*)d_in[11];
    const float* pqi = (const float*)d_in[12];
    const float* pkr = (const float*)d_in[13];
    const float* pki = (const float*)d_in[14];
    const float* Wo  = (const float*)d_in[15];
    const float* bo  = (const float*)d_in[16];
    const float* W1  = (const float*)d_in[17];
    const float* b1  = (const float*)d_in[18];
    const float* W2  = (const float*)d_in[19];
    const float* b2  = (const float*)d_in[20];
    const float* g1  = (const float*)d_in[21];
    const float* be1 = (const float*)d_in[22];
    const float* g2  = (const float*)d_in[23];
    const float* be2 = (const float*)d_in[24];
    float* out = (float*)d_out;

    static bool attr_done = false;
    if (!attr_done) {
        cudaFuncSetAttribute(hproj_kernel,
            cudaFuncAttributeMaxDynamicSharedMemorySize, (int)SM_HGEMM);
        cudaFuncSetAttribute(hwo_kernel,
            cudaFuncAttributeMaxDynamicSharedMemorySize, (int)SM_HGEMM);
        cudaFuncSetAttribute(hff1_kernel,
            cudaFuncAttributeMaxDynamicSharedMemorySize, (int)SM_HGEMM);
        cudaFuncSetAttribute(hff2_kernel,
            cudaFuncAttributeMaxDynamicSharedMemorySize, (int)SM_HGEMM);
        cudaFuncSetAttribute(flash_attn_kernel,
            cudaFuncAttributeMaxDynamicSharedMemorySize, (int)SM_FLASH);
        attr_done = true;
    }

    const int U4 = THREADS * 4;
    convert_all_kernel<<<(N4_ALL + U4 - 1) / U4, THREADS>>>(
        (const float4*)x, (const float4*)Wo, (const float4*)W1, (const float4*)W2);
    repack_g_kernel<<<(1024 * 5120 / 4) / THREADS, THREADS>>>(
        Wqr, Wqi, Wkr, Wki, Wv);

    hproj_kernel<<<dim3(5120 / 128, (Bb * Ss) / 128), THREADS, SM_HGEMM>>>(
        bqr, bqi, bkr, bki, bvv, pqr, pqi, pkr, pki);
    flash_attn_kernel<<<dim3(Ss / 128, Bb * Nn), THREADS, SM_FLASH>>>();
    hwo_kernel<<<dim3(Hh / 128, (Bb * Ss) / 128), THREADS, SM_HGEMM>>>(bo, x);
    layernorm1_kernel<<<Bb * Ss, THREADS>>>(g1, be1);
    hff1_kernel<<<dim3(FFd / 128, (Bb * Ss) / 128), THREADS, SM_HGEMM>>>(b1);
    hff2_kernel<<<dim3(Hh / 128, (Bb * Ss) / 128), THREADS, SM_HGEMM>>>(b2);
    layernorm2_kernel<<<Bb * Ss, THREADS>>>(g2, be2, out);
}

// round 10
// speedup vs baseline: 7.1853x; 1.0126x over previous
#include <cuda_runtime.h>
#include <cuda_fp16.h>
#include <math.h>
#include <stdint.h>

#define THREADS 256
constexpr int Bb  = 4;
constexpr int Ss  = 1024;
constexpr int Hh  = 1024;
constexpr int Nn  = 16;
constexpr int Dd  = 64;
constexpr int FFd = 4096;
constexpr float SCALE = 0.125f;
constexpr float EPSLN = 1e-5f;

// ---------------- scratch (fp16 operands, fp32 residual path) -------------------
__device__ __half g_wpack[1024 * 5120];     // [K=1024][N=5120] qkv weights
__device__ __half g_xt  [Bb * Ss * Hh];     // [M][K]
__device__ __half g_woh [Hh * Hh];          // Wo as-is [K=H][N=H]
__device__ __half g_w1h [Hh * FFd];         // W1 as-is [K=H][N=FF]
__device__ __half g_w2h [FFd * Hh];         // W2 as-is [K=FF][N=H]
__device__ __half g_q[Bb * Nn * Ss * 128];  // [qr*s2+pos*s | -(qi*s2+pos*s)]
__device__ __half g_k[Bb * Nn * Ss * 128];  // [kr+pos | ki+pos]
__device__ __half g_v[Bb * Nn * Ss * Dd];
__device__ __half g_concat[Bb * Ss * Hh];
__device__ float  g_h1 [Bb * Ss * Hh];
__device__ __half g_h1h[Bb * Ss * Hh];
__device__ float  g_tmp[Bb * Ss * Hh];
__device__ __half g_ff[(size_t)Bb * Ss * FFd];

// ---------------- helpers ---------------------------------------------------------
__device__ __forceinline__ uint32_t smem_u32(const void* p) {
    return (uint32_t)__cvta_generic_to_shared(p);
}
__device__ __forceinline__ void cp16(uint32_t dst, const void* src) {
    asm volatile("cp.async.cg.shared.global [%0], [%1], 16;" :: "r"(dst), "l"(src));
}
__device__ __forceinline__ void cp_commit() {
    asm volatile("cp.async.commit_group;");
}
template<int N> __device__ __forceinline__ void cp_wait() {
    asm volatile("cp.async.wait_group %0;" :: "n"(N));
}
__device__ __forceinline__ void mma16816(float (&c)[4], const uint32_t (&a)[4],
                                         const uint32_t (&b)[2]) {
    asm volatile(
        "mma.sync.aligned.m16n8k16.row.col.f32.f16.f16.f32 "
        "{%0,%1,%2,%3}, {%4,%5,%6,%7}, {%8,%9}, {%0,%1,%2,%3};"
        : "+f"(c[0]), "+f"(c[1]), "+f"(c[2]), "+f"(c[3])
        : "r"(a[0]), "r"(a[1]), "r"(a[2]), "r"(a[3]), "r"(b[0]), "r"(b[1]));
}
__device__ __forceinline__ void ldsm4(uint32_t (&r)[4], uint32_t addr) {
    asm volatile("ldmatrix.sync.aligned.m8n8.x4.shared.b16 {%0,%1,%2,%3}, [%4];"
        : "=r"(r[0]), "=r"(r[1]), "=r"(r[2]), "=r"(r[3]) : "r"(addr));
}
__device__ __forceinline__ void ldsm4t(uint32_t (&r)[4], uint32_t addr) {
    asm volatile("ldmatrix.sync.aligned.m8n8.x4.trans.shared.b16 {%0,%1,%2,%3}, [%4];"
        : "=r"(r[0]), "=r"(r[1]), "=r"(r[2]), "=r"(r[3]) : "r"(addr));
}
__device__ __forceinline__ uint32_t h2u(__half2 h) {
    return *reinterpret_cast<uint32_t*>(&h);
}

// ---------------- fp16 tensor-core GEMM core (B in [K][N] layout) -------------------
constexpr int hLA  = 72;
constexpr int hLB  = 136;
constexpr int hASZ = 128 * hLA;
constexpr int hBSZ = 64 * hLB;
constexpr int hBUF = hASZ + hBSZ;
constexpr size_t SM_HGEMM = (size_t)2 * hBUF * sizeof(__half);   // 71680 B

template<int KTOT, typename Epi>
__device__ __forceinline__ void hgemm(
    const __half* __restrict__ A, int lda,
    const __half* __restrict__ B, int ldb,
    int m0, int n0, Epi epi)
{
    extern __shared__ __half hsm[];
    const int tid = threadIdx.x, lane = tid & 31, wid = tid >> 5;
    const int wm = wid >> 2, wn = wid & 3;
    const int lrow = lane & 15, lhi = (lane >> 4) & 1;

    auto load_tile = [&](int buf, int kc) {
        __half* a = hsm + buf * hBUF;
        __half* b = a + hASZ;
        uint32_t ab = smem_u32(a), bb = smem_u32(b);
        #pragma unroll
        for (int u = 0; u < 4; ++u) {
            int idx = tid + u * THREADS;
            int m = idx >> 3, kq = idx & 7;
            cp16(ab + (m * hLA + kq * 8) * 2,
                 A + (size_t)(m0 + m) * lda + kc * 64 + kq * 8);
        }
        #pragma unroll
        for (int u = 0; u < 4; ++u) {
            int idx = tid + u * THREADS;
            int r = idx >> 4, q = idx & 15;
            cp16(bb + (r * hLB + q * 8) * 2,
                 B + (size_t)(kc * 64 + r) * ldb + n0 + q * 8);
        }
    };

    float acc[4][4][4] = {};

    auto compute = [&](int buf) {
        __half* a = hsm + buf * hBUF;
        __half* b = a + hASZ;
        uint32_t ab = smem_u32(a), bb = smem_u32(b);
        #pragma unroll
        for (int ks = 0; ks < 4; ++ks) {
            int kk = ks * 16;
            uint32_t af[4][4];
            #pragma unroll
            for (int i = 0; i < 4; ++i) {
                int row = wm * 64 + i * 16 + lrow;
                ldsm4(af[i], ab + (row * hLA + kk + lhi * 8) * 2);
            }
            #pragma unroll
            for (int p = 0; p < 2; ++p) {
                uint32_t bf[4];
                ldsm4t(bf, bb + ((kk + lrow) * hLB + wn * 32 + p * 16 + lhi * 8) * 2);
                uint32_t b0[2] = { bf[0], bf[1] };
                uint32_t b1[2] = { bf[2], bf[3] };
                #pragma unroll
                for (int i = 0; i < 4; ++i) {
                    mma16816(acc[i][2 * p],     af[i], b0);
                    mma16816(acc[i][2 * p + 1], af[i], b1);
                }
            }
        }
    };

    constexpr int T = KTOT / 64;
    load_tile(0, 0);
    cp_commit();
    for (int i = 0; i < T; ++i) {
        cp_wait<0>();
        __syncthreads();
        if (i + 1 < T) { load_tile((i + 1) & 1, i + 1); cp_commit(); }
        compute(i & 1);
    }

    const int g = lane >> 2, t = lane & 3;
    #pragma unroll
    for (int i = 0; i < 4; ++i) {
        int r0 = m0 + (wm * 4 + i) * 16 + g;
        #pragma unroll
        for (int j = 0; j < 4; ++j) {
            int c0 = n0 + (wn * 4 + j) * 8 + 2 * t;
            epi(r0,     c0, acc[i][j][0], acc[i][j][1]);
            epi(r0 + 8, c0, acc[i][j][2], acc[i][j][3]);
        }
    }
}

// ---------------- pre-conversion kernels --------------------------------------------
constexpr int N4_X  = Bb * Ss * Hh / 4;
constexpr int N4_WO = Hh * Hh / 4;
constexpr int N4_W1 = Hh * FFd / 4;
constexpr int N4_ALL = N4_X + N4_WO + 2 * N4_W1;

__global__ __launch_bounds__(THREADS) void convert_all_kernel(
    const float4* __restrict__ x,  const float4* __restrict__ Wo,
    const float4* __restrict__ W1, const float4* __restrict__ W2)
{
    int base = blockIdx.x * (THREADS * 4) + threadIdx.x;
    #pragma unroll
    for (int u = 0; u < 4; ++u) {
        int i = base + u * THREADS;
        if (i >= N4_ALL) return;
        const float4* src;
        uint2* dst;
        int j;
        if (i < N4_X) {
            src = x;  dst = (uint2*)g_xt;  j = i;
        } else if (i < N4_X + N4_WO) {
            src = Wo; dst = (uint2*)g_woh; j = i - N4_X;
        } else if (i < N4_X + N4_WO + N4_W1) {
            src = W1; dst = (uint2*)g_w1h; j = i - N4_X - N4_WO;
        } else {
            src = W2; dst = (uint2*)g_w2h; j = i - N4_X - N4_WO - N4_W1;
        }
        float4 v = src[j];
        dst[j] = make_uint2(h2u(__floats2half2_rn(v.x, v.y)),
                            h2u(__floats2half2_rn(v.z, v.w)));
    }
}

__global__ __launch_bounds__(THREADS) void repack_g_kernel(
    const float* __restrict__ Wqr, const float* __restrict__ Wqi,
    const float* __restrict__ Wkr, const float* __restrict__ Wki,
    const float* __restrict__ Wv)
{
    int idx = blockIdx.x * THREADS + threadIdx.x;
    int col4 = idx % 1280;
    int k    = idx / 1280;
    int c = col4 * 4;
    int p = c >> 10, n = (c >> 6) & 15, d = c & 63;
    const float* W = (p == 0) ? Wqr : (p == 1) ? Wqi : (p == 2) ? Wkr
                    : (p == 3) ? Wki : Wv;
    float4 v = *reinterpret_cast<const float4*>(
        W + (((size_t)n) << 16) + (size_t)k * 64 + d);
    *reinterpret_cast<uint2*>(g_wpack + (size_t)k * 5120 + c) =
        make_uint2(h2u(__floats2half2_rn(v.x, v.y)),
                   h2u(__floats2half2_rn(v.z, v.w)));
}

// ---------------- GEMM kernels -----------------------------------------------------
__global__ __launch_bounds__(THREADS, 2) void hproj_kernel(
    const float* __restrict__ bqr, const float* __restrict__ bqi,
    const float* __restrict__ bkr, const float* __restrict__ bki,
    const float* __restrict__ bvv,
    const float* __restrict__ pqr, const float* __restrict__ pqi,
    const float* __restrict__ pkr, const float* __restrict__ pki)
{
    int m0 = blockIdx.y * 128, n0 = blockIdx.x * 128;
    hgemm<1024>(g_xt, Hh, g_wpack, 5120, m0, n0,
        [&](int row, int col, float v0, float v1) {
            int p = col >> 10, n = (col >> 6) & 15, d = col & 63;
            int bb = row >> 10, s = row & 1023;
            size_t pidx = (((size_t)n << 10) + s) * Dd + d;
            size_t rowoff = (((size_t)(bb * Nn + n)) << 10) + s;
            float x0, x1;
            __half* dst;
            if (p == 0) {
                x0 = ((v0 + bqr[n * Dd + d])     * SCALE + pqr[pidx])     * SCALE;
                x1 = ((v1 + bqr[n * Dd + d + 1]) * SCALE + pqr[pidx + 1]) * SCALE;
                dst = g_q + rowoff * 128 + d;
            } else if (p == 1) {
                x0 = -(((v0 + bqi[n * Dd + d])     * SCALE + pqi[pidx])     * SCALE);
                x1 = -(((v1 + bqi[n * Dd + d + 1]) * SCALE + pqi[pidx + 1]) * SCALE);
                dst = g_q + rowoff * 128 + 64 + d;
            } else if (p == 2) {
                x0 = v0 + bkr[n * Dd + d]     + pkr[pidx];
                x1 = v1 + bkr[n * Dd + d + 1] + pkr[pidx + 1];
                dst = g_k + rowoff * 128 + d;
            } else if (p == 3) {
                x0 = v0 + bki[n * Dd + d]     + pki[pidx];
                x1 = v1 + bki[n * Dd + d + 1] + pki[pidx + 1];
                dst = g_k + rowoff * 128 + 64 + d;
            } else {
                x0 = v0 + bvv[n * Dd + d];
                x1 = v1 + bvv[n * Dd + d + 1];
                dst = g_v + rowoff * Dd + d;
            }
            *reinterpret_cast<__half2*>(dst) = __floats2half2_rn(x0, x1);
        });
}

__global__ __launch_bounds__(THREADS, 2) void hwo_kernel(
    const float* __restrict__ bo, const float* __restrict__ x)
{
    int m0 = blockIdx.y * 128, n0 = blockIdx.x * 128;
    hgemm<1024>(g_concat, Hh, g_woh, Hh, m0, n0,
        [&](int row, int c0, float v0, float v1) {
            size_t o = (size_t)row * Hh + c0;
            g_tmp[o]     = v0 + bo[c0]     + x[o];
            g_tmp[o + 1] = v1 + bo[c0 + 1] + x[o + 1];
        });
}

__global__ __launch_bounds__(THREADS, 2) void hff1_kernel(const float* __restrict__ b1)
{
    int m0 = blockIdx.y * 128, n0 = blockIdx.x * 128;
    hgemm<1024>(g_h1h, Hh, g_w1h, FFd, m0, n0,
        [&](int row, int c0, float v0, float v1) {
            size_t o = (size_t)row * FFd + c0;
            *reinterpret_cast<__half2*>(g_ff + o) = __floats2half2_rn(
                fmaxf(v0 + b1[c0], 0.f), fmaxf(v1 + b1[c0 + 1], 0.f));
        });
}

__global__ __launch_bounds__(THREADS, 2) void hff2_kernel(const float* __restrict__ b2)
{
    int m0 = blockIdx.y * 128, n0 = blockIdx.x * 128;
    hgemm<4096>(g_ff, FFd, g_w2h, Hh, m0, n0,
        [&](int row, int c0, float v0, float v1) {
            size_t o = (size_t)row * Hh + c0;
            g_tmp[o]     = v0 + b2[c0]     + g_h1[o];
            g_tmp[o + 1] = v1 + b2[c0 + 1] + g_h1[o + 1];
        });
}

// ---------------- flash attention (KV tile 64, 2 CTAs/SM) ---------------------------
// smem (halves): Q [0,17408), KVbuf0 [17408,30720), KVbuf1 [30720,44032)
// KV buffer = K 64x136 (8704) + V 64x72 (4608) = 13312 halves
constexpr int fQ0   = 0;
constexpr int fKV0  = 17408;
constexpr int fKVSZ = 13312;
constexpr int fVOFF = 8704;                // V offset within a KV buffer (halves)
constexpr size_t SM_FLASH = (size_t)(17408 + 2 * 13312) * sizeof(__half); // 88064 B

__global__ __launch_bounds__(THREADS, 2) void flash_attn_kernel()
{
    extern __shared__ __half hsm[];
    const int tid = threadIdx.x, lane = tid & 31, wid = tid >> 5;
    const int g = lane >> 2, t = lane & 3;
    const int lrow = lane & 15, lhi = (lane >> 4) & 1;
    const int bh = blockIdx.y, b = bh >> 4, head = bh & 15;
    const int m0 = blockIdx.x * 128;

    const __half* Qg = g_q + (size_t)bh * Ss * 128;
    const __half* Kg = g_k + (size_t)bh * Ss * 128;
    const __half* Vg = g_v + (size_t)bh * Ss * Dd;

    const uint32_t sQ = smem_u32(hsm + fQ0);

    #pragma unroll
    for (int u = 0; u < 8; ++u) {
        int idx = tid + u * THREADS;
        int m = idx >> 4, q = idx & 15;
        cp16(sQ + (m * 136 + q * 8) * 2, Qg + (size_t)(m0 + m) * 128 + q * 8);
    }

    auto load_kv = [&](int kt, int buf) {
        uint32_t sK = smem_u32(hsm + fKV0 + buf * fKVSZ);
        uint32_t sV = sK + fVOFF * 2;
        const __half* kp = Kg + (size_t)kt * 64 * 128;
        const __half* vp = Vg + (size_t)kt * 64 * Dd;
        #pragma unroll
        for (int u = 0; u < 4; ++u) {
            int idx = tid + u * THREADS;
            int r = idx >> 4, q = idx & 15;
            cp16(sK + (r * 136 + q * 8) * 2, kp + (size_t)r * 128 + q * 8);
        }
        #pragma unroll
        for (int u = 0; u < 2; ++u) {
            int idx = tid + u * THREADS;
            int r = idx >> 3, q = idx & 7;
            cp16(sV + (r * 72 + q * 8) * 2, vp + (size_t)r * Dd + q * 8);
        }
    };
    load_kv(0, 0);
    cp_commit();        // group contains Q + KV(0)

    float m_run0 = -1e30f, m_run1 = -1e30f;
    float l_run0 = 0.f, l_run1 = 0.f;
    float acc_o[8][4] = {};
    const int mr = wid * 16 + g;
    const int mq = wid * 16;

    constexpr int NT = Ss / 64;   // 16 tiles
    for (int kt = 0; kt < NT; ++kt) {
        const int buf = kt & 1;
        cp_wait<0>();
        __syncthreads();          // data visible + prev compute done (buffer reuse)
        if (kt + 1 < NT) { load_kv(kt + 1, buf ^ 1); cp_commit(); }

        const uint32_t sK = smem_u32(hsm + fKV0 + buf * fKVSZ);
        const uint32_t sV = sK + fVOFF * 2;

        // scores: [16 x 64] per warp, K=128 (complex real part, scales prefolded)
        float acc_s[8][4] = {};
        #pragma unroll
        for (int ks = 0; ks < 8; ++ks) {
            uint32_t qf[4];
            ldsm4(qf, sQ + ((mq + lrow) * 136 + ks * 16 + lhi * 8) * 2);
            #pragma unroll
            for (int p = 0; p < 4; ++p) {
                uint32_t bf[4];
                ldsm4(bf, sK + ((p * 16 + lrow) * 136 + ks * 16 + lhi * 8) * 2);
                uint32_t b0[2] = { bf[0], bf[2] };
                uint32_t b1[2] = { bf[1], bf[3] };
                mma16816(acc_s[2 * p],     qf, b0);
                mma16816(acc_s[2 * p + 1], qf, b1);
            }
        }

        // online softmax (rows mr, mr+8), quad reduction
        float tm0 = -1e30f, tm1 = -1e30f;
        #pragma unroll
        for (int j = 0; j < 8; ++j) {
            tm0 = fmaxf(tm0, fmaxf(acc_s[j][0], acc_s[j][1]));
            tm1 = fmaxf(tm1, fmaxf(acc_s[j][2], acc_s[j][3]));
        }
        #pragma unroll
        for (int o = 1; o <= 2; o <<= 1) {
            tm0 = fmaxf(tm0, __shfl_xor_sync(0xffffffffu, tm0, o));
            tm1 = fmaxf(tm1, __shfl_xor_sync(0xffffffffu, tm1, o));
        }
        float mn0 = fmaxf(m_run0, tm0), mn1 = fmaxf(m_run1, tm1);
        float sc0 = __expf(m_run0 - mn0), sc1 = __expf(m_run1 - mn1);
        m_run0 = mn0; m_run1 = mn1;

        float rs0 = 0.f, rs1 = 0.f;
        #pragma unroll
        for (int j = 0; j < 8; ++j) {
            acc_s[j][0] = __expf(acc_s[j][0] - mn0);
            acc_s[j][1] = __expf(acc_s[j][1] - mn0);
            acc_s[j][2] = __expf(acc_s[j][2] - mn1);
            acc_s[j][3] = __expf(acc_s[j][3] - mn1);
            rs0 += acc_s[j][0] + acc_s[j][1];
            rs1 += acc_s[j][2] + acc_s[j][3];
        }
        #pragma unroll
        for (int o = 1; o <= 2; o <<= 1) {
            rs0 += __shfl_xor_sync(0xffffffffu, rs0, o);
            rs1 += __shfl_xor_sync(0xffffffffu, rs1, o);
        }
        l_run0 = l_run0 * sc0 + rs0;
        l_run1 = l_run1 * sc1 + rs1;
        #pragma unroll
        for (int j = 0; j < 8; ++j) {
            acc_o[j][0] *= sc0; acc_o[j][1] *= sc0;
            acc_o[j][2] *= sc1; acc_o[j][3] *= sc1;
        }

        // pack P into A-fragments (scores C-frag layout == PV A-frag layout)
        uint32_t pf[4][4];
        #pragma unroll
        for (int k2 = 0; k2 < 4; ++k2) {
            pf[k2][0] = h2u(__floats2half2_rn(acc_s[2 * k2][0],     acc_s[2 * k2][1]));
            pf[k2][1] = h2u(__floats2half2_rn(acc_s[2 * k2][2],     acc_s[2 * k2][3]));
            pf[k2][2] = h2u(__floats2half2_rn(acc_s[2 * k2 + 1][0], acc_s[2 * k2 + 1][1]));
            pf[k2][3] = h2u(__floats2half2_rn(acc_s[2 * k2 + 1][2], acc_s[2 * k2 + 1][3]));
        }

        // PV: [16 x 64] @ [64 x 64], P from registers
        #pragma unroll
        for (int ks = 0; ks < 4; ++ks) {
            #pragma unroll
            for (int p = 0; p < 4; ++p) {
                uint32_t bf[4];
                ldsm4t(bf, sV + ((ks * 16 + lrow) * 72 + p * 16 + lhi * 8) * 2);
                uint32_t b0[2] = { bf[0], bf[1] };
                uint32_t b1[2] = { bf[2], bf[3] };
                mma16816(acc_o[2 * p],     pf[ks], b0);
                mma16816(acc_o[2 * p + 1], pf[ks], b1);
            }
        }
        // next iteration's top barrier guards buffer reuse
    }

    float inv0 = 1.0f / l_run0, inv1 = 1.0f / l_run1;
    int s0 = m0 + mr;
    #pragma unroll
    for (int j = 0; j < 8; ++j) {
        int c = j * 8 + 2 * t;
        __half* o0 = g_concat + ((size_t)(b * Ss + s0)) * Hh + head * Dd + c;
        __half* o1 = g_concat + ((size_t)(b * Ss + s0 + 8)) * Hh + head * Dd + c;
        *reinterpret_cast<__half2*>(o0) =
            __floats2half2_rn(acc_o[j][0] * inv0, acc_o[j][1] * inv0);
        *reinterpret_cast<__half2*>(o1) =
            __floats2half2_rn(acc_o[j][2] * inv1, acc_o[j][3] * inv1);
    }
}

// ---------------- LayerNorms --------------------------------------------------------
__global__ __launch_bounds__(THREADS) void layernorm1_kernel(
    const float* __restrict__ gw, const float* __restrict__ bw)
{
    int row = blockIdx.x;
    const float4* rp = reinterpret_cast<const float4*>(g_tmp + (size_t)row * Hh);
    float4 v = rp[threadIdx.x];
    float s  = v.x + v.y + v.z + v.w;
    float s2 = v.x * v.x + v.y * v.y + v.z * v.z + v.w * v.w;
    #pragma unroll
    for (int o = 16; o; o >>= 1) {
        s  += __shfl_xor_sync(0xffffffffu, s,  o);
        s2 += __shfl_xor_sync(0xffffffffu, s2, o);
    }
    __shared__ float rs[8], rs2[8];
    int lane = threadIdx.x & 31, wid = threadIdx.x >> 5;
    if (lane == 0) { rs[wid] = s; rs2[wid] = s2; }
    __syncthreads();
    s = 0.f; s2 = 0.f;
    #pragma unroll
    for (int i = 0; i < 8; ++i) { s += rs[i]; s2 += rs2[i]; }
    float mu  = s  * (1.0f / Hh);
    float var = s2 * (1.0f / Hh) - mu * mu;
    float inv = rsqrtf(var + EPSLN);
    float4 g4 = reinterpret_cast<const float4*>(gw)[threadIdx.x];
    float4 b4 = reinterpret_cast<const float4*>(bw)[threadIdx.x];
    float4 o4;
    o4.x = (v.x - mu) * inv * g4.x + b4.x;
    o4.y = (v.y - mu) * inv * g4.y + b4.y;
    o4.z = (v.z - mu) * inv * g4.z + b4.z;
    o4.w = (v.w - mu) * inv * g4.w + b4.w;
    reinterpret_cast<float4*>(g_h1 + (size_t)row * Hh)[threadIdx.x] = o4;
    uint2 hh = make_uint2(h2u(__floats2half2_rn(o4.x, o4.y)),
                          h2u(__floats2half2_rn(o4.z, o4.w)));
    reinterpret_cast<uint2*>(g_h1h + (size_t)row * Hh)[threadIdx.x] = hh;
}

__global__ __launch_bounds__(THREADS) void layernorm2_kernel(
    const float* __restrict__ gw, const float* __restrict__ bw,
    float* __restrict__ out)
{
    int row = blockIdx.x;
    const float4* rp = reinterpret_cast<const float4*>(g_tmp + (size_t)row * Hh);
    float4 v = rp[threadIdx.x];
    float s  = v.x + v.y + v.z + v.w;
    float s2 = v.x * v.x + v.y * v.y + v.z * v.z + v.w * v.w;
    #pragma unroll
    for (int o = 16; o; o >>= 1) {
        s  += __shfl_xor_sync(0xffffffffu, s,  o);
        s2 += __shfl_xor_sync(0xffffffffu, s2, o);
    }
    __shared__ float rs[8], rs2[8];
    int lane = threadIdx.x & 31, wid = threadIdx.x >> 5;
    if (lane == 0) { rs[wid] = s; rs2[wid] = s2; }
    __syncthreads();
    s = 0.f; s2 = 0.f;
    #pragma unroll
    for (int i = 0; i < 8; ++i) { s += rs[i]; s2 += rs2[i]; }
    float mu  = s  * (1.0f / Hh);
    float var = s2 * (1.0f / Hh) - mu * mu;
    float inv = rsqrtf(var + EPSLN);
    float4 g4 = reinterpret_cast<const float4*>(gw)[threadIdx.x];
    float4 b4 = reinterpret_cast<const float4*>(bw)[threadIdx.x];
    float4 o4;
    o4.x = (v.x - mu) * inv * g4.x + b4.x;
    o4.y = (v.y - mu) * inv * g4.y + b4.y;
    o4.z = (v.z - mu) * inv * g4.z + b4.z;
    o4.w = (v.w - mu) * inv * g4.w + b4.w;
    reinterpret_cast<float4*>(out + (size_t)row * Hh)[threadIdx.x] = o4;
}

// ---------------- entry ---------------------------------------------------------------
extern "C" void kernel_launch(void* const* d_in, const int* in_sizes, int n_in,
                              void* d_out, int out_size)
{
    const float* x   = (const float*)d_in[0];
    const float* Wqr = (const float*)d_in[1];
    const float* Wqi = (const float*)d_in[2];
    const float* bqr = (const float*)d_in[3];
    const float* bqi = (const float*)d_in[4];
    const float* Wkr = (const float*)d_in[5];
    const float* Wki = (const float*)d_in[6];
    const float* bkr = (const float*)d_in[7];
    const float* bki = (const float*)d_in[8];
    const float* Wv  = (const float*)d_in[9];
    const float* bvv = (const float*)d_in[10];
    const float* pqr = (const float*)d_in[11];
    const float* pqi = (const float*)d_in[12];
    const float* pkr = (const float*)d_in[13];
    const float* pki = (const float*)d_in[14];
    const float* Wo  = (const float*)d_in[15];
    const float* bo  = (const float*)d_in[16];
    const float* W1  = (const float*)d_in[17];
    const float* b1  = (const float*)d_in[18];
    const float* W2  = (const float*)d_in[19];
    const float* b2  = (const float*)d_in[20];
    const float* g1  = (const float*)d_in[21];
    const float* be1 = (const float*)d_in[22];
    const float* g2  = (const float*)d_in[23];
    const float* be2 = (const float*)d_in[24];
    float* out = (float*)d_out;

    static bool attr_done = false;
    if (!attr_done) {
        cudaFuncSetAttribute(hproj_kernel,
            cudaFuncAttributeMaxDynamicSharedMemorySize, (int)SM_HGEMM);
        cudaFuncSetAttribute(hwo_kernel,
            cudaFuncAttributeMaxDynamicSharedMemorySize, (int)SM_HGEMM);
        cudaFuncSetAttribute(hff1_kernel,
            cudaFuncAttributeMaxDynamicSharedMemorySize, (int)SM_HGEMM);
        cudaFuncSetAttribute(hff2_kernel,
            cudaFuncAttributeMaxDynamicSharedMemorySize, (int)SM_HGEMM);
        cudaFuncSetAttribute(flash_attn_kernel,
            cudaFuncAttributeMaxDynamicSharedMemorySize, (int)SM_FLASH);
        attr_done = true;
    }

    const int U4 = THREADS * 4;
    convert_all_kernel<<<(N4_ALL + U4 - 1) / U4, THREADS>>>(
        (const float4*)x, (const float4*)Wo, (const float4*)W1, (const float4*)W2);
    repack_g_kernel<<<(1024 * 5120 / 4) / THREADS, THREADS>>>(
        Wqr, Wqi, Wkr, Wki, Wv);

    hproj_kernel<<<dim3(5120 / 128, (Bb * Ss) / 128), THREADS, SM_HGEMM>>>(
        bqr, bqi, bkr, bki, bvv, pqr, pqi, pkr, pki);
    flash_attn_kernel<<<dim3(Ss / 128, Bb * Nn), THREADS, SM_FLASH>>>();
    hwo_kernel<<<dim3(Hh / 128, (Bb * Ss) / 128), THREADS, SM_HGEMM>>>(bo, x);
    layernorm1_kernel<<<Bb * Ss, THREADS>>>(g1, be1);
    hff1_kernel<<<dim3(FFd / 128, (Bb * Ss) / 128), THREADS, SM_HGEMM>>>(b1);
    hff2_kernel<<<dim3(Hh / 128, (Bb * Ss) / 128), THREADS, SM_HGEMM>>>(b2);
    layernorm2_kernel<<<Bb * Ss, THREADS>>>(g2, be2, out);
}

// round 11
// speedup vs baseline: 7.3483x; 1.0227x over previous
#include <cuda_runtime.h>
#include <cuda_fp16.h>
#include <math.h>
#include <stdint.h>

#define THREADS 256
constexpr int Bb  = 4;
constexpr int Ss  = 1024;
constexpr int Hh  = 1024;
constexpr int Nn  = 16;
constexpr int Dd  = 64;
constexpr int FFd = 4096;
constexpr float SCALE = 0.125f;
constexpr float LOG2E = 1.4426950408889634f;
constexpr float EPSLN = 1e-5f;

// ---------------- scratch (fp16 operands, fp32 residual path) -------------------
__device__ __half g_wpack[1024 * 5120];     // [K=1024][N=5120] qkv weights
__device__ __half g_xt  [Bb * Ss * Hh];     // [M][K]
__device__ __half g_woh [Hh * Hh];          // Wo as-is [K=H][N=H]
__device__ __half g_w1h [Hh * FFd];         // W1 as-is [K=H][N=FF]
__device__ __half g_w2h [FFd * Hh];         // W2 as-is [K=FF][N=H]
__device__ __half g_q[Bb * Nn * Ss * 128];  // log2e-scaled [qr | -qi] concat
__device__ __half g_k[Bb * Nn * Ss * 128];  // [kr+pos | ki+pos]
__device__ __half g_v[Bb * Nn * Ss * Dd];
__device__ __half g_concat[Bb * Ss * Hh];
__device__ __half g_h1h[Bb * Ss * Hh];
__device__ float  g_tmp[Bb * Ss * Hh];
__device__ __half g_ff[(size_t)Bb * Ss * FFd];

// ---------------- helpers ---------------------------------------------------------
__device__ __forceinline__ uint32_t smem_u32(const void* p) {
    return (uint32_t)__cvta_generic_to_shared(p);
}
__device__ __forceinline__ void cp16(uint32_t dst, const void* src) {
    asm volatile("cp.async.cg.shared.global [%0], [%1], 16;" :: "r"(dst), "l"(src));
}
__device__ __forceinline__ void cp_commit() {
    asm volatile("cp.async.commit_group;");
}
template<int N> __device__ __forceinline__ void cp_wait() {
    asm volatile("cp.async.wait_group %0;" :: "n"(N));
}
__device__ __forceinline__ void mma16816(float (&c)[4], const uint32_t (&a)[4],
                                         const uint32_t (&b)[2]) {
    asm volatile(
        "mma.sync.aligned.m16n8k16.row.col.f32.f16.f16.f32 "
        "{%0,%1,%2,%3}, {%4,%5,%6,%7}, {%8,%9}, {%0,%1,%2,%3};"
        : "+f"(c[0]), "+f"(c[1]), "+f"(c[2]), "+f"(c[3])
        : "r"(a[0]), "r"(a[1]), "r"(a[2]), "r"(a[3]), "r"(b[0]), "r"(b[1]));
}
__device__ __forceinline__ void ldsm4(uint32_t (&r)[4], uint32_t addr) {
    asm volatile("ldmatrix.sync.aligned.m8n8.x4.shared.b16 {%0,%1,%2,%3}, [%4];"
        : "=r"(r[0]), "=r"(r[1]), "=r"(r[2]), "=r"(r[3]) : "r"(addr));
}
__device__ __forceinline__ void ldsm4t(uint32_t (&r)[4], uint32_t addr) {
    asm volatile("ldmatrix.sync.aligned.m8n8.x2.trans.shared.b16 {%0,%1}, [%2];"
        : "=r"(r[0]), "=r"(r[1]) : "r"(addr));
}
__device__ __forceinline__ void ldsm4t4(uint32_t (&r)[4], uint32_t addr) {
    asm volatile("ldmatrix.sync.aligned.m8n8.x4.trans.shared.b16 {%0,%1,%2,%3}, [%4];"
        : "=r"(r[0]), "=r"(r[1]), "=r"(r[2]), "=r"(r[3]) : "r"(addr));
}
__device__ __forceinline__ void ldsm2t(uint32_t (&r)[2], uint32_t addr) {
    asm volatile("ldmatrix.sync.aligned.m8n8.x2.trans.shared.b16 {%0,%1}, [%2];"
        : "=r"(r[0]), "=r"(r[1]) : "r"(addr));
}
__device__ __forceinline__ uint32_t h2u(__half2 h) {
    return *reinterpret_cast<uint32_t*>(&h);
}
__device__ __forceinline__ float ex2f(float x) {
    float r;
    asm("ex2.approx.ftz.f32 %0, %1;" : "=f"(r) : "f"(x));
    return r;
}

// ---------------- fp16 tensor-core GEMM core (B in [K][N] layout) -------------------
constexpr int hLA  = 72;
constexpr int hLB  = 136;
constexpr int hASZ = 128 * hLA;
constexpr int hBSZ = 64 * hLB;
constexpr int hBUF = hASZ + hBSZ;
constexpr size_t SM_HGEMM = (size_t)2 * hBUF * sizeof(__half);   // 71680 B

template<int KTOT, typename Epi>
__device__ __forceinline__ void hgemm(
    const __half* __restrict__ A, int lda,
    const __half* __restrict__ B, int ldb,
    int m0, int n0, Epi epi)
{
    extern __shared__ __half hsm[];
    const int tid = threadIdx.x, lane = tid & 31, wid = tid >> 5;
    const int wm = wid >> 2, wn = wid & 3;
    const int lrow = lane & 15, lhi = (lane >> 4) & 1;

    auto load_tile = [&](int buf, int kc) {
        __half* a = hsm + buf * hBUF;
        __half* b = a + hASZ;
        uint32_t ab = smem_u32(a), bb = smem_u32(b);
        #pragma unroll
        for (int u = 0; u < 4; ++u) {
            int idx = tid + u * THREADS;
            int m = idx >> 3, kq = idx & 7;
            cp16(ab + (m * hLA + kq * 8) * 2,
                 A + (size_t)(m0 + m) * lda + kc * 64 + kq * 8);
        }
        #pragma unroll
        for (int u = 0; u < 4; ++u) {
            int idx = tid + u * THREADS;
            int r = idx >> 4, q = idx & 15;
            cp16(bb + (r * hLB + q * 8) * 2,
                 B + (size_t)(kc * 64 + r) * ldb + n0 + q * 8);
        }
    };

    float acc[4][4][4] = {};

    auto compute = [&](int buf) {
        __half* a = hsm + buf * hBUF;
        __half* b = a + hASZ;
        uint32_t ab = smem_u32(a), bb = smem_u32(b);
        #pragma unroll
        for (int ks = 0; ks < 4; ++ks) {
            int kk = ks * 16;
            uint32_t af[4][4];
            #pragma unroll
            for (int i = 0; i < 4; ++i) {
                int row = wm * 64 + i * 16 + lrow;
                ldsm4(af[i], ab + (row * hLA + kk + lhi * 8) * 2);
            }
            #pragma unroll
            for (int p = 0; p < 2; ++p) {
                uint32_t bf[4];
                ldsm4t4(bf, bb + ((kk + lrow) * hLB + wn * 32 + p * 16 + lhi * 8) * 2);
                uint32_t b0[2] = { bf[0], bf[1] };
                uint32_t b1[2] = { bf[2], bf[3] };
                #pragma unroll
                for (int i = 0; i < 4; ++i) {
                    mma16816(acc[i][2 * p],     af[i], b0);
                    mma16816(acc[i][2 * p + 1], af[i], b1);
                }
            }
        }
    };

    constexpr int T = KTOT / 64;
    load_tile(0, 0);
    cp_commit();
    for (int i = 0; i < T; ++i) {
        cp_wait<0>();
        __syncthreads();
        if (i + 1 < T) { load_tile((i + 1) & 1, i + 1); cp_commit(); }
        compute(i & 1);
    }

    const int g = lane >> 2, t = lane & 3;
    #pragma unroll
    for (int i = 0; i < 4; ++i) {
        int r0 = m0 + (wm * 4 + i) * 16 + g;
        #pragma unroll
        for (int j = 0; j < 4; ++j) {
            int c0 = n0 + (wn * 4 + j) * 8 + 2 * t;
            epi(r0,     c0, acc[i][j][0], acc[i][j][1]);
            epi(r0 + 8, c0, acc[i][j][2], acc[i][j][3]);
        }
    }
}

// ---------------- pre-conversion kernels --------------------------------------------
constexpr int N4_X  = Bb * Ss * Hh / 4;
constexpr int N4_WO = Hh * Hh / 4;
constexpr int N4_W1 = Hh * FFd / 4;
constexpr int N4_ALL = N4_X + N4_WO + 2 * N4_W1;

__global__ __launch_bounds__(THREADS) void convert_all_kernel(
    const float4* __restrict__ x,  const float4* __restrict__ Wo,
    const float4* __restrict__ W1, const float4* __restrict__ W2)
{
    int base = blockIdx.x * (THREADS * 4) + threadIdx.x;
    #pragma unroll
    for (int u = 0; u < 4; ++u) {
        int i = base + u * THREADS;
        if (i >= N4_ALL) return;
        const float4* src;
        uint2* dst;
        int j;
        if (i < N4_X) {
            src = x;  dst = (uint2*)g_xt;  j = i;
        } else if (i < N4_X + N4_WO) {
            src = Wo; dst = (uint2*)g_woh; j = i - N4_X;
        } else if (i < N4_X + N4_WO + N4_W1) {
            src = W1; dst = (uint2*)g_w1h; j = i - N4_X - N4_WO;
        } else {
            src = W2; dst = (uint2*)g_w2h; j = i - N4_X - N4_WO - N4_W1;
        }
        float4 v = src[j];
        dst[j] = make_uint2(h2u(__floats2half2_rn(v.x, v.y)),
                            h2u(__floats2half2_rn(v.z, v.w)));
    }
}

__global__ __launch_bounds__(THREADS) void repack_g_kernel(
    const float* __restrict__ Wqr, const float* __restrict__ Wqi,
    const float* __restrict__ Wkr, const float* __restrict__ Wki,
    const float* __restrict__ Wv)
{
    int idx = blockIdx.x * THREADS + threadIdx.x;
    int col4 = idx % 1280;
    int k    = idx / 1280;
    int c = col4 * 4;
    int p = c >> 10, n = (c >> 6) & 15, d = c & 63;
    const float* W = (p == 0) ? Wqr : (p == 1) ? Wqi : (p == 2) ? Wkr
                    : (p == 3) ? Wki : Wv;
    float4 v = *reinterpret_cast<const float4*>(
        W + (((size_t)n) << 16) + (size_t)k * 64 + d);
    *reinterpret_cast<uint2*>(g_wpack + (size_t)k * 5120 + c) =
        make_uint2(h2u(__floats2half2_rn(v.x, v.y)),
                   h2u(__floats2half2_rn(v.z, v.w)));
}

// ---------------- GEMM kernels -----------------------------------------------------
__global__ __launch_bounds__(THREADS, 2) void hproj_kernel(
    const float* __restrict__ bqr, const float* __restrict__ bqi,
    const float* __restrict__ bkr, const float* __restrict__ bki,
    const float* __restrict__ bvv,
    const float* __restrict__ pqr, const float* __restrict__ pqi,
    const float* __restrict__ pkr, const float* __restrict__ pki)
{
    constexpr float QSC = SCALE * LOG2E;     // log2e folded into q prescale
    int m0 = blockIdx.y * 128, n0 = blockIdx.x * 128;
    hgemm<1024>(g_xt, Hh, g_wpack, 5120, m0, n0,
        [&](int row, int col, float v0, float v1) {
            int p = col >> 10, n = (col >> 6) & 15, d = col & 63;
            int bb = row >> 10, s = row & 1023;
            size_t pidx = (((size_t)n << 10) + s) * Dd + d;
            size_t rowoff = (((size_t)(bb * Nn + n)) << 10) + s;
            float x0, x1;
            __half* dst;
            if (p == 0) {
                x0 = ((v0 + bqr[n * Dd + d])     * SCALE + pqr[pidx])     * QSC;
                x1 = ((v1 + bqr[n * Dd + d + 1]) * SCALE + pqr[pidx + 1]) * QSC;
                dst = g_q + rowoff * 128 + d;
            } else if (p == 1) {
                x0 = -(((v0 + bqi[n * Dd + d])     * SCALE + pqi[pidx])     * QSC);
                x1 = -(((v1 + bqi[n * Dd + d + 1]) * SCALE + pqi[pidx + 1]) * QSC);
                dst = g_q + rowoff * 128 + 64 + d;
            } else if (p == 2) {
                x0 = v0 + bkr[n * Dd + d]     + pkr[pidx];
                x1 = v1 + bkr[n * Dd + d + 1] + pkr[pidx + 1];
                dst = g_k + rowoff * 128 + d;
            } else if (p == 3) {
                x0 = v0 + bki[n * Dd + d]     + pki[pidx];
                x1 = v1 + bki[n * Dd + d + 1] + pki[pidx + 1];
                dst = g_k + rowoff * 128 + 64 + d;
            } else {
                x0 = v0 + bvv[n * Dd + d];
                x1 = v1 + bvv[n * Dd + d + 1];
                dst = g_v + rowoff * Dd + d;
            }
            *reinterpret_cast<__half2*>(dst) = __floats2half2_rn(x0, x1);
        });
}

__global__ __launch_bounds__(THREADS, 2) void hwo_kernel(
    const float* __restrict__ bo, const float* __restrict__ x)
{
    int m0 = blockIdx.y * 128, n0 = blockIdx.x * 128;
    hgemm<1024>(g_concat, Hh, g_woh, Hh, m0, n0,
        [&](int row, int c0, float v0, float v1) {
            size_t o = (size_t)row * Hh + c0;
            g_tmp[o]     = v0 + bo[c0]     + x[o];
            g_tmp[o + 1] = v1 + bo[c0 + 1] + x[o + 1];
        });
}

__global__ __launch_bounds__(THREADS, 2) void hff1_kernel(const float* __restrict__ b1)
{
    int m0 = blockIdx.y * 128, n0 = blockIdx.x * 128;
    hgemm<1024>(g_h1h, Hh, g_w1h, FFd, m0, n0,
        [&](int row, int c0, float v0, float v1) {
            size_t o = (size_t)row * FFd + c0;
            *reinterpret_cast<__half2*>(g_ff + o) = __floats2half2_rn(
                fmaxf(v0 + b1[c0], 0.f), fmaxf(v1 + b1[c0 + 1], 0.f));
        });
}

__global__ __launch_bounds__(THREADS, 2) void hff2_kernel(const float* __restrict__ b2)
{
    int m0 = blockIdx.y * 128, n0 = blockIdx.x * 128;
    hgemm<4096>(g_ff, FFd, g_w2h, Hh, m0, n0,
        [&](int row, int c0, float v0, float v1) {
            size_t o = (size_t)row * Hh + c0;
            __half2 hh = *reinterpret_cast<const __half2*>(g_h1h + o);
            g_tmp[o]     = v0 + b2[c0]     + __low2float(hh);
            g_tmp[o + 1] = v1 + b2[c0 + 1] + __high2float(hh);
        });
}

// ---------------- flash attention (KV 64, 2 CTA/SM, l via ones-column) --------------
// smem (halves): Q [0,17408), KVbuf0 [17408,30720), KVbuf1 [30720,44032)
// KV buffer = K 64x136 (8704) + V 64x72 (4608). V cols 64..71: [1,0,...,0] pad,
// written once; row sums of P then come out of the PV mma (col 64).
constexpr int fQ0   = 0;
constexpr int fKV0  = 17408;
constexpr int fKVSZ = 13312;
constexpr int fVOFF = 8704;
constexpr size_t SM_FLASH = (size_t)(17408 + 2 * 13312) * sizeof(__half); // 88064 B

__global__ __launch_bounds__(THREADS, 2) void flash_attn_kernel()
{
    extern __shared__ __half hsm[];
    const int tid = threadIdx.x, lane = tid & 31, wid = tid >> 5;
    const int g = lane >> 2, t = lane & 3;
    const int lrow = lane & 15, lhi = (lane >> 4) & 1;
    const int bh = blockIdx.y, b = bh >> 4, head = bh & 15;
    const int m0 = blockIdx.x * 128;

    const __half* Qg = g_q + (size_t)bh * Ss * 128;
    const __half* Kg = g_k + (size_t)bh * Ss * 128;
    const __half* Vg = g_v + (size_t)bh * Ss * Dd;

    const uint32_t sQ = smem_u32(hsm + fQ0);

    #pragma unroll
    for (int u = 0; u < 8; ++u) {
        int idx = tid + u * THREADS;
        int m = idx >> 4, q = idx & 15;
        cp16(sQ + (m * 136 + q * 8) * 2, Qg + (size_t)(m0 + m) * 128 + q * 8);
    }

    // init V pad columns (col 64 = 1.0, cols 65..71 = 0) for both buffers
    if (tid < 128) {
        int buf = tid >> 6, r = tid & 63;
        uint4* pad = reinterpret_cast<uint4*>(
            hsm + fKV0 + buf * fKVSZ + fVOFF + r * 72 + 64);
        *pad = make_uint4(0x00003C00u, 0u, 0u, 0u);
    }

    auto load_kv = [&](int kt, int buf) {
        uint32_t sK = smem_u32(hsm + fKV0 + buf * fKVSZ);
        uint32_t sV = sK + fVOFF * 2;
        const __half* kp = Kg + (size_t)kt * 64 * 128;
        const __half* vp = Vg + (size_t)kt * 64 * Dd;
        #pragma unroll
        for (int u = 0; u < 4; ++u) {
            int idx = tid + u * THREADS;
            int r = idx >> 4, q = idx & 15;
            cp16(sK + (r * 136 + q * 8) * 2, kp + (size_t)r * 128 + q * 8);
        }
        #pragma unroll
        for (int u = 0; u < 2; ++u) {
            int idx = tid + u * THREADS;
            int r = idx >> 3, q = idx & 7;
            cp16(sV + (r * 72 + q * 8) * 2, vp + (size_t)r * Dd + q * 8);
        }
    };
    load_kv(0, 0);
    cp_commit();

    float m_run0 = -1e30f, m_run1 = -1e30f;
    float acc_o[8][4] = {};
    float acc_l[4] = {};
    const int mr = wid * 16 + g;
    const int mq = wid * 16;

    constexpr int NT = Ss / 64;
    for (int kt = 0; kt < NT; ++kt) {
        const int buf = kt & 1;
        cp_wait<0>();
        __syncthreads();
        if (kt + 1 < NT) { load_kv(kt + 1, buf ^ 1); cp_commit(); }

        const uint32_t sK = smem_u32(hsm + fKV0 + buf * fKVSZ);
        const uint32_t sV = sK + fVOFF * 2;

        // scores: [16 x 64] per warp, K=128 (log2-domain, scales prefolded)
        float acc_s[8][4] = {};
        #pragma unroll
        for (int ks = 0; ks < 8; ++ks) {
            uint32_t qf[4];
            ldsm4(qf, sQ + ((mq + lrow) * 136 + ks * 16 + lhi * 8) * 2);
            #pragma unroll
            for (int p = 0; p < 4; ++p) {
                uint32_t bf[4];
                ldsm4(bf, sK + ((p * 16 + lrow) * 136 + ks * 16 + lhi * 8) * 2);
                uint32_t b0[2] = { bf[0], bf[2] };
                uint32_t b1[2] = { bf[1], bf[3] };
                mma16816(acc_s[2 * p],     qf, b0);
                mma16816(acc_s[2 * p + 1], qf, b1);
            }
        }

        // online softmax (base-2). rows mr, mr+8; quad reduction for max only.
        float tm0 = -1e30f, tm1 = -1e30f;
        #pragma unroll
        for (int j = 0; j < 8; ++j) {
            tm0 = fmaxf(tm0, fmaxf(acc_s[j][0], acc_s[j][1]));
            tm1 = fmaxf(tm1, fmaxf(acc_s[j][2], acc_s[j][3]));
        }
        #pragma unroll
        for (int o = 1; o <= 2; o <<= 1) {
            tm0 = fmaxf(tm0, __shfl_xor_sync(0xffffffffu, tm0, o));
            tm1 = fmaxf(tm1, __shfl_xor_sync(0xffffffffu, tm1, o));
        }
        float mn0 = fmaxf(m_run0, tm0), mn1 = fmaxf(m_run1, tm1);
        float sc0 = ex2f(m_run0 - mn0), sc1 = ex2f(m_run1 - mn1);
        m_run0 = mn0; m_run1 = mn1;

        #pragma unroll
        for (int j = 0; j < 8; ++j) {
            acc_s[j][0] = ex2f(acc_s[j][0] - mn0);
            acc_s[j][1] = ex2f(acc_s[j][1] - mn0);
            acc_s[j][2] = ex2f(acc_s[j][2] - mn1);
            acc_s[j][3] = ex2f(acc_s[j][3] - mn1);
        }
        #pragma unroll
        for (int j = 0; j < 8; ++j) {
            acc_o[j][0] *= sc0; acc_o[j][1] *= sc0;
            acc_o[j][2] *= sc1; acc_o[j][3] *= sc1;
        }
        acc_l[0] *= sc0; acc_l[1] *= sc0;
        acc_l[2] *= sc1; acc_l[3] *= sc1;

        // pack P into A-fragments (scores C-frag layout == PV A-frag layout)
        uint32_t pf[4][4];
        #pragma unroll
        for (int k2 = 0; k2 < 4; ++k2) {
            pf[k2][0] = h2u(__floats2half2_rn(acc_s[2 * k2][0],     acc_s[2 * k2][1]));
            pf[k2][1] = h2u(__floats2half2_rn(acc_s[2 * k2][2],     acc_s[2 * k2][3]));
            pf[k2][2] = h2u(__floats2half2_rn(acc_s[2 * k2 + 1][0], acc_s[2 * k2 + 1][1]));
            pf[k2][3] = h2u(__floats2half2_rn(acc_s[2 * k2 + 1][2], acc_s[2 * k2 + 1][3]));
        }

        // PV: [16 x 64] @ [64 x 64] + l from ones-column (col 64)
        #pragma unroll
        for (int ks = 0; ks < 4; ++ks) {
            #pragma unroll
            for (int p = 0; p < 4; ++p) {
                uint32_t bf[4];
                ldsm4t4(bf, sV + ((ks * 16 + lrow) * 72 + p * 16 + lhi * 8) * 2);
                uint32_t b0[2] = { bf[0], bf[1] };
                uint32_t b1[2] = { bf[2], bf[3] };
                mma16816(acc_o[2 * p],     pf[ks], b0);
                mma16816(acc_o[2 * p + 1], pf[ks], b1);
            }
            uint32_t bl[2];
            ldsm2t(bl, sV + ((ks * 16 + lrow) * 72 + 64) * 2);
            mma16816(acc_l, pf[ks], bl);
        }
    }

    // l lives at col 64 -> quad thread t=0; broadcast within quad
    float l0 = __shfl_sync(0xffffffffu, acc_l[0], lane & ~3);
    float l1 = __shfl_sync(0xffffffffu, acc_l[2], lane & ~3);
    float inv0 = 1.0f / l0, inv1 = 1.0f / l1;
    int s0 = m0 + mr;
    #pragma unroll
    for (int j = 0; j < 8; ++j) {
        int c = j * 8 + 2 * t;
        __half* o0 = g_concat + ((size_t)(b * Ss + s0)) * Hh + head * Dd + c;
        __half* o1 = g_concat + ((size_t)(b * Ss + s0 + 8)) * Hh + head * Dd + c;
        *reinterpret_cast<__half2*>(o0) =
            __floats2half2_rn(acc_o[j][0] * inv0, acc_o[j][1] * inv0);
        *reinterpret_cast<__half2*>(o1) =
            __floats2half2_rn(acc_o[j][2] * inv1, acc_o[j][3] * inv1);
    }
}

// ---------------- LayerNorms --------------------------------------------------------
__global__ __launch_bounds__(THREADS) void layernorm1_kernel(
    const float* __restrict__ gw, const float* __restrict__ bw)
{
    int row = blockIdx.x;
    const float4* rp = reinterpret_cast<const float4*>(g_tmp + (size_t)row * Hh);
    float4 v = rp[threadIdx.x];
    float s  = v.x + v.y + v.z + v.w;
    float s2 = v.x * v.x + v.y * v.y + v.z * v.z + v.w * v.w;
    #pragma unroll
    for (int o = 16; o; o >>= 1) {
        s  += __shfl_xor_sync(0xffffffffu, s,  o);
        s2 += __shfl_xor_sync(0xffffffffu, s2, o);
    }
    __shared__ float rs[8], rs2[8];
    int lane = threadIdx.x & 31, wid = threadIdx.x >> 5;
    if (lane == 0) { rs[wid] = s; rs2[wid] = s2; }
    __syncthreads();
    s = 0.f; s2 = 0.f;
    #pragma unroll
    for (int i = 0; i < 8; ++i) { s += rs[i]; s2 += rs2[i]; }
    float mu  = s  * (1.0f / Hh);
    float var = s2 * (1.0f / Hh) - mu * mu;
    float inv = rsqrtf(var + EPSLN);
    float4 g4 = reinterpret_cast<const float4*>(gw)[threadIdx.x];
    float4 b4 = reinterpret_cast<const float4*>(bw)[threadIdx.x];
    float4 o4;
    o4.x = (v.x - mu) * inv * g4.x + b4.x;
    o4.y = (v.y - mu) * inv * g4.y + b4.y;
    o4.z = (v.z - mu) * inv * g4.z + b4.z;
    o4.w = (v.w - mu) * inv * g4.w + b4.w;
    uint2 hh = make_uint2(h2u(__floats2half2_rn(o4.x, o4.y)),
                          h2u(__floats2half2_rn(o4.z, o4.w)));
    reinterpret_cast<uint2*>(g_h1h + (size_t)row * Hh)[threadIdx.x] = hh;
}

__global__ __launch_bounds__(THREADS) void layernorm2_kernel(
    const float* __restrict__ gw, const float* __restrict__ bw,
    float* __restrict__ out)
{
    int row = blockIdx.x;
    const float4* rp = reinterpret_cast<const float4*>(g_tmp + (size_t)row * Hh);
    float4 v = rp[threadIdx.x];
    float s  = v.x + v.y + v.z + v.w;
    float s2 = v.x * v.x + v.y * v.y + v.z * v.z + v.w * v.w;
    #pragma unroll
    for (int o = 16; o; o >>= 1) {
        s  += __shfl_xor_sync(0xffffffffu, s,  o);
        s2 += __shfl_xor_sync(0xffffffffu, s2, o);
    }
    __shared__ float rs[8], rs2[8];
    int lane = threadIdx.x & 31, wid = threadIdx.x >> 5;
    if (lane == 0) { rs[wid] = s; rs2[wid] = s2; }
    __syncthreads();
    s = 0.f; s2 = 0.f;
    #pragma unroll
    for (int i = 0; i < 8; ++i) { s += rs[i]; s2 += rs2[i]; }
    float mu  = s  * (1.0f / Hh);
    float var = s2 * (1.0f / Hh) - mu * mu;
    float inv = rsqrtf(var + EPSLN);
    float4 g4 = reinterpret_cast<const float4*>(gw)[threadIdx.x];
    float4 b4 = reinterpret_cast<const float4*>(bw)[threadIdx.x];
    float4 o4;
    o4.x = (v.x - mu) * inv * g4.x + b4.x;
    o4.y = (v.y - mu) * inv * g4.y + b4.y;
    o4.z = (v.z - mu) * inv * g4.z + b4.z;
    o4.w = (v.w - mu) * inv * g4.w + b4.w;
    reinterpret_cast<float4*>(out + (size_t)row * Hh)[threadIdx.x] = o4;
}

// ---------------- entry ---------------------------------------------------------------
extern "C" void kernel_launch(void* const* d_in, const int* in_sizes, int n_in,
                              void* d_out, int out_size)
{
    const float* x   = (const float*)d_in[0];
    const float* Wqr = (const float*)d_in[1];
    const float* Wqi = (const float*)d_in[2];
    const float* bqr = (const float*)d_in[3];
    const float* bqi = (const float*)d_in[4];
    const float* Wkr = (const float*)d_in[5];
    const float* Wki = (const float*)d_in[6];
    const float* bkr = (const float*)d_in[7];
    const float* bki = (const float*)d_in[8];
    const float* Wv  = (const float*)d_in[9];
    const float* bvv = (const float*)d_in[10];
    const float* pqr = (const float*)d_in[11];
    const float* pqi = (const float*)d_in[12];
    const float* pkr = (const float*)d_in[13];
    const float* pki = (const float*)d_in[14];
    const float* Wo  = (const float*)d_in[15];
    const float* bo  = (const float*)d_in[16];
    const float* W1  = (const float*)d_in[17];
    const float* b1  = (const float*)d_in[18];
    const float* W2  = (const float*)d_in[19];
    const float* b2  = (const float*)d_in[20];
    const float* g1  = (const float*)d_in[21];
    const float* be1 = (const float*)d_in[22];
    const float* g2  = (const float*)d_in[23];
    const float* be2 = (const float*)d_in[24];
    float* out = (float*)d_out;

    static bool attr_done = false;
    if (!attr_done) {
        cudaFuncSetAttribute(hproj_kernel,
            cudaFuncAttributeMaxDynamicSharedMemorySize, (int)SM_HGEMM);
        cudaFuncSetAttribute(hwo_kernel,
            cudaFuncAttributeMaxDynamicSharedMemorySize, (int)SM_HGEMM);
        cudaFuncSetAttribute(hff1_kernel,
            cudaFuncAttributeMaxDynamicSharedMemorySize, (int)SM_HGEMM);
        cudaFuncSetAttribute(hff2_kernel,
            cudaFuncAttributeMaxDynamicSharedMemorySize, (int)SM_HGEMM);
        cudaFuncSetAttribute(flash_attn_kernel,
            cudaFuncAttributeMaxDynamicSharedMemorySize, (int)SM_FLASH);
        attr_done = true;
    }

    const int U4 = THREADS * 4;
    convert_all_kernel<<<(N4_ALL + U4 - 1) / U4, THREADS>>>(
        (const float4*)x, (const float4*)Wo, (const float4*)W1, (const float4*)W2);
    repack_g_kernel<<<(1024 * 5120 / 4) / THREADS, THREADS>>>(
        Wqr, Wqi, Wkr, Wki, Wv);

    hproj_kernel<<<dim3(5120 / 128, (Bb * Ss) / 128), THREADS, SM_HGEMM>>>(
        bqr, bqi, bkr, bki, bvv, pqr, pqi, pkr, pki);
    flash_attn_kernel<<<dim3(Ss / 128, Bb * Nn), THREADS, SM_FLASH>>>();
    hwo_kernel<<<dim3(Hh / 128, (Bb * Ss) / 128), THREADS, SM_HGEMM>>>(bo, x);
    layernorm1_kernel<<<Bb * Ss, THREADS>>>(g1, be1);
    hff1_kernel<<<dim3(FFd / 128, (Bb * Ss) / 128), THREADS, SM_HGEMM>>>(b1);
    hff2_kernel<<<dim3(Hh / 128, (Bb * Ss) / 128), THREADS, SM_HGEMM>>>(b2);
    layernorm2_kernel<<<Bb * Ss, THREADS>>>(g2, be2, out);
}

// round 12
// speedup vs baseline: 7.3741x; 1.0035x over previous
#include <cuda_runtime.h>
#include <cuda_fp16.h>
#include <math.h>
#include <stdint.h>

#define THREADS 256
constexpr int Bb  = 4;
constexpr int Ss  = 1024;
constexpr int Hh  = 1024;
constexpr int Nn  = 16;
constexpr int Dd  = 64;
constexpr int FFd = 4096;
constexpr float SCALE = 0.125f;
constexpr float LOG2E = 1.4426950408889634f;
constexpr float EPSLN = 1e-5f;

// ---------------- scratch (fp16 operands, fp32 residual path) -------------------
__device__ __half g_wpack[1024 * 5120];     // [K=1024][N=5120] qkv weights
__device__ __half g_xt  [Bb * Ss * Hh];     // [M][K]
__device__ __half g_woh [Hh * Hh];          // Wo as-is [K=H][N=H]
__device__ __half g_w1h [Hh * FFd];         // W1 as-is [K=H][N=FF]
__device__ __half g_w2h [FFd * Hh];         // W2 as-is [K=FF][N=H]
__device__ __half g_q[Bb * Nn * Ss * 128];  // log2e-scaled [qr | -qi] concat
__device__ __half g_k[Bb * Nn * Ss * 128];  // [kr+pos | ki+pos]
__device__ __half g_v[Bb * Nn * Ss * Dd];
__device__ __half g_concat[Bb * Ss * Hh];
__device__ __half g_h1h[Bb * Ss * Hh];
__device__ float  g_tmp[Bb * Ss * Hh];
__device__ __half g_ff[(size_t)Bb * Ss * FFd];

// ---------------- helpers ---------------------------------------------------------
__device__ __forceinline__ uint32_t smem_u32(const void* p) {
    return (uint32_t)__cvta_generic_to_shared(p);
}
__device__ __forceinline__ void cp16(uint32_t dst, const void* src) {
    asm volatile("cp.async.cg.shared.global [%0], [%1], 16;" :: "r"(dst), "l"(src));
}
__device__ __forceinline__ void cp_commit() {
    asm volatile("cp.async.commit_group;");
}
template<int N> __device__ __forceinline__ void cp_wait() {
    asm volatile("cp.async.wait_group %0;" :: "n"(N));
}
__device__ __forceinline__ void mma16816(float (&c)[4], const uint32_t (&a)[4],
                                         const uint32_t (&b)[2]) {
    asm volatile(
        "mma.sync.aligned.m16n8k16.row.col.f32.f16.f16.f32 "
        "{%0,%1,%2,%3}, {%4,%5,%6,%7}, {%8,%9}, {%0,%1,%2,%3};"
        : "+f"(c[0]), "+f"(c[1]), "+f"(c[2]), "+f"(c[3])
        : "r"(a[0]), "r"(a[1]), "r"(a[2]), "r"(a[3]), "r"(b[0]), "r"(b[1]));
}
__device__ __forceinline__ void ldsm4(uint32_t (&r)[4], uint32_t addr) {
    asm volatile("ldmatrix.sync.aligned.m8n8.x4.shared.b16 {%0,%1,%2,%3}, [%4];"
        : "=r"(r[0]), "=r"(r[1]), "=r"(r[2]), "=r"(r[3]) : "r"(addr));
}
__device__ __forceinline__ void ldsm4t4(uint32_t (&r)[4], uint32_t addr) {
    asm volatile("ldmatrix.sync.aligned.m8n8.x4.trans.shared.b16 {%0,%1,%2,%3}, [%4];"
        : "=r"(r[0]), "=r"(r[1]), "=r"(r[2]), "=r"(r[3]) : "r"(addr));
}
__device__ __forceinline__ void ldsm2t(uint32_t (&r)[2], uint32_t addr) {
    asm volatile("ldmatrix.sync.aligned.m8n8.x2.trans.shared.b16 {%0,%1}, [%2];"
        : "=r"(r[0]), "=r"(r[1]) : "r"(addr));
}
__device__ __forceinline__ uint32_t h2u(__half2 h) {
    return *reinterpret_cast<uint32_t*>(&h);
}
__device__ __forceinline__ float ex2f(float x) {
    float r;
    asm("ex2.approx.ftz.f32 %0, %1;" : "=f"(r) : "f"(x));
    return r;
}

// ---------------- fp16 tensor-core GEMM core (B in [K][N] layout) -------------------
constexpr int hLA  = 72;
constexpr int hLB  = 136;
constexpr int hASZ = 128 * hLA;
constexpr int hBSZ = 64 * hLB;
constexpr int hBUF = hASZ + hBSZ;
constexpr size_t SM_HGEMM = (size_t)2 * hBUF * sizeof(__half);   // 71680 B

template<int KTOT, typename Epi>
__device__ __forceinline__ void hgemm(
    const __half* __restrict__ A, int lda,
    const __half* __restrict__ B, int ldb,
    int m0, int n0, Epi epi)
{
    extern __shared__ __half hsm[];
    const int tid = threadIdx.x, lane = tid & 31, wid = tid >> 5;
    const int wm = wid >> 2, wn = wid & 3;
    const int lrow = lane & 15, lhi = (lane >> 4) & 1;

    auto load_tile = [&](int buf, int kc) {
        __half* a = hsm + buf * hBUF;
        __half* b = a + hASZ;
        uint32_t ab = smem_u32(a), bb = smem_u32(b);
        #pragma unroll
        for (int u = 0; u < 4; ++u) {
            int idx = tid + u * THREADS;
            int m = idx >> 3, kq = idx & 7;
            cp16(ab + (m * hLA + kq * 8) * 2,
                 A + (size_t)(m0 + m) * lda + kc * 64 + kq * 8);
        }
        #pragma unroll
        for (int u = 0; u < 4; ++u) {
            int idx = tid + u * THREADS;
            int r = idx >> 4, q = idx & 15;
            cp16(bb + (r * hLB + q * 8) * 2,
                 B + (size_t)(kc * 64 + r) * ldb + n0 + q * 8);
        }
    };

    float acc[4][4][4] = {};

    auto compute = [&](int buf) {
        __half* a = hsm + buf * hBUF;
        __half* b = a + hASZ;
        uint32_t ab = smem_u32(a), bb = smem_u32(b);
        #pragma unroll
        for (int ks = 0; ks < 4; ++ks) {
            int kk = ks * 16;
            uint32_t af[4][4];
            #pragma unroll
            for (int i = 0; i < 4; ++i) {
                int row = wm * 64 + i * 16 + lrow;
                ldsm4(af[i], ab + (row * hLA + kk + lhi * 8) * 2);
            }
            #pragma unroll
            for (int p = 0; p < 2; ++p) {
                uint32_t bf[4];
                ldsm4t4(bf, bb + ((kk + lrow) * hLB + wn * 32 + p * 16 + lhi * 8) * 2);
                uint32_t b0[2] = { bf[0], bf[1] };
                uint32_t b1[2] = { bf[2], bf[3] };
                #pragma unroll
                for (int i = 0; i < 4; ++i) {
                    mma16816(acc[i][2 * p],     af[i], b0);
                    mma16816(acc[i][2 * p + 1], af[i], b1);
                }
            }
        }
    };

    constexpr int T = KTOT / 64;
    load_tile(0, 0);
    cp_commit();
    for (int i = 0; i < T; ++i) {
        cp_wait<0>();
        __syncthreads();
        if (i + 1 < T) { load_tile((i + 1) & 1, i + 1); cp_commit(); }
        compute(i & 1);
    }

    const int g = lane >> 2, t = lane & 3;
    #pragma unroll
    for (int i = 0; i < 4; ++i) {
        int r0 = m0 + (wm * 4 + i) * 16 + g;
        #pragma unroll
        for (int j = 0; j < 4; ++j) {
            int c0 = n0 + (wn * 4 + j) * 8 + 2 * t;
            epi(r0,     c0, acc[i][j][0], acc[i][j][1]);
            epi(r0 + 8, c0, acc[i][j][2], acc[i][j][3]);
        }
    }
}

// ---------------- pre-conversion kernels --------------------------------------------
constexpr int N4_X  = Bb * Ss * Hh / 4;
constexpr int N4_WO = Hh * Hh / 4;
constexpr int N4_W1 = Hh * FFd / 4;
constexpr int N4_ALL = N4_X + N4_WO + 2 * N4_W1;

__global__ __launch_bounds__(THREADS) void convert_all_kernel(
    const float4* __restrict__ x,  const float4* __restrict__ Wo,
    const float4* __restrict__ W1, const float4* __restrict__ W2)
{
    int base = blockIdx.x * (THREADS * 4) + threadIdx.x;
    #pragma unroll
    for (int u = 0; u < 4; ++u) {
        int i = base + u * THREADS;
        if (i >= N4_ALL) return;
        const float4* src;
        uint2* dst;
        int j;
        if (i < N4_X) {
            src = x;  dst = (uint2*)g_xt;  j = i;
        } else if (i < N4_X + N4_WO) {
            src = Wo; dst = (uint2*)g_woh; j = i - N4_X;
        } else if (i < N4_X + N4_WO + N4_W1) {
            src = W1; dst = (uint2*)g_w1h; j = i - N4_X - N4_WO;
        } else {
            src = W2; dst = (uint2*)g_w2h; j = i - N4_X - N4_WO - N4_W1;
        }
        float4 v = src[j];
        dst[j] = make_uint2(h2u(__floats2half2_rn(v.x, v.y)),
                            h2u(__floats2half2_rn(v.z, v.w)));
    }
}

__global__ __launch_bounds__(THREADS) void repack_g_kernel(
    const float* __restrict__ Wqr, const float* __restrict__ Wqi,
    const float* __restrict__ Wkr, const float* __restrict__ Wki,
    const float* __restrict__ Wv)
{
    int idx = blockIdx.x * THREADS + threadIdx.x;
    int col4 = idx % 1280;
    int k    = idx / 1280;
    int c = col4 * 4;
    int p = c >> 10, n = (c >> 6) & 15, d = c & 63;
    const float* W = (p == 0) ? Wqr : (p == 1) ? Wqi : (p == 2) ? Wkr
                    : (p == 3) ? Wki : Wv;
    float4 v = *reinterpret_cast<const float4*>(
        W + (((size_t)n) << 16) + (size_t)k * 64 + d);
    *reinterpret_cast<uint2*>(g_wpack + (size_t)k * 5120 + c) =
        make_uint2(h2u(__floats2half2_rn(v.x, v.y)),
                   h2u(__floats2half2_rn(v.z, v.w)));
}

// ---------------- GEMM kernels -----------------------------------------------------
__global__ __launch_bounds__(THREADS, 2) void hproj_kernel(
    const float* __restrict__ bqr, const float* __restrict__ bqi,
    const float* __restrict__ bkr, const float* __restrict__ bki,
    const float* __restrict__ bvv,
    const float* __restrict__ pqr, const float* __restrict__ pqi,
    const float* __restrict__ pkr, const float* __restrict__ pki)
{
    constexpr float QSC = SCALE * LOG2E;
    int m0 = blockIdx.y * 128, n0 = blockIdx.x * 128;
    hgemm<1024>(g_xt, Hh, g_wpack, 5120, m0, n0,
        [&](int row, int col, float v0, float v1) {
            int p = col >> 10, n = (col >> 6) & 15, d = col & 63;
            int bb = row >> 10, s = row & 1023;
            size_t pidx = (((size_t)n << 10) + s) * Dd + d;
            size_t rowoff = (((size_t)(bb * Nn + n)) << 10) + s;
            float x0, x1;
            __half* dst;
            if (p == 0) {
                x0 = ((v0 + bqr[n * Dd + d])     * SCALE + pqr[pidx])     * QSC;
                x1 = ((v1 + bqr[n * Dd + d + 1]) * SCALE + pqr[pidx + 1]) * QSC;
                dst = g_q + rowoff * 128 + d;
            } else if (p == 1) {
                x0 = -(((v0 + bqi[n * Dd + d])     * SCALE + pqi[pidx])     * QSC);
                x1 = -(((v1 + bqi[n * Dd + d + 1]) * SCALE + pqi[pidx + 1]) * QSC);
                dst = g_q + rowoff * 128 + 64 + d;
            } else if (p == 2) {
                x0 = v0 + bkr[n * Dd + d]     + pkr[pidx];
                x1 = v1 + bkr[n * Dd + d + 1] + pkr[pidx + 1];
                dst = g_k + rowoff * 128 + d;
            } else if (p == 3) {
                x0 = v0 + bki[n * Dd + d]     + pki[pidx];
                x1 = v1 + bki[n * Dd + d + 1] + pki[pidx + 1];
                dst = g_k + rowoff * 128 + 64 + d;
            } else {
                x0 = v0 + bvv[n * Dd + d];
                x1 = v1 + bvv[n * Dd + d + 1];
                dst = g_v + rowoff * Dd + d;
            }
            *reinterpret_cast<__half2*>(dst) = __floats2half2_rn(x0, x1);
        });
}

__global__ __launch_bounds__(THREADS, 2) void hwo_kernel(
    const float* __restrict__ bo, const float* __restrict__ x)
{
    int m0 = blockIdx.y * 128, n0 = blockIdx.x * 128;
    hgemm<1024>(g_concat, Hh, g_woh, Hh, m0, n0,
        [&](int row, int c0, float v0, float v1) {
            size_t o = (size_t)row * Hh + c0;
            g_tmp[o]     = v0 + bo[c0]     + x[o];
            g_tmp[o + 1] = v1 + bo[c0 + 1] + x[o + 1];
        });
}

__global__ __launch_bounds__(THREADS, 2) void hff1_kernel(const float* __restrict__ b1)
{
    int m0 = blockIdx.y * 128, n0 = blockIdx.x * 128;
    hgemm<1024>(g_h1h, Hh, g_w1h, FFd, m0, n0,
        [&](int row, int c0, float v0, float v1) {
            size_t o = (size_t)row * FFd + c0;
            *reinterpret_cast<__half2*>(g_ff + o) = __floats2half2_rn(
                fmaxf(v0 + b1[c0], 0.f), fmaxf(v1 + b1[c0 + 1], 0.f));
        });
}

__global__ __launch_bounds__(THREADS, 2) void hff2_kernel(const float* __restrict__ b2)
{
    int m0 = blockIdx.y * 128, n0 = blockIdx.x * 128;
    hgemm<4096>(g_ff, FFd, g_w2h, Hh, m0, n0,
        [&](int row, int c0, float v0, float v1) {
            size_t o = (size_t)row * Hh + c0;
            __half2 hh = *reinterpret_cast<const __half2*>(g_h1h + o);
            g_tmp[o]     = v0 + b2[c0]     + __low2float(hh);
            g_tmp[o + 1] = v1 + b2[c0 + 1] + __high2float(hh);
        });
}

// ---------------- flash attention: q-tile 256, 32 q-rows/warp -----------------------
// smem (halves): Q [0, 34816), KVbuf0 [34816,48128), KVbuf1 [48128,61440)
// KV buffer = K 64x136 (8704) + V 64x72 (4608). V col 64 = ones (l column).
constexpr int fQ0   = 0;
constexpr int fKV0  = 34816;
constexpr int fKVSZ = 13312;
constexpr int fVOFF = 8704;
constexpr size_t SM_FLASH = (size_t)(34816 + 2 * 13312) * sizeof(__half); // 122880 B

__global__ __launch_bounds__(THREADS) void flash_attn_kernel()
{
    extern __shared__ __half hsm[];
    const int tid = threadIdx.x, lane = tid & 31, wid = tid >> 5;
    const int g = lane >> 2, t = lane & 3;
    const int lrow = lane & 15, lhi = (lane >> 4) & 1;
    const int bh = blockIdx.y, b = bh >> 4, head = bh & 15;
    const int m0 = blockIdx.x * 256;

    const __half* Qg = g_q + (size_t)bh * Ss * 128;
    const __half* Kg = g_k + (size_t)bh * Ss * 128;
    const __half* Vg = g_v + (size_t)bh * Ss * Dd;

    const uint32_t sQ = smem_u32(hsm + fQ0);

    #pragma unroll
    for (int u = 0; u < 16; ++u) {
        int idx = tid + u * THREADS;
        int m = idx >> 4, q = idx & 15;
        cp16(sQ + (m * 136 + q * 8) * 2, Qg + (size_t)(m0 + m) * 128 + q * 8);
    }

    // init V pad columns (col 64 = 1.0, cols 65..71 = 0) for both buffers
    if (tid < 128) {
        int buf = tid >> 6, r = tid & 63;
        uint4* pad = reinterpret_cast<uint4*>(
            hsm + fKV0 + buf * fKVSZ + fVOFF + r * 72 + 64);
        *pad = make_uint4(0x00003C00u, 0u, 0u, 0u);
    }

    auto load_kv = [&](int kt, int buf) {
        uint32_t sK = smem_u32(hsm + fKV0 + buf * fKVSZ);
        uint32_t sV = sK + fVOFF * 2;
        const __half* kp = Kg + (size_t)kt * 64 * 128;
        const __half* vp = Vg + (size_t)kt * 64 * Dd;
        #pragma unroll
        for (int u = 0; u < 4; ++u) {
            int idx = tid + u * THREADS;
            int r = idx >> 4, q = idx & 15;
            cp16(sK + (r * 136 + q * 8) * 2, kp + (size_t)r * 128 + q * 8);
        }
        #pragma unroll
        for (int u = 0; u < 2; ++u) {
            int idx = tid + u * THREADS;
            int r = idx >> 3, q = idx & 7;
            cp16(sV + (r * 72 + q * 8) * 2, vp + (size_t)r * Dd + q * 8);
        }
    };
    load_kv(0, 0);
    cp_commit();

    float m_run[2][2] = {{-1e30f, -1e30f}, {-1e30f, -1e30f}};
    float acc_o[2][8][4] = {};
    float acc_l[2][4] = {};
    const int mq = wid * 32;

    constexpr int NT = Ss / 64;
    for (int kt = 0; kt < NT; ++kt) {
        const int buf = kt & 1;
        cp_wait<0>();
        __syncthreads();
        if (kt + 1 < NT) { load_kv(kt + 1, buf ^ 1); cp_commit(); }

        const uint32_t sK = smem_u32(hsm + fKV0 + buf * fKVSZ);
        const uint32_t sV = sK + fVOFF * 2;

        // scores: 2 strips x [16 x 64], K=128 — K fragments shared across strips
        float acc_s[2][8][4] = {};
        #pragma unroll
        for (int ks = 0; ks < 8; ++ks) {
            uint32_t qf[2][4];
            #pragma unroll
            for (int si = 0; si < 2; ++si)
                ldsm4(qf[si], sQ + ((mq + si * 16 + lrow) * 136 + ks * 16 + lhi * 8) * 2);
            #pragma unroll
            for (int p = 0; p < 4; ++p) {
                uint32_t bf[4];
                ldsm4(bf, sK + ((p * 16 + lrow) * 136 + ks * 16 + lhi * 8) * 2);
                uint32_t b0[2] = { bf[0], bf[2] };
                uint32_t b1[2] = { bf[1], bf[3] };
                #pragma unroll
                for (int si = 0; si < 2; ++si) {
                    mma16816(acc_s[si][2 * p],     qf[si], b0);
                    mma16816(acc_s[si][2 * p + 1], qf[si], b1);
                }
            }
        }

        // online softmax (base-2), per strip; pack P fragments
        uint32_t pf[2][4][4];
        #pragma unroll
        for (int si = 0; si < 2; ++si) {
            float tm0 = -1e30f, tm1 = -1e30f;
            #pragma unroll
            for (int j = 0; j < 8; ++j) {
                tm0 = fmaxf(tm0, fmaxf(acc_s[si][j][0], acc_s[si][j][1]));
                tm1 = fmaxf(tm1, fmaxf(acc_s[si][j][2], acc_s[si][j][3]));
            }
            #pragma unroll
            for (int o = 1; o <= 2; o <<= 1) {
                tm0 = fmaxf(tm0, __shfl_xor_sync(0xffffffffu, tm0, o));
                tm1 = fmaxf(tm1, __shfl_xor_sync(0xffffffffu, tm1, o));
            }
            float mn0 = fmaxf(m_run[si][0], tm0), mn1 = fmaxf(m_run[si][1], tm1);
            float sc0 = ex2f(m_run[si][0] - mn0), sc1 = ex2f(m_run[si][1] - mn1);
            m_run[si][0] = mn0; m_run[si][1] = mn1;

            #pragma unroll
            for (int j = 0; j < 8; ++j) {
                acc_s[si][j][0] = ex2f(acc_s[si][j][0] - mn0);
                acc_s[si][j][1] = ex2f(acc_s[si][j][1] - mn0);
                acc_s[si][j][2] = ex2f(acc_s[si][j][2] - mn1);
                acc_s[si][j][3] = ex2f(acc_s[si][j][3] - mn1);
            }
            #pragma unroll
            for (int j = 0; j < 8; ++j) {
                acc_o[si][j][0] *= sc0; acc_o[si][j][1] *= sc0;
                acc_o[si][j][2] *= sc1; acc_o[si][j][3] *= sc1;
            }
            acc_l[si][0] *= sc0; acc_l[si][1] *= sc0;
            acc_l[si][2] *= sc1; acc_l[si][3] *= sc1;

            #pragma unroll
            for (int k2 = 0; k2 < 4; ++k2) {
                pf[si][k2][0] = h2u(__floats2half2_rn(acc_s[si][2 * k2][0],     acc_s[si][2 * k2][1]));
                pf[si][k2][1] = h2u(__floats2half2_rn(acc_s[si][2 * k2][2],     acc_s[si][2 * k2][3]));
                pf[si][k2][2] = h2u(__floats2half2_rn(acc_s[si][2 * k2 + 1][0], acc_s[si][2 * k2 + 1][1]));
                pf[si][k2][3] = h2u(__floats2half2_rn(acc_s[si][2 * k2 + 1][2], acc_s[si][2 * k2 + 1][3]));
            }
        }

        // PV: 2 strips x [16 x 64] @ [64 x 64] + l column; V fragments shared
        #pragma unroll
        for (int ks = 0; ks < 4; ++ks) {
            #pragma unroll
            for (int p = 0; p < 4; ++p) {
                uint32_t bf[4];
                ldsm4t4(bf, sV + ((ks * 16 + lrow) * 72 + p * 16 + lhi * 8) * 2);
                uint32_t b0[2] = { bf[0], bf[1] };
                uint32_t b1[2] = { bf[2], bf[3] };
                #pragma unroll
                for (int si = 0; si < 2; ++si) {
                    mma16816(acc_o[si][2 * p],     pf[si][ks], b0);
                    mma16816(acc_o[si][2 * p + 1], pf[si][ks], b1);
                }
            }
            uint32_t bl[2];
            ldsm2t(bl, sV + ((ks * 16 + lrow) * 72 + 64) * 2);
            #pragma unroll
            for (int si = 0; si < 2; ++si)
                mma16816(acc_l[si], pf[si][ks], bl);
        }
    }

    #pragma unroll
    for (int si = 0; si < 2; ++si) {
        float l0 = __shfl_sync(0xffffffffu, acc_l[si][0], lane & ~3);
        float l1 = __shfl_sync(0xffffffffu, acc_l[si][2], lane & ~3);
        float inv0 = 1.0f / l0, inv1 = 1.0f / l1;
        int s0 = m0 + mq + si * 16 + g;
        #pragma unroll
        for (int j = 0; j < 8; ++j) {
            int c = j * 8 + 2 * t;
            __half* o0 = g_concat + ((size_t)(b * Ss + s0)) * Hh + head * Dd + c;
            __half* o1 = g_concat + ((size_t)(b * Ss + s0 + 8)) * Hh + head * Dd + c;
            *reinterpret_cast<__half2*>(o0) =
                __floats2half2_rn(acc_o[si][j][0] * inv0, acc_o[si][j][1] * inv0);
            *reinterpret_cast<__half2*>(o1) =
                __floats2half2_rn(acc_o[si][j][2] * inv1, acc_o[si][j][3] * inv1);
        }
    }
}

// ---------------- LayerNorms --------------------------------------------------------
__global__ __launch_bounds__(THREADS) void layernorm1_kernel(
    const float* __restrict__ gw, const float* __restrict__ bw)
{
    int row = blockIdx.x;
    const float4* rp = reinterpret_cast<const float4*>(g_tmp + (size_t)row * Hh);
    float4 v = rp[threadIdx.x];
    float s  = v.x + v.y + v.z + v.w;
    float s2 = v.x * v.x + v.y * v.y + v.z * v.z + v.w * v.w;
    #pragma unroll
    for (int o = 16; o; o >>= 1) {
        s  += __shfl_xor_sync(0xffffffffu, s,  o);
        s2 += __shfl_xor_sync(0xffffffffu, s2, o);
    }
    __shared__ float rs[8], rs2[8];
    int lane = threadIdx.x & 31, wid = threadIdx.x >> 5;
    if (lane == 0) { rs[wid] = s; rs2[wid] = s2; }
    __syncthreads();
    s = 0.f; s2 = 0.f;
    #pragma unroll
    for (int i = 0; i < 8; ++i) { s += rs[i]; s2 += rs2[i]; }
    float mu  = s  * (1.0f / Hh);
    float var = s2 * (1.0f / Hh) - mu * mu;
    float inv = rsqrtf(var + EPSLN);
    float4 g4 = reinterpret_cast<const float4*>(gw)[threadIdx.x];
    float4 b4 = reinterpret_cast<const float4*>(bw)[threadIdx.x];
    float4 o4;
    o4.x = (v.x - mu) * inv * g4.x + b4.x;
    o4.y = (v.y - mu) * inv * g4.y + b4.y;
    o4.z = (v.z - mu) * inv * g4.z + b4.z;
    o4.w = (v.w - mu) * inv * g4.w + b4.w;
    uint2 hh = make_uint2(h2u(__floats2half2_rn(o4.x, o4.y)),
                          h2u(__floats2half2_rn(o4.z, o4.w)));
    reinterpret_cast<uint2*>(g_h1h + (size_t)row * Hh)[threadIdx.x] = hh;
}

__global__ __launch_bounds__(THREADS) void layernorm2_kernel(
    const float* __restrict__ gw, const float* __restrict__ bw,
    float* __restrict__ out)
{
    int row = blockIdx.x;
    const float4* rp = reinterpret_cast<const float4*>(g_tmp + (size_t)row * Hh);
    float4 v = rp[threadIdx.x];
    float s  = v.x + v.y + v.z + v.w;
    float s2 = v.x * v.x + v.y * v.y + v.z * v.z + v.w * v.w;
    #pragma unroll
    for (int o = 16; o; o >>= 1) {
        s  += __shfl_xor_sync(0xffffffffu, s,  o);
        s2 += __shfl_xor_sync(0xffffffffu, s2, o);
    }
    __shared__ float rs[8], rs2[8];
    int lane = threadIdx.x & 31, wid = threadIdx.x >> 5;
    if (lane == 0) { rs[wid] = s; rs2[wid] = s2; }
    __syncthreads();
    s = 0.f; s2 = 0.f;
    #pragma unroll
    for (int i = 0; i < 8; ++i) { s += rs[i]; s2 += rs2[i]; }
    float mu  = s  * (1.0f / Hh);
    float var = s2 * (1.0f / Hh) - mu * mu;
    float inv = rsqrtf(var + EPSLN);
    float4 g4 = reinterpret_cast<const float4*>(gw)[threadIdx.x];
    float4 b4 = reinterpret_cast<const float4*>(bw)[threadIdx.x];
    float4 o4;
    o4.x = (v.x - mu) * inv * g4.x + b4.x;
    o4.y = (v.y - mu) * inv * g4.y + b4.y;
    o4.z = (v.z - mu) * inv * g4.z + b4.z;
    o4.w = (v.w - mu) * inv * g4.w + b4.w;
    reinterpret_cast<float4*>(out + (size_t)row * Hh)[threadIdx.x] = o4;
}

// ---------------- entry ---------------------------------------------------------------
extern "C" void kernel_launch(void* const* d_in, const int* in_sizes, int n_in,
                              void* d_out, int out_size)
{
    const float* x   = (const float*)d_in[0];
    const float* Wqr = (const float*)d_in[1];
    const float* Wqi = (const float*)d_in[2];
    const float* bqr = (const float*)d_in[3];
    const float* bqi = (const float*)d_in[4];
    const float* Wkr = (const float*)d_in[5];
    const float* Wki = (const float*)d_in[6];
    const float* bkr = (const float*)d_in[7];
    const float* bki = (const float*)d_in[8];
    const float* Wv  = (const float*)d_in[9];
    const float* bvv = (const float*)d_in[10];
    const float* pqr = (const float*)d_in[11];
    const float* pqi = (const float*)d_in[12];
    const float* pkr = (const float*)d_in[13];
    const float* pki = (const float*)d_in[14];
    const float* Wo  = (const float*)d_in[15];
    const float* bo  = (const float*)d_in[16];
    const float* W1  = (const float*)d_in[17];
    const float* b1  = (const float*)d_in[18];
    const float* W2  = (const float*)d_in[19];
    const float* b2  = (const float*)d_in[20];
    const float* g1  = (const float*)d_in[21];
    const float* be1 = (const float*)d_in[22];
    const float* g2  = (const float*)d_in[23];
    const float* be2 = (const float*)d_in[24];
    float* out = (float*)d_out;

    static bool attr_done = false;
    if (!attr_done) {
        cudaFuncSetAttribute(hproj_kernel,
            cudaFuncAttributeMaxDynamicSharedMemorySize, (int)SM_HGEMM);
        cudaFuncSetAttribute(hwo_kernel,
            cudaFuncAttributeMaxDynamicSharedMemorySize, (int)SM_HGEMM);
        cudaFuncSetAttribute(hff1_kernel,
            cudaFuncAttributeMaxDynamicSharedMemorySize, (int)SM_HGEMM);
        cudaFuncSetAttribute(hff2_kernel,
            cudaFuncAttributeMaxDynamicSharedMemorySize, (int)SM_HGEMM);
        cudaFuncSetAttribute(flash_attn_kernel,
            cudaFuncAttributeMaxDynamicSharedMemorySize, (int)SM_FLASH);
        attr_done = true;
    }

    const int U4 = THREADS * 4;
    convert_all_kernel<<<(N4_ALL + U4 - 1) / U4, THREADS>>>(
        (const float4*)x, (const float4*)Wo, (const float4*)W1, (const float4*)W2);
    repack_g_kernel<<<(1024 * 5120 / 4) / THREADS, THREADS>>>(
        Wqr, Wqi, Wkr, Wki, Wv);

    hproj_kernel<<<dim3(5120 / 128, (Bb * Ss) / 128), THREADS, SM_HGEMM>>>(
        bqr, bqi, bkr, bki, bvv, pqr, pqi, pkr, pki);
    flash_attn_kernel<<<dim3(Ss / 256, Bb * Nn), THREADS, SM_FLASH>>>();
    hwo_kernel<<<dim3(Hh / 128, (Bb * Ss) / 128), THREADS, SM_HGEMM>>>(bo, x);
    layernorm1_kernel<<<Bb * Ss, THREADS>>>(g1, be1);
    hff1_kernel<<<dim3(FFd / 128, (Bb * Ss) / 128), THREADS, SM_HGEMM>>>(b1);
    hff2_kernel<<<dim3(Hh / 128, (Bb * Ss) / 128), THREADS, SM_HGEMM>>>(b2);
    layernorm2_kernel<<<Bb * Ss, THREADS>>>(g2, be2, out);
}

// round 13
// speedup vs baseline: 7.4487x; 1.0101x over previous
#include <cuda_runtime.h>
#include <cuda_fp16.h>
#include <math.h>
#include <stdint.h>

#define THREADS 256
#define FA_THREADS 128
constexpr int Bb  = 4;
constexpr int Ss  = 1024;
constexpr int Hh  = 1024;
constexpr int Nn  = 16;
constexpr int Dd  = 64;
constexpr int FFd = 4096;
constexpr float SCALE = 0.125f;
constexpr float LOG2E = 1.4426950408889634f;
constexpr float EPSLN = 1e-5f;

// ---------------- scratch (fp16 operands, fp32 residual path) -------------------
__device__ __half g_wpack[1024 * 5120];     // [K=1024][N=5120] qkv weights
__device__ __half g_xt  [Bb * Ss * Hh];     // [M][K]
__device__ __half g_woh [Hh * Hh];
__device__ __half g_w1h [Hh * FFd];
__device__ __half g_w2h [FFd * Hh];
__device__ __half g_q[Bb * Nn * Ss * 128];  // log2e-scaled [qr | -qi] concat
__device__ __half g_k[Bb * Nn * Ss * 128];  // [kr+pos | ki+pos]
__device__ __half g_v[Bb * Nn * Ss * Dd];
__device__ __half g_concat[Bb * Ss * Hh];
__device__ __half g_h1h[Bb * Ss * Hh];
__device__ float  g_tmp[Bb * Ss * Hh];
__device__ __half g_ff[(size_t)Bb * Ss * FFd];

// ---------------- helpers ---------------------------------------------------------
__device__ __forceinline__ uint32_t smem_u32(const void* p) {
    return (uint32_t)__cvta_generic_to_shared(p);
}
__device__ __forceinline__ void cp16(uint32_t dst, const void* src) {
    asm volatile("cp.async.cg.shared.global [%0], [%1], 16;" :: "r"(dst), "l"(src));
}
__device__ __forceinline__ void cp_commit() {
    asm volatile("cp.async.commit_group;");
}
template<int N> __device__ __forceinline__ void cp_wait() {
    asm volatile("cp.async.wait_group %0;" :: "n"(N));
}
__device__ __forceinline__ void mma16816(float (&c)[4], const uint32_t (&a)[4],
                                         const uint32_t (&b)[2]) {
    asm volatile(
        "mma.sync.aligned.m16n8k16.row.col.f32.f16.f16.f32 "
        "{%0,%1,%2,%3}, {%4,%5,%6,%7}, {%8,%9}, {%0,%1,%2,%3};"
        : "+f"(c[0]), "+f"(c[1]), "+f"(c[2]), "+f"(c[3])
        : "r"(a[0]), "r"(a[1]), "r"(a[2]), "r"(a[3]), "r"(b[0]), "r"(b[1]));
}
__device__ __forceinline__ void ldsm4(uint32_t (&r)[4], uint32_t addr) {
    asm volatile("ldmatrix.sync.aligned.m8n8.x4.shared.b16 {%0,%1,%2,%3}, [%4];"
        : "=r"(r[0]), "=r"(r[1]), "=r"(r[2]), "=r"(r[3]) : "r"(addr));
}
__device__ __forceinline__ void ldsm4t4(uint32_t (&r)[4], uint32_t addr) {
    asm volatile("ldmatrix.sync.aligned.m8n8.x4.trans.shared.b16 {%0,%1,%2,%3}, [%4];"
        : "=r"(r[0]), "=r"(r[1]), "=r"(r[2]), "=r"(r[3]) : "r"(addr));
}
__device__ __forceinline__ void ldsm2t(uint32_t (&r)[2], uint32_t addr) {
    asm volatile("ldmatrix.sync.aligned.m8n8.x2.trans.shared.b16 {%0,%1}, [%2];"
        : "=r"(r[0]), "=r"(r[1]) : "r"(addr));
}
__device__ __forceinline__ uint32_t h2u(__half2 h) {
    return *reinterpret_cast<uint32_t*>(&h);
}
__device__ __forceinline__ float ex2f(float x) {
    float r;
    asm("ex2.approx.ftz.f32 %0, %1;" : "=f"(r) : "f"(x));
    return r;
}

// ---------------- fp16 tensor-core GEMM core (B in [K][N] layout) -------------------
constexpr int hLA  = 72;
constexpr int hLB  = 136;
constexpr int hASZ = 128 * hLA;
constexpr int hBSZ = 64 * hLB;
constexpr int hBUF = hASZ + hBSZ;
constexpr size_t SM_HGEMM = (size_t)2 * hBUF * sizeof(__half);   // 71680 B

template<int KTOT, typename Epi>
__device__ __forceinline__ void hgemm(
    const __half* __restrict__ A, int lda,
    const __half* __restrict__ B, int ldb,
    int m0, int n0, Epi epi)
{
    extern __shared__ __half hsm[];
    const int tid = threadIdx.x, lane = tid & 31, wid = tid >> 5;
    const int wm = wid >> 2, wn = wid & 3;
    const int lrow = lane & 15, lhi = (lane >> 4) & 1;

    auto load_tile = [&](int buf, int kc) {
        __half* a = hsm + buf * hBUF;
        __half* b = a + hASZ;
        uint32_t ab = smem_u32(a), bb = smem_u32(b);
        #pragma unroll
        for (int u = 0; u < 4; ++u) {
            int idx = tid + u * THREADS;
            int m = idx >> 3, kq = idx & 7;
            cp16(ab + (m * hLA + kq * 8) * 2,
                 A + (size_t)(m0 + m) * lda + kc * 64 + kq * 8);
        }
        #pragma unroll
        for (int u = 0; u < 4; ++u) {
            int idx = tid + u * THREADS;
            int r = idx >> 4, q = idx & 15;
            cp16(bb + (r * hLB + q * 8) * 2,
                 B + (size_t)(kc * 64 + r) * ldb + n0 + q * 8);
        }
    };

    float acc[4][4][4] = {};

    auto compute = [&](int buf) {
        __half* a = hsm + buf * hBUF;
        __half* b = a + hASZ;
        uint32_t ab = smem_u32(a), bb = smem_u32(b);
        #pragma unroll
        for (int ks = 0; ks < 4; ++ks) {
            int kk = ks * 16;
            uint32_t af[4][4];
            #pragma unroll
            for (int i = 0; i < 4; ++i) {
                int row = wm * 64 + i * 16 + lrow;
                ldsm4(af[i], ab + (row * hLA + kk + lhi * 8) * 2);
            }
            #pragma unroll
            for (int p = 0; p < 2; ++p) {
                uint32_t bf[4];
                ldsm4t4(bf, bb + ((kk + lrow) * hLB + wn * 32 + p * 16 + lhi * 8) * 2);
                uint32_t b0[2] = { bf[0], bf[1] };
                uint32_t b1[2] = { bf[2], bf[3] };
                #pragma unroll
                for (int i = 0; i < 4; ++i) {
                    mma16816(acc[i][2 * p],     af[i], b0);
                    mma16816(acc[i][2 * p + 1], af[i], b1);
                }
            }
        }
    };

    constexpr int T = KTOT / 64;
    load_tile(0, 0);
    cp_commit();
    for (int i = 0; i < T; ++i) {
        cp_wait<0>();
        __syncthreads();
        if (i + 1 < T) { load_tile((i + 1) & 1, i + 1); cp_commit(); }
        compute(i & 1);
    }

    const int g = lane >> 2, t = lane & 3;
    #pragma unroll
    for (int i = 0; i < 4; ++i) {
        int r0 = m0 + (wm * 4 + i) * 16 + g;
        #pragma unroll
        for (int j = 0; j < 4; ++j) {
            int c0 = n0 + (wn * 4 + j) * 8 + 2 * t;
            epi(r0,     c0, acc[i][j][0], acc[i][j][1]);
            epi(r0 + 8, c0, acc[i][j][2], acc[i][j][3]);
        }
    }
}

// ---------------- merged prepass: converts + qkv repack ------------------------------
constexpr int N4_X  = Bb * Ss * Hh / 4;
constexpr int N4_WO = Hh * Hh / 4;
constexpr int N4_W1 = Hh * FFd / 4;
constexpr int N4_ALL = N4_X + N4_WO + 2 * N4_W1;
constexpr int N4_RP  = 1024 * 5120 / 4;
constexpr int N4_TOT = N4_ALL + N4_RP;

__global__ __launch_bounds__(THREADS) void prepass_kernel(
    const float4* __restrict__ x,  const float4* __restrict__ Wo,
    const float4* __restrict__ W1, const float4* __restrict__ W2,
    const float* __restrict__ Wqr, const float* __restrict__ Wqi,
    const float* __restrict__ Wkr, const float* __restrict__ Wki,
    const float* __restrict__ Wv)
{
    int base = blockIdx.x * (THREADS * 4) + threadIdx.x;
    #pragma unroll
    for (int u = 0; u < 4; ++u) {
        int i = base + u * THREADS;
        if (i >= N4_TOT) return;
        if (i < N4_ALL) {
            const float4* src;
            uint2* dst;
            int j;
            if (i < N4_X) {
                src = x;  dst = (uint2*)g_xt;  j = i;
            } else if (i < N4_X + N4_WO) {
                src = Wo; dst = (uint2*)g_woh; j = i - N4_X;
            } else if (i < N4_X + N4_WO + N4_W1) {
                src = W1; dst = (uint2*)g_w1h; j = i - N4_X - N4_WO;
            } else {
                src = W2; dst = (uint2*)g_w2h; j = i - N4_X - N4_WO - N4_W1;
            }
            float4 v = src[j];
            dst[j] = make_uint2(h2u(__floats2half2_rn(v.x, v.y)),
                                h2u(__floats2half2_rn(v.z, v.w)));
        } else {
            int idx = i - N4_ALL;
            int col4 = idx % 1280;
            int k    = idx / 1280;
            int c = col4 * 4;
            int p = c >> 10, n = (c >> 6) & 15, d = c & 63;
            const float* W = (p == 0) ? Wqr : (p == 1) ? Wqi : (p == 2) ? Wkr
                            : (p == 3) ? Wki : Wv;
            float4 v = *reinterpret_cast<const float4*>(
                W + (((size_t)n) << 16) + (size_t)k * 64 + d);
            *reinterpret_cast<uint2*>(g_wpack + (size_t)k * 5120 + c) =
                make_uint2(h2u(__floats2half2_rn(v.x, v.y)),
                           h2u(__floats2half2_rn(v.z, v.w)));
        }
    }
}

// ---------------- GEMM kernels -----------------------------------------------------
__global__ __launch_bounds__(THREADS, 2) void hproj_kernel(
    const float* __restrict__ bqr, const float* __restrict__ bqi,
    const float* __restrict__ bkr, const float* __restrict__ bki,
    const float* __restrict__ bvv,
    const float* __restrict__ pqr, const float* __restrict__ pqi,
    const float* __restrict__ pkr, const float* __restrict__ pki)
{
    constexpr float QSC = SCALE * LOG2E;
    int m0 = blockIdx.y * 128, n0 = blockIdx.x * 128;
    hgemm<1024>(g_xt, Hh, g_wpack, 5120, m0, n0,
        [&](int row, int col, float v0, float v1) {
            int p = col >> 10, n = (col >> 6) & 15, d = col & 63;
            int bb = row >> 10, s = row & 1023;
            size_t pidx = (((size_t)n << 10) + s) * Dd + d;
            size_t rowoff = (((size_t)(bb * Nn + n)) << 10) + s;
            float x0, x1;
            __half* dst;
            if (p == 0) {
                x0 = ((v0 + bqr[n * Dd + d])     * SCALE + pqr[pidx])     * QSC;
                x1 = ((v1 + bqr[n * Dd + d + 1]) * SCALE + pqr[pidx + 1]) * QSC;
                dst = g_q + rowoff * 128 + d;
            } else if (p == 1) {
                x0 = -(((v0 + bqi[n * Dd + d])     * SCALE + pqi[pidx])     * QSC);
                x1 = -(((v1 + bqi[n * Dd + d + 1]) * SCALE + pqi[pidx + 1]) * QSC);
                dst = g_q + rowoff * 128 + 64 + d;
            } else if (p == 2) {
                x0 = v0 + bkr[n * Dd + d]     + pkr[pidx];
                x1 = v1 + bkr[n * Dd + d + 1] + pkr[pidx + 1];
                dst = g_k + rowoff * 128 + d;
            } else if (p == 3) {
                x0 = v0 + bki[n * Dd + d]     + pki[pidx];
                x1 = v1 + bki[n * Dd + d + 1] + pki[pidx + 1];
                dst = g_k + rowoff * 128 + 64 + d;
            } else {
                x0 = v0 + bvv[n * Dd + d];
                x1 = v1 + bvv[n * Dd + d + 1];
                dst = g_v + rowoff * Dd + d;
            }
            *reinterpret_cast<__half2*>(dst) = __floats2half2_rn(x0, x1);
        });
}

__global__ __launch_bounds__(THREADS, 2) void hwo_kernel(
    const float* __restrict__ bo, const float* __restrict__ x)
{
    int m0 = blockIdx.y * 128, n0 = blockIdx.x * 128;
    hgemm<1024>(g_concat, Hh, g_woh, Hh, m0, n0,
        [&](int row, int c0, float v0, float v1) {
            size_t o = (size_t)row * Hh + c0;
            g_tmp[o]     = v0 + bo[c0]     + x[o];
            g_tmp[o + 1] = v1 + bo[c0 + 1] + x[o + 1];
        });
}

__global__ __launch_bounds__(THREADS, 2) void hff1_kernel(const float* __restrict__ b1)
{
    int m0 = blockIdx.y * 128, n0 = blockIdx.x * 128;
    hgemm<1024>(g_h1h, Hh, g_w1h, FFd, m0, n0,
        [&](int row, int c0, float v0, float v1) {
            size_t o = (size_t)row * FFd + c0;
            *reinterpret_cast<__half2*>(g_ff + o) = __floats2half2_rn(
                fmaxf(v0 + b1[c0], 0.f), fmaxf(v1 + b1[c0 + 1], 0.f));
        });
}

__global__ __launch_bounds__(THREADS, 2) void hff2_kernel(const float* __restrict__ b2)
{
    int m0 = blockIdx.y * 128, n0 = blockIdx.x * 128;
    hgemm<4096>(g_ff, FFd, g_w2h, Hh, m0, n0,
        [&](int row, int c0, float v0, float v1) {
            size_t o = (size_t)row * Hh + c0;
            __half2 hh = *reinterpret_cast<const __half2*>(g_h1h + o);
            g_tmp[o]     = v0 + b2[c0]     + __low2float(hh);
            g_tmp[o + 1] = v1 + b2[c0 + 1] + __high2float(hh);
        });
}

// ---------------- flash attention: 128-thr CTAs, 32 q-rows/warp, 2 CTA/SM -----------
// smem (halves): Q [0, 17408), KVbuf0 [17408,30720), KVbuf1 [30720,44032)
constexpr int fQ0   = 0;
constexpr int fKV0  = 17408;
constexpr int fKVSZ = 13312;
constexpr int fVOFF = 8704;
constexpr size_t SM_FLASH = (size_t)(17408 + 2 * 13312) * sizeof(__half); // 88064 B

__global__ __launch_bounds__(FA_THREADS, 2) void flash_attn_kernel()
{
    extern __shared__ __half hsm[];
    const int tid = threadIdx.x, lane = tid & 31, wid = tid >> 5;
    const int g = lane >> 2, t = lane & 3;
    const int lrow = lane & 15, lhi = (lane >> 4) & 1;
    const int bh = blockIdx.y, b = bh >> 4, head = bh & 15;
    const int m0 = blockIdx.x * 128;

    const __half* Qg = g_q + (size_t)bh * Ss * 128;
    const __half* Kg = g_k + (size_t)bh * Ss * 128;
    const __half* Vg = g_v + (size_t)bh * Ss * Dd;

    const uint32_t sQ = smem_u32(hsm + fQ0);

    #pragma unroll
    for (int u = 0; u < 16; ++u) {
        int idx = tid + u * FA_THREADS;
        int m = idx >> 4, q = idx & 15;
        cp16(sQ + (m * 136 + q * 8) * 2, Qg + (size_t)(m0 + m) * 128 + q * 8);
    }

    // init V pad columns (col 64 = 1.0, cols 65..71 = 0) for both buffers
    {
        int buf = tid >> 6, r = tid & 63;
        uint4* pad = reinterpret_cast<uint4*>(
            hsm + fKV0 + buf * fKVSZ + fVOFF + r * 72 + 64);
        *pad = make_uint4(0x00003C00u, 0u, 0u, 0u);
    }

    auto load_kv = [&](int kt, int buf) {
        uint32_t sK = smem_u32(hsm + fKV0 + buf * fKVSZ);
        uint32_t sV = sK + fVOFF * 2;
        const __half* kp = Kg + (size_t)kt * 64 * 128;
        const __half* vp = Vg + (size_t)kt * 64 * Dd;
        #pragma unroll
        for (int u = 0; u < 8; ++u) {
            int idx = tid + u * FA_THREADS;
            int r = idx >> 4, q = idx & 15;
            cp16(sK + (r * 136 + q * 8) * 2, kp + (size_t)r * 128 + q * 8);
        }
        #pragma unroll
        for (int u = 0; u < 4; ++u) {
            int idx = tid + u * FA_THREADS;
            int r = idx >> 3, q = idx & 7;
            cp16(sV + (r * 72 + q * 8) * 2, vp + (size_t)r * Dd + q * 8);
        }
    };
    load_kv(0, 0);
    cp_commit();

    float m_run[2][2] = {{-1e30f, -1e30f}, {-1e30f, -1e30f}};
    float acc_o[2][8][4] = {};
    float acc_l[2][4] = {};
    const int mq = wid * 32;

    constexpr int NT = Ss / 64;
    for (int kt = 0; kt < NT; ++kt) {
        const int buf = kt & 1;
        cp_wait<0>();
        __syncthreads();
        if (kt + 1 < NT) { load_kv(kt + 1, buf ^ 1); cp_commit(); }

        const uint32_t sK = smem_u32(hsm + fKV0 + buf * fKVSZ);
        const uint32_t sV = sK + fVOFF * 2;

        // scores: 2 strips x [16 x 64], K=128 — K fragments shared across strips
        float acc_s[2][8][4] = {};
        #pragma unroll
        for (int ks = 0; ks < 8; ++ks) {
            uint32_t qf[2][4];
            #pragma unroll
            for (int si = 0; si < 2; ++si)
                ldsm4(qf[si], sQ + ((mq + si * 16 + lrow) * 136 + ks * 16 + lhi * 8) * 2);
            #pragma unroll
            for (int p = 0; p < 4; ++p) {
                uint32_t bf[4];
                ldsm4(bf, sK + ((p * 16 + lrow) * 136 + ks * 16 + lhi * 8) * 2);
                uint32_t b0[2] = { bf[0], bf[2] };
                uint32_t b1[2] = { bf[1], bf[3] };
                #pragma unroll
                for (int si = 0; si < 2; ++si) {
                    mma16816(acc_s[si][2 * p],     qf[si], b0);
                    mma16816(acc_s[si][2 * p + 1], qf[si], b1);
                }
            }
        }

        // online softmax (base-2), per strip; pack P fragments
        uint32_t pf[2][4][4];
        #pragma unroll
        for (int si = 0; si < 2; ++si) {
            float tm0 = -1e30f, tm1 = -1e30f;
            #pragma unroll
            for (int j = 0; j < 8; ++j) {
                tm0 = fmaxf(tm0, fmaxf(acc_s[si][j][0], acc_s[si][j][1]));
                tm1 = fmaxf(tm1, fmaxf(acc_s[si][j][2], acc_s[si][j][3]));
            }
            #pragma unroll
            for (int o = 1; o <= 2; o <<= 1) {
                tm0 = fmaxf(tm0, __shfl_xor_sync(0xffffffffu, tm0, o));
                tm1 = fmaxf(tm1, __shfl_xor_sync(0xffffffffu, tm1, o));
            }
            float mn0 = fmaxf(m_run[si][0], tm0), mn1 = fmaxf(m_run[si][1], tm1);
            float sc0 = ex2f(m_run[si][0] - mn0), sc1 = ex2f(m_run[si][1] - mn1);
            m_run[si][0] = mn0; m_run[si][1] = mn1;

            #pragma unroll
            for (int j = 0; j < 8; ++j) {
                acc_s[si][j][0] = ex2f(acc_s[si][j][0] - mn0);
                acc_s[si][j][1] = ex2f(acc_s[si][j][1] - mn0);
                acc_s[si][j][2] = ex2f(acc_s[si][j][2] - mn1);
                acc_s[si][j][3] = ex2f(acc_s[si][j][3] - mn1);
            }
            #pragma unroll
            for (int j = 0; j < 8; ++j) {
                acc_o[si][j][0] *= sc0; acc_o[si][j][1] *= sc0;
                acc_o[si][j][2] *= sc1; acc_o[si][j][3] *= sc1;
            }
            acc_l[si][0] *= sc0; acc_l[si][1] *= sc0;
            acc_l[si][2] *= sc1; acc_l[si][3] *= sc1;

            #pragma unroll
            for (int k2 = 0; k2 < 4; ++k2) {
                pf[si][k2][0] = h2u(__floats2half2_rn(acc_s[si][2 * k2][0],     acc_s[si][2 * k2][1]));
                pf[si][k2][1] = h2u(__floats2half2_rn(acc_s[si][2 * k2][2],     acc_s[si][2 * k2][3]));
                pf[si][k2][2] = h2u(__floats2half2_rn(acc_s[si][2 * k2 + 1][0], acc_s[si][2 * k2 + 1][1]));
                pf[si][k2][3] = h2u(__floats2half2_rn(acc_s[si][2 * k2 + 1][2], acc_s[si][2 * k2 + 1][3]));
            }
        }

        // PV: 2 strips x [16 x 64] @ [64 x 64] + l column; V fragments shared
        #pragma unroll
        for (int ks = 0; ks < 4; ++ks) {
            #pragma unroll
            for (int p = 0; p < 4; ++p) {
                uint32_t bf[4];
                ldsm4t4(bf, sV + ((ks * 16 + lrow) * 72 + p * 16 + lhi * 8) * 2);
                uint32_t b0[2] = { bf[0], bf[1] };
                uint32_t b1[2] = { bf[2], bf[3] };
                #pragma unroll
                for (int si = 0; si < 2; ++si) {
                    mma16816(acc_o[si][2 * p],     pf[si][ks], b0);
                    mma16816(acc_o[si][2 * p + 1], pf[si][ks], b1);
                }
            }
            uint32_t bl[2];
            ldsm2t(bl, sV + ((ks * 16 + lrow) * 72 + 64) * 2);
            #pragma unroll
            for (int si = 0; si < 2; ++si)
                mma16816(acc_l[si], pf[si][ks], bl);
        }
    }

    #pragma unroll
    for (int si = 0; si < 2; ++si) {
        float l0 = __shfl_sync(0xffffffffu, acc_l[si][0], lane & ~3);
        float l1 = __shfl_sync(0xffffffffu, acc_l[si][2], lane & ~3);
        float inv0 = 1.0f / l0, inv1 = 1.0f / l1;
        int s0 = m0 + mq + si * 16 + g;
        #pragma unroll
        for (int j = 0; j < 8; ++j) {
            int c = j * 8 + 2 * t;
            __half* o0 = g_concat + ((size_t)(b * Ss + s0)) * Hh + head * Dd + c;
            __half* o1 = g_concat + ((size_t)(b * Ss + s0 + 8)) * Hh + head * Dd + c;
            *reinterpret_cast<__half2*>(o0) =
                __floats2half2_rn(acc_o[si][j][0] * inv0, acc_o[si][j][1] * inv0);
            *reinterpret_cast<__half2*>(o1) =
                __floats2half2_rn(acc_o[si][j][2] * inv1, acc_o[si][j][3] * inv1);
        }
    }
}

// ---------------- LayerNorms --------------------------------------------------------
__global__ __launch_bounds__(THREADS) void layernorm1_kernel(
    const float* __restrict__ gw, const float* __restrict__ bw)
{
    int row = blockIdx.x;
    const float4* rp = reinterpret_cast<const float4*>(g_tmp + (size_t)row * Hh);
    float4 v = rp[threadIdx.x];
    float s  = v.x + v.y + v.z + v.w;
    float s2 = v.x * v.x + v.y * v.y + v.z * v.z + v.w * v.w;
    #pragma unroll
    for (int o = 16; o; o >>= 1) {
        s  += __shfl_xor_sync(0xffffffffu, s,  o);
        s2 += __shfl_xor_sync(0xffffffffu, s2, o);
    }
    __shared__ float rs[8], rs2[8];
    int lane = threadIdx.x & 31, wid = threadIdx.x >> 5;
    if (lane == 0) { rs[wid] = s; rs2[wid] = s2; }
    __syncthreads();
    s = 0.f; s2 = 0.f;
    #pragma unroll
    for (int i = 0; i < 8; ++i) { s += rs[i]; s2 += rs2[i]; }
    float mu  = s  * (1.0f / Hh);
    float var = s2 * (1.0f / Hh) - mu * mu;
    float inv = rsqrtf(var + EPSLN);
    float4 g4 = reinterpret_cast<const float4*>(gw)[threadIdx.x];
    float4 b4 = reinterpret_cast<const float4*>(bw)[threadIdx.x];
    float4 o4;
    o4.x = (v.x - mu) * inv * g4.x + b4.x;
    o4.y = (v.y - mu) * inv * g4.y + b4.y;
    o4.z = (v.z - mu) * inv * g4.z + b4.z;
    o4.w = (v.w - mu) * inv * g4.w + b4.w;
    uint2 hh = make_uint2(h2u(__floats2half2_rn(o4.x, o4.y)),
                          h2u(__floats2half2_rn(o4.z, o4.w)));
    reinterpret_cast<uint2*>(g_h1h + (size_t)row * Hh)[threadIdx.x] = hh;
}

__global__ __launch_bounds__(THREADS) void layernorm2_kernel(
    const float* __restrict__ gw, const float* __restrict__ bw,
    float* __restrict__ out)
{
    int row = blockIdx.x;
    const float4* rp = reinterpret_cast<const float4*>(g_tmp + (size_t)row * Hh);
    float4 v = rp[threadIdx.x];
    float s  = v.x + v.y + v.z + v.w;
    float s2 = v.x * v.x + v.y * v.y + v.z * v.z + v.w * v.w;
    #pragma unroll
    for (int o = 16; o; o >>= 1) {
        s  += __shfl_xor_sync(0xffffffffu, s,  o);
        s2 += __shfl_xor_sync(0xffffffffu, s2, o);
    }
    __shared__ float rs[8], rs2[8];
    int lane = threadIdx.x & 31, wid = threadIdx.x >> 5;
    if (lane == 0) { rs[wid] = s; rs2[wid] = s2; }
    __syncthreads();
    s = 0.f; s2 = 0.f;
    #pragma unroll
    for (int i = 0; i < 8; ++i) { s += rs[i]; s2 += rs2[i]; }
    float mu  = s  * (1.0f / Hh);
    float var = s2 * (1.0f / Hh) - mu * mu;
    float inv = rsqrtf(var + EPSLN);
    float4 g4 = reinterpret_cast<const float4*>(gw)[threadIdx.x];
    float4 b4 = reinterpret_cast<const float4*>(bw)[threadIdx.x];
    float4 o4;
    o4.x = (v.x - mu) * inv * g4.x + b4.x;
    o4.y = (v.y - mu) * inv * g4.y + b4.y;
    o4.z = (v.z - mu) * inv * g4.z + b4.z;
    o4.w = (v.w - mu) * inv * g4.w + b4.w;
    reinterpret_cast<float4*>(out + (size_t)row * Hh)[threadIdx.x] = o4;
}

// ---------------- entry ---------------------------------------------------------------
extern "C" void kernel_launch(void* const* d_in, const int* in_sizes, int n_in,
                              void* d_out, int out_size)
{
    const float* x   = (const float*)d_in[0];
    const float* Wqr = (const float*)d_in[1];
    const float* Wqi = (const float*)d_in[2];
    const float* bqr = (const float*)d_in[3];
    const float* bqi = (const float*)d_in[4];
    const float* Wkr = (const float*)d_in[5];
    const float* Wki = (const float*)d_in[6];
    const float* bkr = (const float*)d_in[7];
    const float* bki = (const float*)d_in[8];
    const float* Wv  = (const float*)d_in[9];
    const float* bvv = (const float*)d_in[10];
    const float* pqr = (const float*)d_in[11];
    const float* pqi = (const float*)d_in[12];
    const float* pkr = (const float*)d_in[13];
    const float* pki = (const float*)d_in[14];
    const float* Wo  = (const float*)d_in[15];
    const float* bo  = (const float*)d_in[16];
    const float* W1  = (const float*)d_in[17];
    const float* b1  = (const float*)d_in[18];
    const float* W2  = (const float*)d_in[19];
    const float* b2  = (const float*)d_in[20];
    const float* g1  = (const float*)d_in[21];
    const float* be1 = (const float*)d_in[22];
    const float* g2  = (const float*)d_in[23];
    const float* be2 = (const float*)d_in[24];
    float* out = (float*)d_out;

    static bool attr_done = false;
    if (!attr_done) {
        cudaFuncSetAttribute(hproj_kernel,
            cudaFuncAttributeMaxDynamicSharedMemorySize, (int)SM_HGEMM);
        cudaFuncSetAttribute(hwo_kernel,
            cudaFuncAttributeMaxDynamicSharedMemorySize, (int)SM_HGEMM);
        cudaFuncSetAttribute(hff1_kernel,
            cudaFuncAttributeMaxDynamicSharedMemorySize, (int)SM_HGEMM);
        cudaFuncSetAttribute(hff2_kernel,
            cudaFuncAttributeMaxDynamicSharedMemorySize, (int)SM_HGEMM);
        cudaFuncSetAttribute(flash_attn_kernel,
            cudaFuncAttributeMaxDynamicSharedMemorySize, (int)SM_FLASH);
        attr_done = true;
    }

    const int U4 = THREADS * 4;
    prepass_kernel<<<(N4_TOT + U4 - 1) / U4, THREADS>>>(
        (const float4*)x, (const float4*)Wo, (const float4*)W1, (const float4*)W2,
        Wqr, Wqi, Wkr, Wki, Wv);

    hproj_kernel<<<dim3(5120 / 128, (Bb * Ss) / 128), THREADS, SM_HGEMM>>>(
        bqr, bqi, bkr, bki, bvv, pqr, pqi, pkr, pki);
    flash_attn_kernel<<<dim3(Ss / 128, Bb * Nn), FA_THREADS, SM_FLASH>>>();
    hwo_kernel<<<dim3(Hh / 128, (Bb * Ss) / 128), THREADS, SM_HGEMM>>>(bo, x);
    layernorm1_kernel<<<Bb * Ss, THREADS>>>(g1, be1);
    hff1_kernel<<<dim3(FFd / 128, (Bb * Ss) / 128), THREADS, SM_HGEMM>>>(b1);
    hff2_kernel<<<dim3(Hh / 128, (Bb * Ss) / 128), THREADS, SM_HGEMM>>>(b2);
    layernorm2_kernel<<<Bb * Ss, THREADS>>>(g2, be2, out);
}